// round 5
// baseline (speedup 1.0000x reference)
#include <cuda_runtime.h>
#include <cstdint>
#include <cstdio>

#define B_   256
#define T_   600
#define I_   129
#define H_   200
#define G_   800   // 4*H
#define KP_  160   // padded K for the I=129 operands

// ---------------- scratch (device globals; no cudaMalloc allowed) ----------------
__device__ float g_xg[(size_t)T_ * B_ * G_];     // 491.5 MB
__device__ float g_h1[(size_t)T_ * B_ * H_];     // 122.9 MB
__device__ float g_h2[(size_t)T_ * B_ * H_];     // 122.9 MB
__device__ float g_tmp[(size_t)T_ * B_ * KP_];   // 98.3 MB (xt, later y1; stride 160)
__device__ float g_wp1[G_ * KP_];                // w_ih1 padded to [800,160]
__device__ float g_wp2[I_ * KP_];                // fc2_w padded to [129,160]

// per-batch-group barriers (4 groups of 25 blocks)
__device__ unsigned g_cnt2[4] = {0, 0, 0, 0};
__device__ unsigned g_gen2[4] = {0, 0, 0, 0};

// ---------------- fast activations ----------------
__device__ __forceinline__ float sigmf(float x) {
    return __fdividef(1.f, 1.f + __expf(-x));
}
__device__ __forceinline__ float tanh_fast(float x) {
    float e = __expf(2.f * x);
    return 1.f - __fdividef(2.f, e + 1.f);
}

// ---------------- tf32 helpers ----------------
__device__ __forceinline__ uint32_t f2tf32(float x) {
    uint32_t r;
    asm("cvt.rna.tf32.f32 %0, %1;" : "=r"(r) : "f"(x));
    return r;
}
__device__ __forceinline__ float tfhi(float v) { return __uint_as_float(f2tf32(v)); }

__device__ __forceinline__ void mma_tf32(float* d, const uint32_t* a, const uint32_t* b) {
    asm volatile(
        "mma.sync.aligned.m16n8k8.row.col.f32.tf32.tf32.f32 "
        "{%0,%1,%2,%3}, {%4,%5,%6,%7}, {%8,%9}, {%0,%1,%2,%3};"
        : "+f"(d[0]), "+f"(d[1]), "+f"(d[2]), "+f"(d[3])
        : "r"(a[0]), "r"(a[1]), "r"(a[2]), "r"(a[3]), "r"(b[0]), "r"(b[1]));
}

// ---------------- weight padding: w[N,K] -> wp[N,160] (zero-filled) ----------------
__global__ void pad_w(const float* __restrict__ w, float* __restrict__ wp, int N, int K)
{
    int i = blockIdx.x * 256 + threadIdx.x;
    if (i < N * KP_) {
        int n = i / KP_, k = i - n * KP_;
        wp[i] = (k < K) ? w[(size_t)n * K + k] : 0.f;
    }
}

// ---------------- transpose x [B,I,T] -> xt [(t*B+b), 160] (zero-padded) ----------
__global__ void transpose_x(const float* __restrict__ x, float* __restrict__ xt)
{
    __shared__ float sm[32][33];
    const int b  = blockIdx.z;
    const int i0 = blockIdx.y * 32;
    const int t0 = blockIdx.x * 32;
    const int tx = threadIdx.x, ty = threadIdx.y; // block (32,8)
#pragma unroll
    for (int s = 0; s < 32; s += 8) {
        int i = i0 + ty + s, t = t0 + tx;
        sm[ty + s][tx] = (i < I_ && t < T_) ? x[((size_t)b * I_ + i) * T_ + t] : 0.f;
    }
    __syncthreads();
#pragma unroll
    for (int s = 0; s < 32; s += 8) {
        int t = t0 + ty + s, i = i0 + tx;
        if (t < T_ && i < KP_)
            xt[((size_t)t * B_ + b) * KP_ + i] = sm[tx][ty + s];
    }
}

// ---------------- GEMM building blocks ----------------
// smem tile layout (per buffer): A 128 rows x stride 80, W 64 rows x stride 80.
// Row r, k-group kb (8 k's), slot tg: float4 {hi(k), hi(k+4), lo(k), lo(k+4)},
// k = kb*8 + tg. Stride 80 (mod 32 = 16) -> conflict-free LDS.128 fragments.
#define TBUF 15360   // floats per buffer: 128*80 + 64*80

__device__ __forceinline__ void sts_unit(float* dst, float4 p0, float4 p1)
{
    float h0 = tfhi(p0.x), h1 = tfhi(p0.y), h2 = tfhi(p0.z), h3 = tfhi(p0.w);
    float q0 = tfhi(p1.x), q1 = tfhi(p1.y), q2 = tfhi(p1.z), q3 = tfhi(p1.w);
    ((float4*)dst)[0] = make_float4(h0, q0, tfhi(p0.x - h0), tfhi(p1.x - q0));
    ((float4*)dst)[1] = make_float4(h1, q1, tfhi(p0.y - h1), tfhi(p1.y - q1));
    ((float4*)dst)[2] = make_float4(h2, q2, tfhi(p0.z - h2), tfhi(p1.z - q2));
    ((float4*)dst)[3] = make_float4(h3, q3, tfhi(p0.w - h3), tfhi(p1.w - q3));
}

__device__ __forceinline__ void load_tile(
    const float* __restrict__ A, int ldA, const float* __restrict__ W, int ldW,
    int m0, int n0, int N, int K, int kbase, int tid,
    float4 ra[2][2], float4 rw[2])
{
    const float4 z = make_float4(0.f, 0.f, 0.f, 0.f);
#pragma unroll
    for (int j = 0; j < 2; ++j) {
        int u = tid * 2 + j;
        int mm = u >> 2, kb = u & 3;
        int k = kbase + kb * 8;
        if (k + 8 <= K) {
            const float* p = A + (size_t)(m0 + mm) * ldA + k;
            ra[j][0] = *(const float4*)(p);
            ra[j][1] = *(const float4*)(p + 4);
        } else { ra[j][0] = z; ra[j][1] = z; }
    }
    {
        int nn = tid >> 2, kb = tid & 3;
        int k = kbase + kb * 8;
        if (k + 8 <= K && n0 + nn < N) {
            const float* p = W + (size_t)(n0 + nn) * ldW + k;
            rw[0] = *(const float4*)(p);
            rw[1] = *(const float4*)(p + 4);
        } else { rw[0] = z; rw[1] = z; }
    }
}

__device__ __forceinline__ void sts_tile(float* Sa, int tid,
                                         float4 ra[2][2], float4 rw[2])
{
    float* Sw = Sa + 10240;
#pragma unroll
    for (int j = 0; j < 2; ++j) {
        int u = tid * 2 + j;
        sts_unit(Sa + (u >> 2) * 80 + (u & 3) * 16, ra[j][0], ra[j][1]);
    }
    sts_unit(Sw + (tid >> 2) * 80 + (tid & 3) * 16, rw[0], rw[1]);
}

__device__ __forceinline__ void mma_tile(const float* Sa, int wm, int wn,
                                         int g4, int tg, float acc[2][4][4])
{
    const float* Sw = Sa + 10240;
#pragma unroll
    for (int kk = 0; kk < 4; ++kk) {
        int koff = kk * 16 + tg * 4;
        uint32_t ah[2][4], al[2][4];
#pragma unroll
        for (int mf = 0; mf < 2; ++mf) {
            const float* pa = Sa + (wm * 32 + mf * 16 + g4) * 80 + koff;
            float4 A0 = *(const float4*)pa;
            float4 A1 = *(const float4*)(pa + 8 * 80);
            ah[mf][0] = __float_as_uint(A0.x); ah[mf][1] = __float_as_uint(A1.x);
            ah[mf][2] = __float_as_uint(A0.y); ah[mf][3] = __float_as_uint(A1.y);
            al[mf][0] = __float_as_uint(A0.z); al[mf][1] = __float_as_uint(A1.z);
            al[mf][2] = __float_as_uint(A0.w); al[mf][3] = __float_as_uint(A1.w);
        }
#pragma unroll
        for (int nf = 0; nf < 4; ++nf) {
            const float* pb = Sw + (wn * 32 + nf * 8 + g4) * 80 + koff;
            float4 Bv = *(const float4*)pb;
            uint32_t bh[2] = {__float_as_uint(Bv.x), __float_as_uint(Bv.y)};
            uint32_t bl[2] = {__float_as_uint(Bv.z), __float_as_uint(Bv.w)};
            mma_tf32(acc[0][nf], ah[0], bh);
            mma_tf32(acc[0][nf], ah[0], bl);
            mma_tf32(acc[0][nf], al[0], bh);
            mma_tf32(acc[1][nf], ah[1], bh);
            mma_tf32(acc[1][nf], ah[1], bl);
            mma_tf32(acc[1][nf], al[1], bh);
        }
    }
}

// ---------------- tensor-core GEMM (3xTF32, double-buffered) ----------------
// Block tile 128(m) x 64(n); 8 warps 4(m) x 2(n), warp tile 32x32; ktile 32.
// MODE 0: out[m*ldOut+n] = v + bias[n] + bias2[n]
// MODE 1: out[m*ldOut+n] = relu(v + bias[n]) for n<N, 0 for n in [N,160)
// MODE 2: out[(b*129+n)*600+t] = sigmoid(v + bias[n]); t=m>>8, b=m&255
template <int MODE>
__global__ void __launch_bounds__(256) gemm_tc(
    const float* __restrict__ A, int ldA,
    const float* __restrict__ W, int ldW,
    const float* __restrict__ bias, const float* __restrict__ bias2,
    float* __restrict__ out, int K, int N, int ldOut)
{
    extern __shared__ float sm[];
    const int tid  = threadIdx.x;
    const int warp = tid >> 5, lane = tid & 31;
    const int wm = warp >> 1, wn = warp & 1;
    const int g4 = lane >> 2, tg = lane & 3;
    const int m0 = blockIdx.y * 128;
    const int n0 = blockIdx.x * 64;

    float acc[2][4][4] = {};
    float4 ra[2][2], rw[2];

    const int ktiles = (K + 31) >> 5;

    load_tile(A, ldA, W, ldW, m0, n0, N, K, 0, tid, ra, rw);
    sts_tile(sm, tid, ra, rw);
    __syncthreads();

    for (int kt = 0; kt < ktiles; ++kt) {
        if (kt + 1 < ktiles)
            load_tile(A, ldA, W, ldW, m0, n0, N, K, (kt + 1) * 32, tid, ra, rw);
        mma_tile(sm + (kt & 1) * TBUF, wm, wn, g4, tg, acc);
        if (kt + 1 < ktiles)
            sts_tile(sm + ((kt + 1) & 1) * TBUF, tid, ra, rw);
        __syncthreads();
    }

    // epilogue
#pragma unroll
    for (int mf = 0; mf < 2; ++mf) {
        int m_a = m0 + wm * 32 + mf * 16 + g4;
#pragma unroll
        for (int nf = 0; nf < 4; ++nf) {
            int n = n0 + wn * 32 + nf * 8 + tg * 2;
#pragma unroll
            for (int half = 0; half < 2; ++half) {
                int m = m_a + half * 8;
                float v0 = acc[mf][nf][half * 2 + 0];
                float v1 = acc[mf][nf][half * 2 + 1];
                if (MODE == 0) {
                    float2 o;
                    o.x = v0 + bias[n] + bias2[n];
                    o.y = v1 + bias[n + 1] + bias2[n + 1];
                    *(float2*)(out + (size_t)m * ldOut + n) = o;
                } else if (MODE == 1) {
                    if (n < KP_) {
                        float2 o;
                        o.x = (n     < N) ? fmaxf(v0 + bias[n], 0.f)     : 0.f;
                        o.y = (n + 1 < N) ? fmaxf(v1 + bias[n + 1], 0.f) : 0.f;
                        *(float2*)(out + (size_t)m * ldOut + n) = o;
                    }
                } else {
                    int tt = m >> 8, b = m & 255;
                    if (n < N)
                        out[((size_t)b * I_ + n) * T_ + tt] = sigmf(v0 + bias[n]);
                    if (n + 1 < N)
                        out[((size_t)b * I_ + n + 1) * T_ + tt] = sigmf(v1 + bias[n + 1]);
                }
            }
        }
    }
}

// ---------------- tensor-core persistent LSTM scan ------------------------------
// grid = 100 blocks: 4 batch-groups (64 batches) x 25 unit-blocks (8 units).
// Gate-interleaved cols: col c = unit_local*4 + gate -> after 4 shfl.xor(1) each
// thread holds all 4 gates of one unit for 2 batches; c-state in registers;
// no epilogue smem round-trip.
__global__ void __launch_bounds__(256, 1) lstm_scan_tc(
    const float* __restrict__ xg, const float* __restrict__ whh,
    float* __restrict__ hout)
{
    extern __shared__ float sm[];
    float* w_s = sm;                   // 32 * 400 = 12800
    float* h_s = sm + 12800;           // 64 * 400 = 25600

    const int tid  = threadIdx.x;
    const int warp = tid >> 5, lane = tid & 31;
    const int g4 = lane >> 2, tg = lane & 3;
    const int wm = warp >> 1, wn = warp & 1;
    const int bb = blockIdx.x & 3;
    const int uu = blockIdx.x >> 2;
    const int b0 = bb * 64;
    const int u0 = uu * 8;

    // stage w_hh slice once: col c = ul*4 + gate, interleaved hi/lo
    for (int i = 0; i < 13; ++i) {
        int lin = tid + 256 * i;
        if (lin < 3200) {
            int c = lin / 100, rem = lin - c * 100;
            int kb = rem >> 2, tgs = rem & 3;
            int grow = (c & 3) * H_ + u0 + (c >> 2);   // gate*200 + unit
            int k0 = kb * 8 + tgs;
            float w0 = whh[(size_t)grow * H_ + k0];
            float w1 = whh[(size_t)grow * H_ + k0 + 4];
            float hh0 = tfhi(w0), hh1 = tfhi(w1);
            *(float4*)(w_s + c * 400 + kb * 16 + tgs * 4) =
                make_float4(hh0, hh1, tfhi(w0 - hh0), tfhi(w1 - hh1));
        }
    }

    const int eg    = tg & 1;                            // 0: owns gates01, 1: gates23
    const int u_own = u0 + wn * 4 + (tg >> 1) + eg * 2;  // unit this thread finishes
    const int ma    = b0 + wm * 16 + g4;
    const int mb    = ma + 8;
    float ca = 0.f, cb = 0.f;

    const float* hA = h_s + (wm * 16 + g4) * 400 + tg * 4;
    const float* hB = hA + 8 * 400;
    const float* wA = w_s + (wn * 16 + g4) * 400 + tg * 4;
    const float* wB = wA + 8 * 400;

    for (int t = 0; t < T_; ++t) {
        // prefetch xg (no h dependency) before the barrier wait
        const float* xra = xg + ((size_t)t * B_ + ma) * G_ + u_own;
        const float* xrb = xg + ((size_t)t * B_ + mb) * G_ + u_own;
        float xa0 = xra[0], xa1 = xra[H_], xa2 = xra[2 * H_], xa3 = xra[3 * H_];
        float xb0 = xrb[0], xb1 = xrb[H_], xb2 = xrb[2 * H_], xb3 = xrb[3 * H_];

        if (t > 0) {
            __syncthreads();
            if (tid == 0) {
                unsigned gen = *(volatile unsigned*)&g_gen2[bb];
                if (atomicAdd(&g_cnt2[bb], 1u) == 24u) {
                    atomicExch(&g_cnt2[bb], 0u);
                    __threadfence();
                    atomicAdd(&g_gen2[bb], 1u);
                } else {
                    while (*(volatile unsigned*)&g_gen2[bb] == gen) { __nanosleep(32); }
                }
                __threadfence();
            }
            __syncthreads();
        }

        // stage h(t-1): 64x200 fp32 -> interleaved hi/lo smem
        if (t == 0) {
            float4 z = make_float4(0.f, 0.f, 0.f, 0.f);
#pragma unroll
            for (int i = 0; i < 25; ++i) {
                int lin = tid + 256 * i;
                *(float4*)(h_s + (lin / 100) * 400 + (lin % 100) * 4) = z;
            }
        } else {
            const float* hp = hout + (size_t)(t - 1) * B_ * H_;
#pragma unroll
            for (int i = 0; i < 25; ++i) {
                int lin = tid + 256 * i;
                int row = lin / 100, rem = lin - row * 100;
                int kb = rem >> 2, tgs = rem & 3;
                int k0 = kb * 8 + tgs;
                const float* src = hp + (size_t)(b0 + row) * H_;
                float v0 = __ldcg(src + k0);
                float v1 = __ldcg(src + k0 + 4);
                float h0 = tfhi(v0), h1 = tfhi(v1);
                *(float4*)(h_s + row * 400 + kb * 16 + tgs * 4) =
                    make_float4(h0, h1, tfhi(v0 - h0), tfhi(v1 - h1));
            }
        }
        __syncthreads();

        // MMA: G[64,32] = h @ w^T (3xTF32)
        float acc0[4] = {0.f, 0.f, 0.f, 0.f};
        float acc1[4] = {0.f, 0.f, 0.f, 0.f};
#pragma unroll 5
        for (int kb = 0; kb < 25; ++kb) {
            float4 A0 = *(const float4*)(hA + kb * 16);
            float4 A1 = *(const float4*)(hB + kb * 16);
            float4 B0 = *(const float4*)(wA + kb * 16);
            float4 B1 = *(const float4*)(wB + kb * 16);
            uint32_t ah[4] = {__float_as_uint(A0.x), __float_as_uint(A1.x),
                              __float_as_uint(A0.y), __float_as_uint(A1.y)};
            uint32_t al[4] = {__float_as_uint(A0.z), __float_as_uint(A1.z),
                              __float_as_uint(A0.w), __float_as_uint(A1.w)};
            uint32_t bh0[2] = {__float_as_uint(B0.x), __float_as_uint(B0.y)};
            uint32_t bl0[2] = {__float_as_uint(B0.z), __float_as_uint(B0.w)};
            uint32_t bh1[2] = {__float_as_uint(B1.x), __float_as_uint(B1.y)};
            uint32_t bl1[2] = {__float_as_uint(B1.z), __float_as_uint(B1.w)};
            mma_tf32(acc0, ah, bh0);
            mma_tf32(acc0, ah, bl0);
            mma_tf32(acc0, al, bh0);
            mma_tf32(acc1, ah, bh1);
            mma_tf32(acc1, ah, bl1);
            mma_tf32(acc1, al, bh1);
        }

        // gate exchange: even tg sends acc1 (its partner's unit), odd sends acc0
        float s0 = __shfl_xor_sync(0xffffffffu, eg ? acc0[0] : acc1[0], 1);
        float s1 = __shfl_xor_sync(0xffffffffu, eg ? acc0[1] : acc1[1], 1);
        float s2 = __shfl_xor_sync(0xffffffffu, eg ? acc0[2] : acc1[2], 1);
        float s3 = __shfl_xor_sync(0xffffffffu, eg ? acc0[3] : acc1[3], 1);
        float gia, gfa, gib, gfb, gga, goa, ggb, gob;
        if (!eg) {
            gia = acc0[0]; gfa = acc0[1]; gib = acc0[2]; gfb = acc0[3];
            gga = s0;      goa = s1;      ggb = s2;      gob = s3;
        } else {
            gia = s0;      gfa = s1;      gib = s2;      gfb = s3;
            gga = acc1[0]; goa = acc1[1]; ggb = acc1[2]; gob = acc1[3];
        }

        // gates + cell update (c in registers across all 600 steps)
        float iv = sigmf(gia + xa0), fv = sigmf(gfa + xa1);
        float gv = tanh_fast(gga + xa2), ov = sigmf(goa + xa3);
        ca = fv * ca + iv * gv;
        float ha = ov * tanh_fast(ca);

        iv = sigmf(gib + xb0); fv = sigmf(gfb + xb1);
        gv = tanh_fast(ggb + xb2); ov = sigmf(gob + xb3);
        cb = fv * cb + iv * gv;
        float hb = ov * tanh_fast(cb);

        __stcg(hout + ((size_t)t * B_ + ma) * H_ + u_own, ha);
        __stcg(hout + ((size_t)t * B_ + mb) * H_ + u_own, hb);
        __threadfence();   // order h stores before next barrier arrive
    }
}

// ---------------- launch --------------------------------------------------------
extern "C" void kernel_launch(void* const* d_in, const int* in_sizes, int n_in,
                              void* d_out, int out_size)
{
    const float* x     = (const float*)d_in[0];
    const float* w_ih1 = (const float*)d_in[1];
    const float* w_hh1 = (const float*)d_in[2];
    const float* b_ih1 = (const float*)d_in[3];
    const float* b_hh1 = (const float*)d_in[4];
    const float* w_ih2 = (const float*)d_in[5];
    const float* w_hh2 = (const float*)d_in[6];
    const float* b_ih2 = (const float*)d_in[7];
    const float* b_hh2 = (const float*)d_in[8];
    const float* fc1_w = (const float*)d_in[9];
    const float* fc1_b = (const float*)d_in[10];
    const float* fc2_w = (const float*)d_in[11];
    const float* fc2_b = (const float*)d_in[12];
    float* out = (float*)d_out;

    float *xg, *h1, *h2, *tmp, *wp1, *wp2;
    cudaGetSymbolAddress((void**)&xg,  g_xg);
    cudaGetSymbolAddress((void**)&h1,  g_h1);
    cudaGetSymbolAddress((void**)&h2,  g_h2);
    cudaGetSymbolAddress((void**)&tmp, g_tmp);
    cudaGetSymbolAddress((void**)&wp1, g_wp1);
    cudaGetSymbolAddress((void**)&wp2, g_wp2);

    const int SCAN_SMEM = (12800 + 25600) * (int)sizeof(float);   // 153600 B
    cudaFuncSetAttribute(lstm_scan_tc, cudaFuncAttributeMaxDynamicSharedMemorySize, SCAN_SMEM);

    const int GEMM_SMEM = 2 * TBUF * (int)sizeof(float);          // 122880 B
    cudaFuncSetAttribute(gemm_tc<0>, cudaFuncAttributeMaxDynamicSharedMemorySize, GEMM_SMEM);
    cudaFuncSetAttribute(gemm_tc<1>, cudaFuncAttributeMaxDynamicSharedMemorySize, GEMM_SMEM);
    cudaFuncSetAttribute(gemm_tc<2>, cudaFuncAttributeMaxDynamicSharedMemorySize, GEMM_SMEM);

    const int MROWS = B_ * T_;                 // 153600
    const dim3 grows(13, MROWS / 128);         // N=800 -> 13 n-tiles
    const dim3 frows(3,  MROWS / 128);         // N up to 160 -> 3 n-tiles

    // 0. pad odd-K weights once per call (cheap, deterministic)
    pad_w<<<(G_ * KP_ + 255) / 256, 256>>>(w_ih1, wp1, G_, I_);
    pad_w<<<(I_ * KP_ + 255) / 256, 256>>>(fc2_w, wp2, I_, I_);
    // 1. x -> [T*B, 160] zero-padded
    transpose_x<<<dim3((T_ + 31) / 32, KP_ / 32, B_), dim3(32, 8)>>>(x, tmp);
    // 2. xg1 = xt @ wp1^T + b_ih1 + b_hh1          (K=160, all aligned)
    gemm_tc<0><<<grows, 256, GEMM_SMEM>>>(tmp, KP_, wp1, KP_, b_ih1, b_hh1, xg, KP_, G_, G_);
    // 3. layer-1 scan
    lstm_scan_tc<<<100, 256, SCAN_SMEM>>>(xg, w_hh1, h1);
    // 4. xg2 = h1 @ w_ih2^T + b_ih2 + b_hh2        (K=200)
    gemm_tc<0><<<grows, 256, GEMM_SMEM>>>(h1, H_, w_ih2, H_, b_ih2, b_hh2, xg, H_, G_, G_);
    // 5. layer-2 scan
    lstm_scan_tc<<<100, 256, SCAN_SMEM>>>(xg, w_hh2, h2);
    // 6. y1 = relu(h2 @ fc1_w^T + fc1_b) -> tmp[., 160] (zero-padded cols)
    gemm_tc<1><<<frows, 256, GEMM_SMEM>>>(h2, H_, fc1_w, H_, fc1_b, nullptr, tmp, H_, I_, KP_);
    // 7. out = sigmoid(y1 @ wp2^T + fc2_b), transposed store to [B,129,T]
    gemm_tc<2><<<frows, 256, GEMM_SMEM>>>(tmp, KP_, wp2, KP_, fc2_b, nullptr, out, KP_, I_, 0);
}

// round 6
// speedup vs baseline: 1.0625x; 1.0625x over previous
#include <cuda_runtime.h>
#include <cstdint>
#include <cstdio>

#define B_   256
#define T_   600
#define I_   129
#define H_   200
#define G_   800   // 4*H
#define KP_  160   // padded K for the I=129 operands
#define HSW_ 400   // g_hs row width: 25 kb-groups * 16 floats

// ---------------- scratch (device globals; no cudaMalloc allowed) ----------------
__device__ float g_xg[(size_t)T_ * B_ * G_];      // 491.5 MB
__device__ float g_hs[(size_t)T_ * B_ * HSW_];    // 245.8 MB  hi/lo-split h (both layers)
__device__ float g_tmp[(size_t)T_ * B_ * KP_];    // 98.3 MB  (xt, later y1; stride 160)
__device__ float g_wp1[G_ * KP_];                 // w_ih1 padded to [800,160]
__device__ float g_wp2[I_ * KP_];                 // fc2_w padded to [129,160]

// per-batch-group barriers (4 groups of 25 blocks)
__device__ unsigned g_cnt2[4] = {0, 0, 0, 0};
__device__ unsigned g_gen2[4] = {0, 0, 0, 0};

// ---------------- fast activations ----------------
__device__ __forceinline__ float sigmf(float x) {
    return __fdividef(1.f, 1.f + __expf(-x));
}
__device__ __forceinline__ float tanh_fast(float x) {
    float e = __expf(2.f * x);
    return 1.f - __fdividef(2.f, e + 1.f);
}

// ---------------- tf32 helpers ----------------
__device__ __forceinline__ uint32_t f2tf32(float x) {
    uint32_t r;
    asm("cvt.rna.tf32.f32 %0, %1;" : "=r"(r) : "f"(x));
    return r;
}
__device__ __forceinline__ float tfhi(float v) { return __uint_as_float(f2tf32(v)); }
__device__ __forceinline__ uint32_t fu(float v) { return __float_as_uint(v); }

__device__ __forceinline__ void mma_tf32(float* d, const uint32_t* a, const uint32_t* b) {
    asm volatile(
        "mma.sync.aligned.m16n8k8.row.col.f32.tf32.tf32.f32 "
        "{%0,%1,%2,%3}, {%4,%5,%6,%7}, {%8,%9}, {%0,%1,%2,%3};"
        : "+f"(d[0]), "+f"(d[1]), "+f"(d[2]), "+f"(d[3])
        : "r"(a[0]), "r"(a[1]), "r"(a[2]), "r"(a[3]), "r"(b[0]), "r"(b[1]));
}

// interleaved 8-k split: q[tg] = {hi(k0+tg), hi(k0+tg+4), lo(k0+tg), lo(k0+tg+4)}
__device__ __forceinline__ void split8(float4 p0, float4 p1, float4 q[4])
{
    float h0 = tfhi(p0.x), h1 = tfhi(p0.y), h2 = tfhi(p0.z), h3 = tfhi(p0.w);
    float g0 = tfhi(p1.x), g1 = tfhi(p1.y), g2 = tfhi(p1.z), g3 = tfhi(p1.w);
    q[0] = make_float4(h0, g0, tfhi(p0.x - h0), tfhi(p1.x - g0));
    q[1] = make_float4(h1, g1, tfhi(p0.y - h1), tfhi(p1.y - g1));
    q[2] = make_float4(h2, g2, tfhi(p0.z - h2), tfhi(p1.z - g2));
    q[3] = make_float4(h3, g3, tfhi(p0.w - h3), tfhi(p1.w - g3));
}

// ---------------- weight padding: w[N,K] -> wp[N,160] (zero-filled) ----------------
__global__ void pad_w(const float* __restrict__ w, float* __restrict__ wp, int N, int K)
{
    int i = blockIdx.x * 256 + threadIdx.x;
    if (i < N * KP_) {
        int n = i / KP_, k = i - n * KP_;
        wp[i] = (k < K) ? w[(size_t)n * K + k] : 0.f;
    }
}

// ---------------- transpose x [B,I,T] -> xt [(t*B+b), 160] (zero-padded) ----------
__global__ void transpose_x(const float* __restrict__ x, float* __restrict__ xt)
{
    __shared__ float sm[32][33];
    const int b  = blockIdx.z;
    const int i0 = blockIdx.y * 32;
    const int t0 = blockIdx.x * 32;
    const int tx = threadIdx.x, ty = threadIdx.y; // block (32,8)
#pragma unroll
    for (int s = 0; s < 32; s += 8) {
        int i = i0 + ty + s, t = t0 + tx;
        sm[ty + s][tx] = (i < I_ && t < T_) ? x[((size_t)b * I_ + i) * T_ + t] : 0.f;
    }
    __syncthreads();
#pragma unroll
    for (int s = 0; s < 32; s += 8) {
        int t = t0 + ty + s, i = i0 + tx;
        if (t < T_ && i < KP_)
            xt[((size_t)t * B_ + b) * KP_ + i] = sm[tx][ty + s];
    }
}

// ---------------- GEMM (3xTF32, ktile 16, double-buffered, 2 CTA/SM) -------------
// smem per buffer: A 128 rows x stride 48, W 64 rows x stride 48 (stride 48 == 16
// mod 32 words -> conflict-free LDS.128 fragments; rotated STS -> conflict-free).
#define TB2 9216   // floats per buffer: 128*48 + 64*48

template <bool ASPLIT>
__device__ __forceinline__ void ld_regs(
    const float* __restrict__ A, int ldA,
    const float* __restrict__ W, int ldW,
    int m0, int n0, int N, int K, int kt, int tid,
    float4 ra[4], float4 rw[2])
{
    const float4 z = make_float4(0.f, 0.f, 0.f, 0.f);
    const int row = tid >> 1, kbl = tid & 1;
    if (ASPLIT) {
        int kb = kt * 2 + kbl;
        if (kb * 8 + 8 <= K) {
            const float4* p = (const float4*)(A + (size_t)(m0 + row) * HSW_) + kb * 4;
            ra[0] = p[0]; ra[1] = p[1]; ra[2] = p[2]; ra[3] = p[3];
        } else { ra[0] = z; ra[1] = z; ra[2] = z; ra[3] = z; }
    } else {
        int k = kt * 16 + kbl * 8;
        if (k + 8 <= K) {
            const float* p = A + (size_t)(m0 + row) * ldA + k;
            ra[0] = *(const float4*)p;
            ra[1] = *(const float4*)(p + 4);
        } else { ra[0] = z; ra[1] = z; }
    }
    if (tid < 128) {
        int wr = tid >> 1;
        int k = kt * 16 + kbl * 8;
        if (k + 8 <= K && n0 + wr < N) {
            const float* p = W + (size_t)(n0 + wr) * ldW + k;
            rw[0] = *(const float4*)p;
            rw[1] = *(const float4*)(p + 4);
        } else { rw[0] = z; rw[1] = z; }
    }
}

template <bool ASPLIT>
__device__ __forceinline__ void st_smem(float* buf, int tid, float4 ra[4], float4 rw[2])
{
    const int row = tid >> 1, kbl = tid & 1;
    {
        float4 q[4];
        if (ASPLIT) { q[0] = ra[0]; q[1] = ra[1]; q[2] = ra[2]; q[3] = ra[3]; }
        else        split8(ra[0], ra[1], q);
        float4* da = (float4*)(buf + row * 48 + kbl * 16);
        int rot = row & 3;
#pragma unroll
        for (int j = 0; j < 4; ++j) { int jj = (rot + j) & 3; da[jj] = q[jj]; }
    }
    if (tid < 128) {
        int wr = tid >> 1;
        float4 q[4];
        split8(rw[0], rw[1], q);
        float4* dw = (float4*)(buf + 6144 + wr * 48 + kbl * 16);
        int rot = wr & 3;
#pragma unroll
        for (int j = 0; j < 4; ++j) { int jj = (rot + j) & 3; dw[jj] = q[jj]; }
    }
}

__device__ __forceinline__ void mma_tile16(const float* buf, int wm, int wn,
                                           int g4, int tg, float acc[2][4][4])
{
    const float* Sw = buf + 6144;
#pragma unroll
    for (int kk = 0; kk < 2; ++kk) {
        int koff = kk * 16 + tg * 4;
        uint32_t ah[2][4], al[2][4];
#pragma unroll
        for (int mf = 0; mf < 2; ++mf) {
            const float* pa = buf + (wm * 32 + mf * 16 + g4) * 48 + koff;
            float4 A0 = *(const float4*)pa;
            float4 A1 = *(const float4*)(pa + 8 * 48);
            ah[mf][0] = fu(A0.x); ah[mf][1] = fu(A1.x);
            ah[mf][2] = fu(A0.y); ah[mf][3] = fu(A1.y);
            al[mf][0] = fu(A0.z); al[mf][1] = fu(A1.z);
            al[mf][2] = fu(A0.w); al[mf][3] = fu(A1.w);
        }
#pragma unroll
        for (int nf = 0; nf < 4; ++nf) {
            const float* pb = Sw + (wn * 32 + nf * 8 + g4) * 48 + koff;
            float4 Bv = *(const float4*)pb;
            uint32_t bh[2] = {fu(Bv.x), fu(Bv.y)};
            uint32_t bl[2] = {fu(Bv.z), fu(Bv.w)};
            mma_tf32(acc[0][nf], ah[0], bh);
            mma_tf32(acc[0][nf], ah[0], bl);
            mma_tf32(acc[0][nf], al[0], bh);
            mma_tf32(acc[1][nf], ah[1], bh);
            mma_tf32(acc[1][nf], ah[1], bl);
            mma_tf32(acc[1][nf], al[1], bh);
        }
    }
}

// MODE 0: out[m*ldOut+n] = v + bias[n] + bias2[n]   (guarded n<N)
// MODE 1: out[m*ldOut+n] = relu(v+bias[n]) for n<N, 0 for n in [N,160)
// MODE 2: out[(b*129+n)*600+t] = sigmoid(v+bias[n]); t=m>>8, b=m&255
template <int MODE, bool ASPLIT>
__global__ void __launch_bounds__(256, 2) gemm_tc(
    const float* __restrict__ A, int ldA,
    const float* __restrict__ W, int ldW,
    const float* __restrict__ bias, const float* __restrict__ bias2,
    float* __restrict__ out, int K, int N, int ldOut)
{
    extern __shared__ float sm[];
    const int tid  = threadIdx.x;
    const int warp = tid >> 5, lane = tid & 31;
    const int wm = warp >> 1, wn = warp & 1;
    const int g4 = lane >> 2, tg = lane & 3;
    const int m0 = blockIdx.y * 128;
    const int n0 = blockIdx.x * 64;

    float acc[2][4][4] = {};
    float4 ra[4], rw[2];

    const int ktiles = (K + 15) >> 4;

    ld_regs<ASPLIT>(A, ldA, W, ldW, m0, n0, N, K, 0, tid, ra, rw);
    st_smem<ASPLIT>(sm, tid, ra, rw);
    __syncthreads();

    for (int kt = 0; kt < ktiles; ++kt) {
        if (kt + 1 < ktiles)
            ld_regs<ASPLIT>(A, ldA, W, ldW, m0, n0, N, K, kt + 1, tid, ra, rw);
        mma_tile16(sm + (kt & 1) * TB2, wm, wn, g4, tg, acc);
        if (kt + 1 < ktiles)
            st_smem<ASPLIT>(sm + ((kt + 1) & 1) * TB2, tid, ra, rw);
        __syncthreads();
    }

    // epilogue
#pragma unroll
    for (int mf = 0; mf < 2; ++mf) {
        int m_a = m0 + wm * 32 + mf * 16 + g4;
#pragma unroll
        for (int nf = 0; nf < 4; ++nf) {
            int n = n0 + wn * 32 + nf * 8 + tg * 2;
#pragma unroll
            for (int half = 0; half < 2; ++half) {
                int m = m_a + half * 8;
                float v0 = acc[mf][nf][half * 2 + 0];
                float v1 = acc[mf][nf][half * 2 + 1];
                if (MODE == 0) {
                    if (n < N) {                 // N even, n even -> pair safe
                        float2 o;
                        o.x = v0 + bias[n] + bias2[n];
                        o.y = v1 + bias[n + 1] + bias2[n + 1];
                        *(float2*)(out + (size_t)m * ldOut + n) = o;
                    }
                } else if (MODE == 1) {
                    if (n < KP_) {
                        float2 o;
                        o.x = (n     < N) ? fmaxf(v0 + bias[n], 0.f)     : 0.f;
                        o.y = (n + 1 < N) ? fmaxf(v1 + bias[n + 1], 0.f) : 0.f;
                        *(float2*)(out + (size_t)m * ldOut + n) = o;
                    }
                } else {
                    int tt = m >> 8, b = m & 255;
                    if (n < N)
                        out[((size_t)b * I_ + n) * T_ + tt] = sigmf(v0 + bias[n]);
                    if (n + 1 < N)
                        out[((size_t)b * I_ + n + 1) * T_ + tt] = sigmf(v1 + bias[n + 1]);
                }
            }
        }
    }
}

// ---------------- tensor-core persistent LSTM scan ------------------------------
// grid = 100 blocks: 4 batch-groups (64 batches) x 25 unit-blocks (8 units = 32
// gate-cols, col c = gate*8+ul). h exchanged through g_hs in PRE-SPLIT hi/lo
// layout -> staging is pure LDG.128/STS.128; producer does the tf32 split once.
__global__ void __launch_bounds__(256, 1) lstm_scan_tc(
    const float* __restrict__ xg, const float* __restrict__ whh,
    float* __restrict__ hs)
{
    extern __shared__ float sm[];
    float* w_s = sm;                   // 32 * 400 = 12800
    float* h_s = sm + 12800;           // 64 * 400 = 25600
    float* g_s = sm + 38400;           // 64 * 40  = 2560

    const int tid  = threadIdx.x;
    const int warp = tid >> 5, lane = tid & 31;
    const int g4 = lane >> 2, tg = lane & 3;
    const int wm = warp >> 1, wn = warp & 1;
    const int bb = blockIdx.x & 3;
    const int uu = blockIdx.x >> 2;
    const int b0 = bb * 64;
    const int u0 = uu * 8;

    // stage w_hh slice once: col c = gate*8 + unit_local, interleaved hi/lo
    for (int i = 0; i < 13; ++i) {
        int lin = tid + 256 * i;
        if (lin < 3200) {
            int c = lin / 100, rem = lin - c * 100;
            int kb = rem >> 2, tgs = rem & 3;
            int grow = (c >> 3) * H_ + u0 + (c & 7);
            int k0 = kb * 8 + tgs;
            float w0 = whh[(size_t)grow * H_ + k0];
            float w1 = whh[(size_t)grow * H_ + k0 + 4];
            float hh0 = tfhi(w0), hh1 = tfhi(w1);
            *(float4*)(w_s + c * 400 + kb * 16 + tgs * 4) =
                make_float4(hh0, hh1, tfhi(w0 - hh0), tfhi(w1 - hh1));
        }
    }

    const int eb  = tid >> 2;          // 0..63
    const int eul = (tid & 3) * 2;     // 0,2,4,6
    float c0 = 0.f, c1 = 0.f;

    const float* hA = h_s + (wm * 16 + g4) * 400 + tg * 4;
    const float* hB = hA + 8 * 400;
    const float* wA = w_s + (wn * 16 + g4) * 400 + tg * 4;
    const float* wB = wA + 8 * 400;

    // precomputed epilogue hs offsets (x & 3)*4 + (x >> 2)
    const int off0 = (eul & 3) * 4 + (eul >> 2);
    const int off1 = ((eul + 1) & 3) * 4 + ((eul + 1) >> 2);

    for (int t = 0; t < T_; ++t) {
        // prefetch xg (no h dependency) before the barrier wait
        const float* xr = xg + ((size_t)t * B_ + b0 + eb) * G_ + u0 + eul;
        float xa00 = xr[0], xa01 = xr[H_], xa02 = xr[2 * H_], xa03 = xr[3 * H_];
        float xa10 = xr[1], xa11 = xr[H_ + 1], xa12 = xr[2 * H_ + 1], xa13 = xr[3 * H_ + 1];

        if (t > 0) {
            __syncthreads();
            if (tid == 0) {
                unsigned gen = *(volatile unsigned*)&g_gen2[bb];
                if (atomicAdd(&g_cnt2[bb], 1u) == 24u) {
                    atomicExch(&g_cnt2[bb], 0u);
                    __threadfence();
                    atomicAdd(&g_gen2[bb], 1u);
                } else {
                    while (*(volatile unsigned*)&g_gen2[bb] == gen) { }
                }
                __threadfence();
            }
            __syncthreads();
        }

        // stage h(t-1): pre-split rows, pure copy
        if (t == 0) {
            float4 z = make_float4(0.f, 0.f, 0.f, 0.f);
#pragma unroll
            for (int i = 0; i < 25; ++i) {
                int lin = tid + 256 * i;
                *(float4*)(h_s + (lin / 100) * 400 + (lin % 100) * 4) = z;
            }
        } else {
            const float4* src = (const float4*)(hs + ((size_t)(t - 1) * B_ + b0) * HSW_);
#pragma unroll
            for (int i = 0; i < 25; ++i) {
                int lin = tid + 256 * i;
                int row = lin / 100, rem = lin - row * 100;
                float4 v = __ldcg(src + row * 100 + rem);
                *(float4*)(h_s + row * 400 + rem * 4) = v;
            }
        }
        __syncthreads();

        // MMA: G[64,32] = h @ w^T (3xTF32)
        float acc0[4] = {0.f, 0.f, 0.f, 0.f};
        float acc1[4] = {0.f, 0.f, 0.f, 0.f};
#pragma unroll 5
        for (int kb = 0; kb < 25; ++kb) {
            float4 A0 = *(const float4*)(hA + kb * 16);
            float4 A1 = *(const float4*)(hB + kb * 16);
            float4 B0 = *(const float4*)(wA + kb * 16);
            float4 B1 = *(const float4*)(wB + kb * 16);
            uint32_t ah[4] = {fu(A0.x), fu(A1.x), fu(A0.y), fu(A1.y)};
            uint32_t al[4] = {fu(A0.z), fu(A1.z), fu(A0.w), fu(A1.w)};
            uint32_t bh0[2] = {fu(B0.x), fu(B0.y)};
            uint32_t bl0[2] = {fu(B0.z), fu(B0.w)};
            uint32_t bh1[2] = {fu(B1.x), fu(B1.y)};
            uint32_t bl1[2] = {fu(B1.z), fu(B1.w)};
            mma_tf32(acc0, ah, bh0);
            mma_tf32(acc0, ah, bl0);
            mma_tf32(acc0, al, bh0);
            mma_tf32(acc1, ah, bh1);
            mma_tf32(acc1, ah, bl1);
            mma_tf32(acc1, al, bh1);
        }

        // accumulators -> g_s (stride 40)
        {
            float* d0 = g_s + (wm * 16 + g4) * 40 + wn * 16 + tg * 2;
            *(float2*)(d0)              = make_float2(acc0[0], acc0[1]);
            *(float2*)(d0 + 8)          = make_float2(acc1[0], acc1[1]);
            *(float2*)(d0 + 8 * 40)     = make_float2(acc0[2], acc0[3]);
            *(float2*)(d0 + 8 * 40 + 8) = make_float2(acc1[2], acc1[3]);
        }
        __syncthreads();

        // gates + cell update for (eb, eul) and (eb, eul+1); c in registers
        {
            const float* gr = g_s + eb * 40 + eul;
            float ig = sigmf(gr[0] + xa00);
            float fg = sigmf(gr[8] + xa01);
            float gg = tanh_fast(gr[16] + xa02);
            float og = sigmf(gr[24] + xa03);
            c0 = fg * c0 + ig * gg;
            float h0o = og * tanh_fast(c0);

            ig = sigmf(gr[1] + xa10);
            fg = sigmf(gr[9] + xa11);
            gg = tanh_fast(gr[17] + xa12);
            og = sigmf(gr[25] + xa13);
            c1 = fg * c1 + ig * gg;
            float h1o = og * tanh_fast(c1);

            // store h pre-split (hi/lo) into g_hs(t); kb group of this block = uu
            float hi0 = tfhi(h0o), lo0 = tfhi(h0o - hi0);
            float hi1 = tfhi(h1o), lo1 = tfhi(h1o - hi1);
            float* hb = hs + ((size_t)t * B_ + b0 + eb) * HSW_ + uu * 16;
            __stcg(hb + off0,     hi0);
            __stcg(hb + off0 + 2, lo0);
            __stcg(hb + off1,     hi1);
            __stcg(hb + off1 + 2, lo1);
        }
        __threadfence();   // make h(t) visible before next barrier arrival
    }
}

// ---------------- launch --------------------------------------------------------
extern "C" void kernel_launch(void* const* d_in, const int* in_sizes, int n_in,
                              void* d_out, int out_size)
{
    const float* x     = (const float*)d_in[0];
    const float* w_ih1 = (const float*)d_in[1];
    const float* w_hh1 = (const float*)d_in[2];
    const float* b_ih1 = (const float*)d_in[3];
    const float* b_hh1 = (const float*)d_in[4];
    const float* w_ih2 = (const float*)d_in[5];
    const float* w_hh2 = (const float*)d_in[6];
    const float* b_ih2 = (const float*)d_in[7];
    const float* b_hh2 = (const float*)d_in[8];
    const float* fc1_w = (const float*)d_in[9];
    const float* fc1_b = (const float*)d_in[10];
    const float* fc2_w = (const float*)d_in[11];
    const float* fc2_b = (const float*)d_in[12];
    float* out = (float*)d_out;

    float *xg, *hsb, *tmp, *wp1, *wp2;
    cudaGetSymbolAddress((void**)&xg,  g_xg);
    cudaGetSymbolAddress((void**)&hsb, g_hs);
    cudaGetSymbolAddress((void**)&tmp, g_tmp);
    cudaGetSymbolAddress((void**)&wp1, g_wp1);
    cudaGetSymbolAddress((void**)&wp2, g_wp2);

    const int SCAN_SMEM = (12800 + 25600 + 2560) * (int)sizeof(float); // 163840 B
    cudaFuncSetAttribute(lstm_scan_tc, cudaFuncAttributeMaxDynamicSharedMemorySize, SCAN_SMEM);

    const int GEMM_SMEM = 2 * TB2 * (int)sizeof(float);                // 73728 B
    cudaFuncSetAttribute((const void*)gemm_tc<0, false>, cudaFuncAttributeMaxDynamicSharedMemorySize, GEMM_SMEM);
    cudaFuncSetAttribute((const void*)gemm_tc<0, true>,  cudaFuncAttributeMaxDynamicSharedMemorySize, GEMM_SMEM);
    cudaFuncSetAttribute((const void*)gemm_tc<1, true>,  cudaFuncAttributeMaxDynamicSharedMemorySize, GEMM_SMEM);
    cudaFuncSetAttribute((const void*)gemm_tc<2, false>, cudaFuncAttributeMaxDynamicSharedMemorySize, GEMM_SMEM);

    const int MROWS = B_ * T_;                 // 153600
    const dim3 grows(13, MROWS / 128);         // N=800 -> 13 n-tiles
    const dim3 frows(3,  MROWS / 128);         // N up to 160 -> 3 n-tiles

    // 0. pad odd-K weights
    pad_w<<<(G_ * KP_ + 255) / 256, 256>>>(w_ih1, wp1, G_, I_);
    pad_w<<<(I_ * KP_ + 255) / 256, 256>>>(fc2_w, wp2, I_, I_);
    // 1. x -> [T*B, 160] zero-padded
    transpose_x<<<dim3((T_ + 31) / 32, KP_ / 32, B_), dim3(32, 8)>>>(x, tmp);
    // 2. xg1 = xt @ wp1^T + b_ih1 + b_hh1          (K=160)
    gemm_tc<0, false><<<grows, 256, GEMM_SMEM>>>(tmp, KP_, wp1, KP_, b_ih1, b_hh1, xg, KP_, G_, G_);
    // 3. layer-1 scan -> g_hs (pre-split)
    lstm_scan_tc<<<100, 256, SCAN_SMEM>>>(xg, w_hh1, hsb);
    // 4. xg2 = h1 @ w_ih2^T + b_ih2 + b_hh2        (A = g_hs pre-split, K=200)
    gemm_tc<0, true><<<grows, 256, GEMM_SMEM>>>(hsb, 0, w_ih2, H_, b_ih2, b_hh2, xg, H_, G_, G_);
    // 5. layer-2 scan -> g_hs (overwrites; h1 already consumed)
    lstm_scan_tc<<<100, 256, SCAN_SMEM>>>(xg, w_hh2, hsb);
    // 6. y1 = relu(h2 @ fc1_w^T + fc1_b) -> tmp[., 160] (zero-padded cols)
    gemm_tc<1, true><<<frows, 256, GEMM_SMEM>>>(hsb, 0, fc1_w, H_, fc1_b, nullptr, tmp, H_, I_, KP_);
    // 7. out = sigmoid(y1 @ wp2^T + fc2_b), transposed store to [B,129,T]
    gemm_tc<2, false><<<frows, 256, GEMM_SMEM>>>(tmp, KP_, wp2, KP_, fc2_b, nullptr, out, KP_, I_, 0);
}

// round 7
// speedup vs baseline: 1.1345x; 1.0677x over previous
#include <cuda_runtime.h>
#include <cstdint>
#include <cstdio>

#define B_   256
#define T_   600
#define I_   129
#define H_   200
#define G_   800   // 4*H
#define KP_  160   // padded K for the I=129 operands
#define HSW_ 400   // g_hs row width: 25 kb-groups * 16 floats

// ---------------- scratch (device globals; no cudaMalloc allowed) ----------------
__device__ float g_xg [(size_t)T_ * B_ * G_];     // 491.5 MB (xg1)
__device__ float g_xg2[(size_t)T_ * B_ * G_];     // 491.5 MB (xg2, produced by L1 scan)
__device__ float g_hs [(size_t)T_ * B_ * HSW_];   // 245.8 MB hi/lo-split h (both layers)
__device__ float g_tmp[(size_t)T_ * B_ * KP_];    // 98.3 MB (xt, later y1; stride 160)
__device__ float g_wp1[G_ * KP_];                 // w_ih1 padded to [800,160]
__device__ float g_wp2[I_ * KP_];                 // fc2_w padded to [129,160]

// per-batch-group barriers (4 groups of 25 blocks)
__device__ unsigned g_cnt2[4] = {0, 0, 0, 0};
__device__ unsigned g_gen2[4] = {0, 0, 0, 0};

// ---------------- fast activations ----------------
__device__ __forceinline__ float sigmf(float x) {
    return __fdividef(1.f, 1.f + __expf(-x));
}
__device__ __forceinline__ float tanh_fast(float x) {
    float e = __expf(2.f * x);
    return 1.f - __fdividef(2.f, e + 1.f);
}

// ---------------- tf32 helpers ----------------
__device__ __forceinline__ uint32_t f2tf32(float x) {
    uint32_t r;
    asm("cvt.rna.tf32.f32 %0, %1;" : "=r"(r) : "f"(x));
    return r;
}
__device__ __forceinline__ float tfhi(float v) { return __uint_as_float(f2tf32(v)); }
__device__ __forceinline__ uint32_t fu(float v) { return __float_as_uint(v); }

__device__ __forceinline__ void mma_tf32(float* d, const uint32_t* a, const uint32_t* b) {
    asm volatile(
        "mma.sync.aligned.m16n8k8.row.col.f32.tf32.tf32.f32 "
        "{%0,%1,%2,%3}, {%4,%5,%6,%7}, {%8,%9}, {%0,%1,%2,%3};"
        : "+f"(d[0]), "+f"(d[1]), "+f"(d[2]), "+f"(d[3])
        : "r"(a[0]), "r"(a[1]), "r"(a[2]), "r"(a[3]), "r"(b[0]), "r"(b[1]));
}

__device__ __forceinline__ void cpasync16(uint32_t dst, const void* src) {
    asm volatile("cp.async.cg.shared.global [%0], [%1], 16;" :: "r"(dst), "l"(src));
}

// interleaved 8-k split: q[tg] = {hi(k0+tg), hi(k0+tg+4), lo(k0+tg), lo(k0+tg+4)}
__device__ __forceinline__ void split8(float4 p0, float4 p1, float4 q[4])
{
    float h0 = tfhi(p0.x), h1 = tfhi(p0.y), h2 = tfhi(p0.z), h3 = tfhi(p0.w);
    float g0 = tfhi(p1.x), g1 = tfhi(p1.y), g2 = tfhi(p1.z), g3 = tfhi(p1.w);
    q[0] = make_float4(h0, g0, tfhi(p0.x - h0), tfhi(p1.x - g0));
    q[1] = make_float4(h1, g1, tfhi(p0.y - h1), tfhi(p1.y - g1));
    q[2] = make_float4(h2, g2, tfhi(p0.z - h2), tfhi(p1.z - g2));
    q[3] = make_float4(h3, g3, tfhi(p0.w - h3), tfhi(p1.w - g3));
}

// ---------------- weight padding ----------------
__global__ void pad_w(const float* __restrict__ w, float* __restrict__ wp, int N, int K)
{
    int i = blockIdx.x * 256 + threadIdx.x;
    if (i < N * KP_) {
        int n = i / KP_, k = i - n * KP_;
        wp[i] = (k < K) ? w[(size_t)n * K + k] : 0.f;
    }
}

// ---------------- transpose x [B,I,T] -> xt [(t*B+b), 160] (zero-padded) ----------
__global__ void transpose_x(const float* __restrict__ x, float* __restrict__ xt)
{
    __shared__ float sm[32][33];
    const int b  = blockIdx.z;
    const int i0 = blockIdx.y * 32;
    const int t0 = blockIdx.x * 32;
    const int tx = threadIdx.x, ty = threadIdx.y;
#pragma unroll
    for (int s = 0; s < 32; s += 8) {
        int i = i0 + ty + s, t = t0 + tx;
        sm[ty + s][tx] = (i < I_ && t < T_) ? x[((size_t)b * I_ + i) * T_ + t] : 0.f;
    }
    __syncthreads();
#pragma unroll
    for (int s = 0; s < 32; s += 8) {
        int t = t0 + ty + s, i = i0 + tx;
        if (t < T_ && i < KP_)
            xt[((size_t)t * B_ + b) * KP_ + i] = sm[tx][ty + s];
    }
}

// ---------------- GEMM (3xTF32, ktile 16, double-buffered, 2 CTA/SM) -------------
#define TB2 9216   // floats per buffer: 128*48 + 64*48

template <bool ASPLIT>
__device__ __forceinline__ void ld_regs(
    const float* __restrict__ A, int ldA,
    const float* __restrict__ W, int ldW,
    int m0, int n0, int N, int K, int kt, int tid,
    float4 ra[4], float4 rw[2])
{
    const float4 z = make_float4(0.f, 0.f, 0.f, 0.f);
    const int row = tid >> 1, kbl = tid & 1;
    if (ASPLIT) {
        int kb = kt * 2 + kbl;
        if (kb * 8 + 8 <= K) {
            const float4* p = (const float4*)(A + (size_t)(m0 + row) * HSW_) + kb * 4;
            ra[0] = p[0]; ra[1] = p[1]; ra[2] = p[2]; ra[3] = p[3];
        } else { ra[0] = z; ra[1] = z; ra[2] = z; ra[3] = z; }
    } else {
        int k = kt * 16 + kbl * 8;
        if (k + 8 <= K) {
            const float* p = A + (size_t)(m0 + row) * ldA + k;
            ra[0] = *(const float4*)p;
            ra[1] = *(const float4*)(p + 4);
        } else { ra[0] = z; ra[1] = z; }
    }
    if (tid < 128) {
        int wr = tid >> 1;
        int k = kt * 16 + kbl * 8;
        if (k + 8 <= K && n0 + wr < N) {
            const float* p = W + (size_t)(n0 + wr) * ldW + k;
            rw[0] = *(const float4*)p;
            rw[1] = *(const float4*)(p + 4);
        } else { rw[0] = z; rw[1] = z; }
    }
}

template <bool ASPLIT>
__device__ __forceinline__ void st_smem(float* buf, int tid, float4 ra[4], float4 rw[2])
{
    const int row = tid >> 1, kbl = tid & 1;
    {
        float4 q[4];
        if (ASPLIT) { q[0] = ra[0]; q[1] = ra[1]; q[2] = ra[2]; q[3] = ra[3]; }
        else        split8(ra[0], ra[1], q);
        float4* da = (float4*)(buf + row * 48 + kbl * 16);
        int rot = row & 3;
#pragma unroll
        for (int j = 0; j < 4; ++j) { int jj = (rot + j) & 3; da[jj] = q[jj]; }
    }
    if (tid < 128) {
        int wr = tid >> 1;
        float4 q[4];
        split8(rw[0], rw[1], q);
        float4* dw = (float4*)(buf + 6144 + wr * 48 + kbl * 16);
        int rot = wr & 3;
#pragma unroll
        for (int j = 0; j < 4; ++j) { int jj = (rot + j) & 3; dw[jj] = q[jj]; }
    }
}

__device__ __forceinline__ void mma_tile16(const float* buf, int wm, int wn,
                                           int g4, int tg, float acc[2][4][4])
{
    const float* Sw = buf + 6144;
#pragma unroll
    for (int kk = 0; kk < 2; ++kk) {
        int koff = kk * 16 + tg * 4;
        uint32_t ah[2][4], al[2][4];
#pragma unroll
        for (int mf = 0; mf < 2; ++mf) {
            const float* pa = buf + (wm * 32 + mf * 16 + g4) * 48 + koff;
            float4 A0 = *(const float4*)pa;
            float4 A1 = *(const float4*)(pa + 8 * 48);
            ah[mf][0] = fu(A0.x); ah[mf][1] = fu(A1.x);
            ah[mf][2] = fu(A0.y); ah[mf][3] = fu(A1.y);
            al[mf][0] = fu(A0.z); al[mf][1] = fu(A1.z);
            al[mf][2] = fu(A0.w); al[mf][3] = fu(A1.w);
        }
#pragma unroll
        for (int nf = 0; nf < 4; ++nf) {
            const float* pb = Sw + (wn * 32 + nf * 8 + g4) * 48 + koff;
            float4 Bv = *(const float4*)pb;
            uint32_t bh[2] = {fu(Bv.x), fu(Bv.y)};
            uint32_t bl[2] = {fu(Bv.z), fu(Bv.w)};
            mma_tf32(acc[0][nf], ah[0], bh);
            mma_tf32(acc[0][nf], ah[0], bl);
            mma_tf32(acc[0][nf], al[0], bh);
            mma_tf32(acc[1][nf], ah[1], bh);
            mma_tf32(acc[1][nf], ah[1], bl);
            mma_tf32(acc[1][nf], al[1], bh);
        }
    }
}

template <int MODE, bool ASPLIT>
__global__ void __launch_bounds__(256, 2) gemm_tc(
    const float* __restrict__ A, int ldA,
    const float* __restrict__ W, int ldW,
    const float* __restrict__ bias, const float* __restrict__ bias2,
    float* __restrict__ out, int K, int N, int ldOut)
{
    extern __shared__ float sm[];
    const int tid  = threadIdx.x;
    const int warp = tid >> 5, lane = tid & 31;
    const int wm = warp >> 1, wn = warp & 1;
    const int g4 = lane >> 2, tg = lane & 3;
    const int m0 = blockIdx.y * 128;
    const int n0 = blockIdx.x * 64;

    float acc[2][4][4] = {};
    float4 ra[4], rw[2];

    const int ktiles = (K + 15) >> 4;

    ld_regs<ASPLIT>(A, ldA, W, ldW, m0, n0, N, K, 0, tid, ra, rw);
    st_smem<ASPLIT>(sm, tid, ra, rw);
    __syncthreads();

    for (int kt = 0; kt < ktiles; ++kt) {
        if (kt + 1 < ktiles)
            ld_regs<ASPLIT>(A, ldA, W, ldW, m0, n0, N, K, kt + 1, tid, ra, rw);
        mma_tile16(sm + (kt & 1) * TB2, wm, wn, g4, tg, acc);
        if (kt + 1 < ktiles)
            st_smem<ASPLIT>(sm + ((kt + 1) & 1) * TB2, tid, ra, rw);
        __syncthreads();
    }

#pragma unroll
    for (int mf = 0; mf < 2; ++mf) {
        int m_a = m0 + wm * 32 + mf * 16 + g4;
#pragma unroll
        for (int nf = 0; nf < 4; ++nf) {
            int n = n0 + wn * 32 + nf * 8 + tg * 2;
#pragma unroll
            for (int half = 0; half < 2; ++half) {
                int m = m_a + half * 8;
                float v0 = acc[mf][nf][half * 2 + 0];
                float v1 = acc[mf][nf][half * 2 + 1];
                if (MODE == 0) {
                    if (n < N) {
                        float2 o;
                        o.x = v0 + bias[n] + bias2[n];
                        o.y = v1 + bias[n + 1] + bias2[n + 1];
                        *(float2*)(out + (size_t)m * ldOut + n) = o;
                    }
                } else if (MODE == 1) {
                    if (n < KP_) {
                        float2 o;
                        o.x = (n     < N) ? fmaxf(v0 + bias[n], 0.f)     : 0.f;
                        o.y = (n + 1 < N) ? fmaxf(v1 + bias[n + 1], 0.f) : 0.f;
                        *(float2*)(out + (size_t)m * ldOut + n) = o;
                    }
                } else {
                    int tt = m >> 8, b = m & 255;
                    if (n < N)
                        out[((size_t)b * I_ + n) * T_ + tt] = sigmf(v0 + bias[n]);
                    if (n + 1 < N)
                        out[((size_t)b * I_ + n + 1) * T_ + tt] = sigmf(v1 + bias[n + 1]);
                }
            }
        }
    }
}

// ---------------- tensor-core persistent LSTM scan ------------------------------
// grid = 100 blocks: 4 batch-groups (64 batches) x 25 unit-blocks (8 units = 32
// gate-cols, col c = gate*8+ul). h exchanged via g_hs in PRE-SPLIT hi/lo layout.
// Barrier = CG-style: one tid0 fence per step (NOT per-thread).
// FUSE: additionally computes xg2(t-1) = h(t-1) @ w_ih2_slice into xgo (the
// staged h is already in smem; +6 MMA/kb is nearly free under the sync bound).
template <bool FUSE>
__global__ void __launch_bounds__(256, 1) lstm_scan_tc(
    const float* __restrict__ xg, const float* __restrict__ whh,
    const float* __restrict__ wih2, float* __restrict__ hs,
    float* __restrict__ xgo,
    const float* __restrict__ bia, const float* __restrict__ bib)
{
    extern __shared__ float sm[];
    float* w_s  = sm;                                   // 32*400
    float* w2_s = sm + 12800;                           // 32*400 (FUSE only)
    float* h_s  = sm + (FUSE ? 25600 : 12800);          // 64*400
    float* g_s  = h_s + 25600;                          // 64*40

    const int tid  = threadIdx.x;
    const int warp = tid >> 5, lane = tid & 31;
    const int g4 = lane >> 2, tg = lane & 3;
    const int wm = warp >> 1, wn = warp & 1;
    const int bb = blockIdx.x & 3;
    const int uu = blockIdx.x >> 2;
    const int b0 = bb * 64;
    const int u0 = uu * 8;

    // stage weight slices once: col c = gate*8 + unit_local, interleaved hi/lo
    for (int i = 0; i < 13; ++i) {
        int lin = tid + 256 * i;
        if (lin < 3200) {
            int c = lin / 100, rem = lin - c * 100;
            int kb = rem >> 2, tgs = rem & 3;
            int grow = (c >> 3) * H_ + u0 + (c & 7);
            int k0 = kb * 8 + tgs;
            {
                float w0 = whh[(size_t)grow * H_ + k0];
                float w1 = whh[(size_t)grow * H_ + k0 + 4];
                float hh0 = tfhi(w0), hh1 = tfhi(w1);
                *(float4*)(w_s + c * 400 + kb * 16 + tgs * 4) =
                    make_float4(hh0, hh1, tfhi(w0 - hh0), tfhi(w1 - hh1));
            }
            if (FUSE) {
                float w0 = wih2[(size_t)grow * H_ + k0];
                float w1 = wih2[(size_t)grow * H_ + k0 + 4];
                float hh0 = tfhi(w0), hh1 = tfhi(w1);
                *(float4*)(w2_s + c * 400 + kb * 16 + tgs * 4) =
                    make_float4(hh0, hh1, tfhi(w0 - hh0), tfhi(w1 - hh1));
            }
        }
    }

    const int eb  = tid >> 2;          // 0..63
    const int eul = (tid & 3) * 2;     // 0,2,4,6
    float c0 = 0.f, c1 = 0.f;

    // biases to fold into gates (null for layer 1: xg1 already has them)
    float bs[8];
#pragma unroll
    for (int g = 0; g < 8; ++g) bs[g] = 0.f;
    if (bia) {
#pragma unroll
        for (int g = 0; g < 4; ++g) {
            bs[g]     = bia[g * H_ + u0 + eul]     + bib[g * H_ + u0 + eul];
            bs[4 + g] = bia[g * H_ + u0 + eul + 1] + bib[g * H_ + u0 + eul + 1];
        }
    }

    const float* hA = h_s + (wm * 16 + g4) * 400 + tg * 4;
    const float* hB = hA + 8 * 400;
    const float* wA = w_s + (wn * 16 + g4) * 400 + tg * 4;
    const float* wB = wA + 8 * 400;
    const float* vA = w2_s + (wn * 16 + g4) * 400 + tg * 4;
    const float* vB = vA + 8 * 400;

    const int off0 = (eul & 3) * 4 + (eul >> 2);
    const int off1 = ((eul + 1) & 3) * 4 + ((eul + 1) >> 2);
    const uint32_t h_s_u32 = (uint32_t)__cvta_generic_to_shared(h_s);

    // xg2 write coordinates (FUSE)
    const int cA = wn * 16 + tg * 2;
    const int nA = (cA >> 3) * H_ + u0 + (cA & 7);
    const int cB = cA + 8;
    const int nB = (cB >> 3) * H_ + u0 + (cB & 7);
    const int rowA = b0 + wm * 16 + g4;

    const int TEND = FUSE ? T_ + 1 : T_;

    for (int t = 0; t < TEND; ++t) {
        const bool tail = (t == T_);   // only reachable when FUSE

        float xa00, xa01, xa02, xa03, xa10, xa11, xa12, xa13;
        if (!tail) {
            const float* xr = xg + ((size_t)t * B_ + b0 + eb) * G_ + u0 + eul;
            xa00 = xr[0]; xa01 = xr[H_]; xa02 = xr[2 * H_]; xa03 = xr[3 * H_];
            xa10 = xr[1]; xa11 = xr[H_ + 1]; xa12 = xr[2 * H_ + 1]; xa13 = xr[3 * H_ + 1];
        }

        // CG-style group barrier: ONE gpu-scope fence, by tid0 only
        if (t > 0) {
            __syncthreads();                    // orders all threads' h stores (CTA scope)
            if (tid == 0) {
                __threadfence();                // publish them at gpu scope (cumulative)
                unsigned gen = *(volatile unsigned*)&g_gen2[bb];
                if (atomicAdd(&g_cnt2[bb], 1u) == 24u) {
                    atomicExch(&g_cnt2[bb], 0u);
                    __threadfence();
                    atomicAdd(&g_gen2[bb], 1u);
                } else {
                    while (*(volatile unsigned*)&g_gen2[bb] == gen) { }
                }
                __threadfence();                // acquire
            }
            __syncthreads();
        }

        // stage h(t-1): pre-split rows, cp.async pure copy
        if (t == 0) {
            float4 z = make_float4(0.f, 0.f, 0.f, 0.f);
#pragma unroll
            for (int i = 0; i < 25; ++i) {
                int lin = tid + 256 * i;
                *(float4*)(h_s + (lin / 100) * 400 + (lin % 100) * 4) = z;
            }
        } else {
            const float4* src = (const float4*)(hs + ((size_t)(t - 1) * B_ + b0) * HSW_);
#pragma unroll
            for (int i = 0; i < 25; ++i) {
                int lin = tid + 256 * i;
                int row = lin / 100, rem = lin - row * 100;
                cpasync16(h_s_u32 + (row * 400 + rem * 4) * 4, src + row * 100 + rem);
            }
            asm volatile("cp.async.commit_group;\ncp.async.wait_group 0;" ::: "memory");
        }
        __syncthreads();

        // MMA over kb: recurrence (skip at tail) + fused xg2 (FUSE, t>0)
        float acc0[4] = {0.f, 0.f, 0.f, 0.f};
        float acc1[4] = {0.f, 0.f, 0.f, 0.f};
        float xac0[4] = {0.f, 0.f, 0.f, 0.f};
        float xac1[4] = {0.f, 0.f, 0.f, 0.f};
#pragma unroll 5
        for (int kb = 0; kb < 25; ++kb) {
            float4 A0 = *(const float4*)(hA + kb * 16);
            float4 A1 = *(const float4*)(hB + kb * 16);
            uint32_t ah[4] = {fu(A0.x), fu(A1.x), fu(A0.y), fu(A1.y)};
            uint32_t al[4] = {fu(A0.z), fu(A1.z), fu(A0.w), fu(A1.w)};
            if (!tail) {
                float4 B0 = *(const float4*)(wA + kb * 16);
                float4 B1 = *(const float4*)(wB + kb * 16);
                uint32_t bh0[2] = {fu(B0.x), fu(B0.y)};
                uint32_t bl0[2] = {fu(B0.z), fu(B0.w)};
                uint32_t bh1[2] = {fu(B1.x), fu(B1.y)};
                uint32_t bl1[2] = {fu(B1.z), fu(B1.w)};
                mma_tf32(acc0, ah, bh0);
                mma_tf32(acc0, ah, bl0);
                mma_tf32(acc0, al, bh0);
                mma_tf32(acc1, ah, bh1);
                mma_tf32(acc1, ah, bl1);
                mma_tf32(acc1, al, bh1);
            }
            if (FUSE && t > 0) {
                float4 V0 = *(const float4*)(vA + kb * 16);
                float4 V1 = *(const float4*)(vB + kb * 16);
                uint32_t ch0[2] = {fu(V0.x), fu(V0.y)};
                uint32_t cl0[2] = {fu(V0.z), fu(V0.w)};
                uint32_t ch1[2] = {fu(V1.x), fu(V1.y)};
                uint32_t cl1[2] = {fu(V1.z), fu(V1.w)};
                mma_tf32(xac0, ah, ch0);
                mma_tf32(xac0, ah, cl0);
                mma_tf32(xac0, al, ch0);
                mma_tf32(xac1, ah, ch1);
                mma_tf32(xac1, ah, cl1);
                mma_tf32(xac1, al, ch1);
            }
        }

        // write xg2(t-1)
        if (FUSE && t > 0) {
            float* xo = xgo + ((size_t)(t - 1) * B_ + rowA) * G_;
            __stcg((float2*)(xo + nA),           make_float2(xac0[0], xac0[1]));
            __stcg((float2*)(xo + nB),           make_float2(xac1[0], xac1[1]));
            __stcg((float2*)(xo + 8 * G_ + nA),  make_float2(xac0[2], xac0[3]));
            __stcg((float2*)(xo + 8 * G_ + nB),  make_float2(xac1[2], xac1[3]));
        }
        if (tail) break;

        // accumulators -> g_s (stride 40)
        {
            float* d0 = g_s + (wm * 16 + g4) * 40 + wn * 16 + tg * 2;
            *(float2*)(d0)              = make_float2(acc0[0], acc0[1]);
            *(float2*)(d0 + 8)          = make_float2(acc1[0], acc1[1]);
            *(float2*)(d0 + 8 * 40)     = make_float2(acc0[2], acc0[3]);
            *(float2*)(d0 + 8 * 40 + 8) = make_float2(acc1[2], acc1[3]);
        }
        __syncthreads();

        // gates + cell update for (eb, eul) and (eb, eul+1)
        {
            const float* gr = g_s + eb * 40 + eul;
            float ig = sigmf(gr[0] + xa00 + bs[0]);
            float fg = sigmf(gr[8] + xa01 + bs[1]);
            float gg = tanh_fast(gr[16] + xa02 + bs[2]);
            float og = sigmf(gr[24] + xa03 + bs[3]);
            c0 = fg * c0 + ig * gg;
            float h0o = og * tanh_fast(c0);

            ig = sigmf(gr[1] + xa10 + bs[4]);
            fg = sigmf(gr[9] + xa11 + bs[5]);
            gg = tanh_fast(gr[17] + xa12 + bs[6]);
            og = sigmf(gr[25] + xa13 + bs[7]);
            c1 = fg * c1 + ig * gg;
            float h1o = og * tanh_fast(c1);

            float hi0 = tfhi(h0o), lo0 = tfhi(h0o - hi0);
            float hi1 = tfhi(h1o), lo1 = tfhi(h1o - hi1);
            float* hb = hs + ((size_t)t * B_ + b0 + eb) * HSW_ + uu * 16;
            __stcg(hb + off0,     hi0);
            __stcg(hb + off0 + 2, lo0);
            __stcg(hb + off1,     hi1);
            __stcg(hb + off1 + 2, lo1);
        }
        // no per-thread fence: next iteration's barrier (syncthreads + tid0 fence)
        // publishes these stores before any consumer reads them.
    }
}

// ---------------- launch --------------------------------------------------------
extern "C" void kernel_launch(void* const* d_in, const int* in_sizes, int n_in,
                              void* d_out, int out_size)
{
    const float* x     = (const float*)d_in[0];
    const float* w_ih1 = (const float*)d_in[1];
    const float* w_hh1 = (const float*)d_in[2];
    const float* b_ih1 = (const float*)d_in[3];
    const float* b_hh1 = (const float*)d_in[4];
    const float* w_ih2 = (const float*)d_in[5];
    const float* w_hh2 = (const float*)d_in[6];
    const float* b_ih2 = (const float*)d_in[7];
    const float* b_hh2 = (const float*)d_in[8];
    const float* fc1_w = (const float*)d_in[9];
    const float* fc1_b = (const float*)d_in[10];
    const float* fc2_w = (const float*)d_in[11];
    const float* fc2_b = (const float*)d_in[12];
    float* out = (float*)d_out;

    float *xg, *xg2, *hsb, *tmp, *wp1, *wp2;
    cudaGetSymbolAddress((void**)&xg,  g_xg);
    cudaGetSymbolAddress((void**)&xg2, g_xg2);
    cudaGetSymbolAddress((void**)&hsb, g_hs);
    cudaGetSymbolAddress((void**)&tmp, g_tmp);
    cudaGetSymbolAddress((void**)&wp1, g_wp1);
    cudaGetSymbolAddress((void**)&wp2, g_wp2);

    const int SCAN1_SMEM = (25600 + 25600 + 2560) * (int)sizeof(float); // 215040 B
    const int SCAN2_SMEM = (12800 + 25600 + 2560) * (int)sizeof(float); // 163840 B
    cudaFuncSetAttribute(lstm_scan_tc<true>,  cudaFuncAttributeMaxDynamicSharedMemorySize, SCAN1_SMEM);
    cudaFuncSetAttribute(lstm_scan_tc<false>, cudaFuncAttributeMaxDynamicSharedMemorySize, SCAN2_SMEM);

    const int GEMM_SMEM = 2 * TB2 * (int)sizeof(float);                 // 73728 B
    cudaFuncSetAttribute((const void*)gemm_tc<0, false>, cudaFuncAttributeMaxDynamicSharedMemorySize, GEMM_SMEM);
    cudaFuncSetAttribute((const void*)gemm_tc<1, true>,  cudaFuncAttributeMaxDynamicSharedMemorySize, GEMM_SMEM);
    cudaFuncSetAttribute((const void*)gemm_tc<2, false>, cudaFuncAttributeMaxDynamicSharedMemorySize, GEMM_SMEM);

    const int MROWS = B_ * T_;                 // 153600
    const dim3 grows(13, MROWS / 128);
    const dim3 frows(3,  MROWS / 128);

    // 0. pad odd-K weights
    pad_w<<<(G_ * KP_ + 255) / 256, 256>>>(w_ih1, wp1, G_, I_);
    pad_w<<<(I_ * KP_ + 255) / 256, 256>>>(fc2_w, wp2, I_, I_);
    // 1. x -> [T*B, 160] zero-padded
    transpose_x<<<dim3((T_ + 31) / 32, KP_ / 32, B_), dim3(32, 8)>>>(x, tmp);
    // 2. xg1 = xt @ wp1^T + b_ih1 + b_hh1
    gemm_tc<0, false><<<grows, 256, GEMM_SMEM>>>(tmp, KP_, wp1, KP_, b_ih1, b_hh1, xg, KP_, G_, G_);
    // 3. layer-1 scan (fused: also produces xg2 = h1 @ w_ih2^T, no biases)
    lstm_scan_tc<true><<<100, 256, SCAN1_SMEM>>>(xg, w_hh1, w_ih2, hsb, xg2, nullptr, nullptr);
    // 4. layer-2 scan (adds b_ih2+b_hh2 in-epilogue)
    lstm_scan_tc<false><<<100, 256, SCAN2_SMEM>>>(xg2, w_hh2, nullptr, hsb, nullptr, b_ih2, b_hh2);
    // 5. y1 = relu(h2 @ fc1_w^T + fc1_b) -> tmp[., 160]
    gemm_tc<1, true><<<frows, 256, GEMM_SMEM>>>(hsb, 0, fc1_w, H_, fc1_b, nullptr, tmp, H_, I_, KP_);
    // 6. out = sigmoid(y1 @ wp2^T + fc2_b), transposed store to [B,129,T]
    gemm_tc<2, false><<<frows, 256, GEMM_SMEM>>>(tmp, KP_, wp2, KP_, fc2_b, nullptr, out, KP_, I_, 0);
}

// round 8
// speedup vs baseline: 1.3259x; 1.1688x over previous
#include <cuda_runtime.h>
#include <cstdint>
#include <cstdio>

#define B_   256
#define T_   600
#define I_   129
#define H_   200
#define G_   800   // 4*H
#define KP_  160   // padded K for the I=129 operands
#define HPK_ 208   // packed h row: 13 kb2-groups * 16 floats (k 200..207 = garbage*0)
#define SST_ 212   // smem stride for packed rows (212 mod 32 = 20 -> conflict-free)

// ---------------- scratch (device globals; no cudaMalloc allowed) ----------------
__device__ float g_xg [(size_t)T_ * B_ * G_];     // xg1
__device__ float g_xg2[(size_t)T_ * B_ * G_];     // xg2 (produced by fused L1 scan)
__device__ float g_hs [(size_t)T_ * B_ * HPK_];   // packed tf32-rounded h (scan exchange)
__device__ float g_h2l[(size_t)T_ * B_ * H_];     // linear fp32 h2 (for fc1)
__device__ float g_tmp[(size_t)T_ * B_ * KP_];    // xt, later y1 (stride 160)
__device__ float g_wp1[G_ * KP_];                 // w_ih1 padded to [800,160]
__device__ float g_wp2[I_ * KP_];                 // fc2_w padded to [129,160]

// per-batch-group barriers (4 groups of 25 blocks)
__device__ unsigned g_cnt2[4] = {0, 0, 0, 0};
__device__ unsigned g_gen2[4] = {0, 0, 0, 0};

// ---------------- fast activations ----------------
__device__ __forceinline__ float sigmf(float x) {
    return __fdividef(1.f, 1.f + __expf(-x));
}
__device__ __forceinline__ float tanh_fast(float x) {
    float e = __expf(2.f * x);
    return 1.f - __fdividef(2.f, e + 1.f);
}

// ---------------- tf32 helpers ----------------
__device__ __forceinline__ uint32_t f2tf32(float x) {
    uint32_t r;
    asm("cvt.rna.tf32.f32 %0, %1;" : "=r"(r) : "f"(x));
    return r;
}
__device__ __forceinline__ float tfhi(float v) { return __uint_as_float(f2tf32(v)); }
__device__ __forceinline__ uint32_t fu(float v) { return __float_as_uint(v); }

__device__ __forceinline__ void mma_tf32(float* d, const uint32_t* a, const uint32_t* b) {
    asm volatile(
        "mma.sync.aligned.m16n8k8.row.col.f32.tf32.tf32.f32 "
        "{%0,%1,%2,%3}, {%4,%5,%6,%7}, {%8,%9}, {%0,%1,%2,%3};"
        : "+f"(d[0]), "+f"(d[1]), "+f"(d[2]), "+f"(d[3])
        : "r"(a[0]), "r"(a[1]), "r"(a[2]), "r"(a[3]), "r"(b[0]), "r"(b[1]));
}

__device__ __forceinline__ void cpasync16(uint32_t dst, const void* src) {
    asm volatile("cp.async.cg.shared.global [%0], [%1], 16;" :: "r"(dst), "l"(src));
}

// interleaved 8-k split: q[tg] = {hi(k0+tg), hi(k0+tg+4), lo(k0+tg), lo(k0+tg+4)}
__device__ __forceinline__ void split8(float4 p0, float4 p1, float4 q[4])
{
    float h0 = tfhi(p0.x), h1 = tfhi(p0.y), h2 = tfhi(p0.z), h3 = tfhi(p0.w);
    float g0 = tfhi(p1.x), g1 = tfhi(p1.y), g2 = tfhi(p1.z), g3 = tfhi(p1.w);
    q[0] = make_float4(h0, g0, tfhi(p0.x - h0), tfhi(p1.x - g0));
    q[1] = make_float4(h1, g1, tfhi(p0.y - h1), tfhi(p1.y - g1));
    q[2] = make_float4(h2, g2, tfhi(p0.z - h2), tfhi(p1.z - g2));
    q[3] = make_float4(h3, g3, tfhi(p0.w - h3), tfhi(p1.w - g3));
}

// packed position of element r (0..15) within a kb2 group of 16
__device__ __forceinline__ int packpos(int r) {
    return (r < 8) ? ((r & 3) * 4 + (r >> 2))
                   : (((r - 8) & 3) * 4 + ((r - 8) >> 2) + 2);
}

// ---------------- weight padding ----------------
__global__ void pad_w(const float* __restrict__ w, float* __restrict__ wp, int N, int K)
{
    int i = blockIdx.x * 256 + threadIdx.x;
    if (i < N * KP_) {
        int n = i / KP_, k = i - n * KP_;
        wp[i] = (k < K) ? w[(size_t)n * K + k] : 0.f;
    }
}

// ---------------- transpose x [B,I,T] -> xt [(t*B+b), 160] (zero-padded) ----------
__global__ void transpose_x(const float* __restrict__ x, float* __restrict__ xt)
{
    __shared__ float sm[32][33];
    const int b  = blockIdx.z;
    const int i0 = blockIdx.y * 32;
    const int t0 = blockIdx.x * 32;
    const int tx = threadIdx.x, ty = threadIdx.y;
#pragma unroll
    for (int s = 0; s < 32; s += 8) {
        int i = i0 + ty + s, t = t0 + tx;
        sm[ty + s][tx] = (i < I_ && t < T_) ? x[((size_t)b * I_ + i) * T_ + t] : 0.f;
    }
    __syncthreads();
#pragma unroll
    for (int s = 0; s < 32; s += 8) {
        int t = t0 + ty + s, i = i0 + tx;
        if (t < T_ && i < KP_)
            xt[((size_t)t * B_ + b) * KP_ + i] = sm[tx][ty + s];
    }
}

// ---------------- GEMM (3xTF32, ktile 16, double-buffered, 2 CTA/SM) -------------
#define TB2 9216   // floats per buffer: 128*48 + 64*48

__device__ __forceinline__ void ld_regs(
    const float* __restrict__ A, int ldA,
    const float* __restrict__ W, int ldW,
    int m0, int n0, int N, int K, int kt, int tid,
    float4 ra[2], float4 rw[2])
{
    const float4 z = make_float4(0.f, 0.f, 0.f, 0.f);
    const int row = tid >> 1, kbl = tid & 1;
    int k = kt * 16 + kbl * 8;
    if (k + 8 <= K) {
        const float* p = A + (size_t)(m0 + row) * ldA + k;
        ra[0] = *(const float4*)p;
        ra[1] = *(const float4*)(p + 4);
    } else { ra[0] = z; ra[1] = z; }
    if (tid < 128) {
        int wr = tid >> 1;
        if (k + 8 <= K && n0 + wr < N) {
            const float* p = W + (size_t)(n0 + wr) * ldW + k;
            rw[0] = *(const float4*)p;
            rw[1] = *(const float4*)(p + 4);
        } else { rw[0] = z; rw[1] = z; }
    }
}

__device__ __forceinline__ void st_smem(float* buf, int tid, float4 ra[2], float4 rw[2])
{
    const int row = tid >> 1, kbl = tid & 1;
    {
        float4 q[4];
        split8(ra[0], ra[1], q);
        float4* da = (float4*)(buf + row * 48 + kbl * 16);
        int rot = row & 3;
#pragma unroll
        for (int j = 0; j < 4; ++j) { int jj = (rot + j) & 3; da[jj] = q[jj]; }
    }
    if (tid < 128) {
        int wr = tid >> 1;
        float4 q[4];
        split8(rw[0], rw[1], q);
        float4* dw = (float4*)(buf + 6144 + wr * 48 + kbl * 16);
        int rot = wr & 3;
#pragma unroll
        for (int j = 0; j < 4; ++j) { int jj = (rot + j) & 3; dw[jj] = q[jj]; }
    }
}

__device__ __forceinline__ void mma_tile16(const float* buf, int wm, int wn,
                                           int g4, int tg, float acc[2][4][4])
{
    const float* Sw = buf + 6144;
#pragma unroll
    for (int kk = 0; kk < 2; ++kk) {
        int koff = kk * 16 + tg * 4;
        uint32_t ah[2][4], al[2][4];
#pragma unroll
        for (int mf = 0; mf < 2; ++mf) {
            const float* pa = buf + (wm * 32 + mf * 16 + g4) * 48 + koff;
            float4 A0 = *(const float4*)pa;
            float4 A1 = *(const float4*)(pa + 8 * 48);
            ah[mf][0] = fu(A0.x); ah[mf][1] = fu(A1.x);
            ah[mf][2] = fu(A0.y); ah[mf][3] = fu(A1.y);
            al[mf][0] = fu(A0.z); al[mf][1] = fu(A1.z);
            al[mf][2] = fu(A0.w); al[mf][3] = fu(A1.w);
        }
#pragma unroll
        for (int nf = 0; nf < 4; ++nf) {
            const float* pb = Sw + (wn * 32 + nf * 8 + g4) * 48 + koff;
            float4 Bv = *(const float4*)pb;
            uint32_t bh[2] = {fu(Bv.x), fu(Bv.y)};
            uint32_t bl[2] = {fu(Bv.z), fu(Bv.w)};
            mma_tf32(acc[0][nf], ah[0], bh);
            mma_tf32(acc[0][nf], ah[0], bl);
            mma_tf32(acc[0][nf], al[0], bh);
            mma_tf32(acc[1][nf], ah[1], bh);
            mma_tf32(acc[1][nf], ah[1], bl);
            mma_tf32(acc[1][nf], al[1], bh);
        }
    }
}

template <int MODE>
__global__ void __launch_bounds__(256, 2) gemm_tc(
    const float* __restrict__ A, int ldA,
    const float* __restrict__ W, int ldW,
    const float* __restrict__ bias, const float* __restrict__ bias2,
    float* __restrict__ out, int K, int N, int ldOut)
{
    extern __shared__ float sm[];
    const int tid  = threadIdx.x;
    const int warp = tid >> 5, lane = tid & 31;
    const int wm = warp >> 1, wn = warp & 1;
    const int g4 = lane >> 2, tg = lane & 3;
    const int m0 = blockIdx.y * 128;
    const int n0 = blockIdx.x * 64;

    float acc[2][4][4] = {};
    float4 ra[2], rw[2];

    const int ktiles = (K + 15) >> 4;

    ld_regs(A, ldA, W, ldW, m0, n0, N, K, 0, tid, ra, rw);
    st_smem(sm, tid, ra, rw);
    __syncthreads();

    for (int kt = 0; kt < ktiles; ++kt) {
        if (kt + 1 < ktiles)
            ld_regs(A, ldA, W, ldW, m0, n0, N, K, kt + 1, tid, ra, rw);
        mma_tile16(sm + (kt & 1) * TB2, wm, wn, g4, tg, acc);
        if (kt + 1 < ktiles)
            st_smem(sm + ((kt + 1) & 1) * TB2, tid, ra, rw);
        __syncthreads();
    }

#pragma unroll
    for (int mf = 0; mf < 2; ++mf) {
        int m_a = m0 + wm * 32 + mf * 16 + g4;
#pragma unroll
        for (int nf = 0; nf < 4; ++nf) {
            int n = n0 + wn * 32 + nf * 8 + tg * 2;
#pragma unroll
            for (int half = 0; half < 2; ++half) {
                int m = m_a + half * 8;
                float v0 = acc[mf][nf][half * 2 + 0];
                float v1 = acc[mf][nf][half * 2 + 1];
                if (MODE == 0) {
                    if (n < N) {
                        float2 o;
                        o.x = v0 + bias[n] + bias2[n];
                        o.y = v1 + bias[n + 1] + bias2[n + 1];
                        *(float2*)(out + (size_t)m * ldOut + n) = o;
                    }
                } else if (MODE == 1) {
                    if (n < KP_) {
                        float2 o;
                        o.x = (n     < N) ? fmaxf(v0 + bias[n], 0.f)     : 0.f;
                        o.y = (n + 1 < N) ? fmaxf(v1 + bias[n + 1], 0.f) : 0.f;
                        *(float2*)(out + (size_t)m * ldOut + n) = o;
                    }
                } else {
                    int tt = m >> 8, b = m & 255;
                    if (n < N)
                        out[((size_t)b * I_ + n) * T_ + tt] = sigmf(v0 + bias[n]);
                    if (n + 1 < N)
                        out[((size_t)b * I_ + n + 1) * T_ + tt] = sigmf(v1 + bias[n + 1]);
                }
            }
        }
    }
}

// ---------------- tensor-core persistent LSTM scan (single TF32) ----------------
// grid = 100 blocks: 4 batch-groups (64 batches) x 25 unit-blocks (8 units = 32
// gate-cols, col c = gate*8+ul). h stored tf32-rounded in packed rows of 208
// (13 kb2 groups of float4 {v(k+tg), v(k+tg+4), v(k+8+tg), v(k+8+tg+4)}).
// Weight slots for k>=200 are zeroed, so garbage h tail contributes nothing.
// FUSE: also computes xg2(t-1) = h(t-1) @ w_ih2^T. WRITELIN: also stores
// full-precision linear h rows for the downstream FC GEMM.
template <bool FUSE, bool WRITELIN>
__global__ void __launch_bounds__(256, 1) lstm_scan_tc(
    const float* __restrict__ xg, const float* __restrict__ whh,
    const float* __restrict__ wih2, float* __restrict__ hs,
    float* __restrict__ hlin, float* __restrict__ xgo,
    const float* __restrict__ bia, const float* __restrict__ bib)
{
    extern __shared__ float sm[];
    float* w_s  = sm;                                       // 32*212
    float* w2_s = sm + 32 * SST_;                           // 32*212 (FUSE only)
    float* h_s  = sm + (FUSE ? 64 : 32) * SST_;             // 64*212
    float* g_s  = h_s + 64 * SST_;                          // 64*40

    const int tid  = threadIdx.x;
    const int warp = tid >> 5, lane = tid & 31;
    const int g4 = lane >> 2, tg = lane & 3;
    const int wm = warp >> 1, wn = warp & 1;
    const int bb = blockIdx.x & 3;
    const int uu = blockIdx.x >> 2;
    const int b0 = bb * 64;
    const int u0 = uu * 8;

    // stage weight slices once: col c = gate*8 + ul, packed tf32 (zeros for k>=200)
    for (int i = 0; i < 7; ++i) {
        int lin = tid + 256 * i;                       // 32 cols * 52 slots = 1664
        if (lin < 1664) {
            int c = lin / 52, rem = lin - c * 52;
            int kb2 = rem >> 2, tgs = rem & 3;
            int grow = (c >> 3) * H_ + u0 + (c & 7);
            int k0 = kb2 * 16;
            int e0 = k0 + tgs, e1 = k0 + tgs + 4, e2 = k0 + 8 + tgs, e3 = k0 + 12 + tgs;
            const float* wr_ = whh + (size_t)grow * H_;
            float4 v;
            v.x = (e0 < H_) ? tfhi(wr_[e0]) : 0.f;
            v.y = (e1 < H_) ? tfhi(wr_[e1]) : 0.f;
            v.z = (e2 < H_) ? tfhi(wr_[e2]) : 0.f;
            v.w = (e3 < H_) ? tfhi(wr_[e3]) : 0.f;
            *(float4*)(w_s + c * SST_ + kb2 * 16 + tgs * 4) = v;
            if (FUSE) {
                const float* w2r = wih2 + (size_t)grow * H_;
                float4 u;
                u.x = (e0 < H_) ? tfhi(w2r[e0]) : 0.f;
                u.y = (e1 < H_) ? tfhi(w2r[e1]) : 0.f;
                u.z = (e2 < H_) ? tfhi(w2r[e2]) : 0.f;
                u.w = (e3 < H_) ? tfhi(w2r[e3]) : 0.f;
                *(float4*)(w2_s + c * SST_ + kb2 * 16 + tgs * 4) = u;
            }
        }
    }

    const int eb  = tid >> 2;          // 0..63
    const int eul = (tid & 3) * 2;     // 0,2,4,6
    float c0 = 0.f, c1 = 0.f;

    // biases folded into gates (layer 1 passes null: xg1 already has them)
    float bs[8];
#pragma unroll
    for (int g = 0; g < 8; ++g) bs[g] = 0.f;
    if (bia) {
#pragma unroll
        for (int g = 0; g < 4; ++g) {
            bs[g]     = bia[g * H_ + u0 + eul]     + bib[g * H_ + u0 + eul];
            bs[4 + g] = bia[g * H_ + u0 + eul + 1] + bib[g * H_ + u0 + eul + 1];
        }
    }

    const float* hA = h_s + (wm * 16 + g4) * SST_ + tg * 4;
    const float* hB = hA + 8 * SST_;
    const float* wA = w_s + (wn * 16 + g4) * SST_ + tg * 4;
    const float* wB = wA + 8 * SST_;
    const float* vA = w2_s + (wn * 16 + g4) * SST_ + tg * 4;
    const float* vB = vA + 8 * SST_;

    // packed h output offsets for this thread's two units
    const int kb2o = uu >> 1;
    const int r0 = (uu & 1) * 8 + eul;
    const int off0 = kb2o * 16 + packpos(r0);
    const int off1 = kb2o * 16 + packpos(r0 + 1);
    const uint32_t h_s_u32 = (uint32_t)__cvta_generic_to_shared(h_s);

    // xg2 write coordinates (FUSE)
    const int cA = wn * 16 + tg * 2;
    const int nA = (cA >> 3) * H_ + u0 + (cA & 7);
    const int cB = cA + 8;
    const int nB = (cB >> 3) * H_ + u0 + (cB & 7);
    const int rowA = b0 + wm * 16 + g4;

    const int TEND = FUSE ? T_ + 1 : T_;

    for (int t = 0; t < TEND; ++t) {
        const bool tail = (t == T_);   // only reachable when FUSE

        float xa00, xa01, xa02, xa03, xa10, xa11, xa12, xa13;
        if (!tail) {
            const float* xr = xg + ((size_t)t * B_ + b0 + eb) * G_ + u0 + eul;
            xa00 = xr[0]; xa01 = xr[H_]; xa02 = xr[2 * H_]; xa03 = xr[3 * H_];
            xa10 = xr[1]; xa11 = xr[H_ + 1]; xa12 = xr[2 * H_ + 1]; xa13 = xr[3 * H_ + 1];
        }

        // CG-style group barrier: ONE gpu-scope fence by tid0
        if (t > 0) {
            __syncthreads();
            if (tid == 0) {
                __threadfence();
                unsigned gen = *(volatile unsigned*)&g_gen2[bb];
                if (atomicAdd(&g_cnt2[bb], 1u) == 24u) {
                    atomicExch(&g_cnt2[bb], 0u);
                    __threadfence();
                    atomicAdd(&g_gen2[bb], 1u);
                } else {
                    while (*(volatile unsigned*)&g_gen2[bb] == gen) { }
                }
                __threadfence();
            }
            __syncthreads();
        }

        // stage h(t-1): packed rows, pure cp.async copy (52 float4 per row)
        if (t == 0) {
            float4 z = make_float4(0.f, 0.f, 0.f, 0.f);
            for (int lin = tid; lin < 64 * 53; lin += 256)
                *(float4*)(h_s + lin * 4) = z;
        } else {
            const float4* src = (const float4*)(hs + ((size_t)(t - 1) * B_ + b0) * HPK_);
#pragma unroll
            for (int i = 0; i < 13; ++i) {
                int lin = tid + 256 * i;               // 64*52 = 3328
                int row = lin / 52, rem = lin - row * 52;
                cpasync16(h_s_u32 + (row * SST_ + rem * 4) * 4, src + row * 52 + rem);
            }
            asm volatile("cp.async.commit_group;\ncp.async.wait_group 0;" ::: "memory");
        }
        __syncthreads();

        // MMA: single tf32, 13 kb2 groups (2 k8-frags per packed float4)
        float acc0[4] = {0.f, 0.f, 0.f, 0.f};
        float acc1[4] = {0.f, 0.f, 0.f, 0.f};
        float xac0[4] = {0.f, 0.f, 0.f, 0.f};
        float xac1[4] = {0.f, 0.f, 0.f, 0.f};
#pragma unroll
        for (int kb2 = 0; kb2 < 13; ++kb2) {
            float4 A0 = *(const float4*)(hA + kb2 * 16);
            float4 A1 = *(const float4*)(hB + kb2 * 16);
            uint32_t aA[4] = {fu(A0.x), fu(A1.x), fu(A0.y), fu(A1.y)};
            uint32_t aB[4] = {fu(A0.z), fu(A1.z), fu(A0.w), fu(A1.w)};
            if (!tail) {
                float4 B0 = *(const float4*)(wA + kb2 * 16);
                float4 B1 = *(const float4*)(wB + kb2 * 16);
                uint32_t b0A[2] = {fu(B0.x), fu(B0.y)};
                uint32_t b0B[2] = {fu(B0.z), fu(B0.w)};
                uint32_t b1A[2] = {fu(B1.x), fu(B1.y)};
                uint32_t b1B[2] = {fu(B1.z), fu(B1.w)};
                mma_tf32(acc0, aA, b0A);
                mma_tf32(acc0, aB, b0B);
                mma_tf32(acc1, aA, b1A);
                mma_tf32(acc1, aB, b1B);
            }
            if (FUSE && t > 0) {
                float4 V0 = *(const float4*)(vA + kb2 * 16);
                float4 V1 = *(const float4*)(vB + kb2 * 16);
                uint32_t c0A[2] = {fu(V0.x), fu(V0.y)};
                uint32_t c0B[2] = {fu(V0.z), fu(V0.w)};
                uint32_t c1A[2] = {fu(V1.x), fu(V1.y)};
                uint32_t c1B[2] = {fu(V1.z), fu(V1.w)};
                mma_tf32(xac0, aA, c0A);
                mma_tf32(xac0, aB, c0B);
                mma_tf32(xac1, aA, c1A);
                mma_tf32(xac1, aB, c1B);
            }
        }

        // write xg2(t-1)
        if (FUSE && t > 0) {
            float* xo = xgo + ((size_t)(t - 1) * B_ + rowA) * G_;
            __stcg((float2*)(xo + nA),           make_float2(xac0[0], xac0[1]));
            __stcg((float2*)(xo + nB),           make_float2(xac1[0], xac1[1]));
            __stcg((float2*)(xo + 8 * G_ + nA),  make_float2(xac0[2], xac0[3]));
            __stcg((float2*)(xo + 8 * G_ + nB),  make_float2(xac1[2], xac1[3]));
        }
        if (tail) break;

        // accumulators -> g_s (stride 40)
        {
            float* d0 = g_s + (wm * 16 + g4) * 40 + wn * 16 + tg * 2;
            *(float2*)(d0)              = make_float2(acc0[0], acc0[1]);
            *(float2*)(d0 + 8)          = make_float2(acc1[0], acc1[1]);
            *(float2*)(d0 + 8 * 40)     = make_float2(acc0[2], acc0[3]);
            *(float2*)(d0 + 8 * 40 + 8) = make_float2(acc1[2], acc1[3]);
        }
        __syncthreads();

        // gates + cell update for (eb, eul) and (eb, eul+1)
        {
            const float* gr = g_s + eb * 40 + eul;
            float ig = sigmf(gr[0] + xa00 + bs[0]);
            float fg = sigmf(gr[8] + xa01 + bs[1]);
            float gg = tanh_fast(gr[16] + xa02 + bs[2]);
            float og = sigmf(gr[24] + xa03 + bs[3]);
            c0 = fg * c0 + ig * gg;
            float h0o = og * tanh_fast(c0);

            ig = sigmf(gr[1] + xa10 + bs[4]);
            fg = sigmf(gr[9] + xa11 + bs[5]);
            gg = tanh_fast(gr[17] + xa12 + bs[6]);
            og = sigmf(gr[25] + xa13 + bs[7]);
            c1 = fg * c1 + ig * gg;
            float h1o = og * tanh_fast(c1);

            // packed tf32-rounded h for the recurrence
            float* hb = hs + ((size_t)t * B_ + b0 + eb) * HPK_;
            __stcg(hb + off0, tfhi(h0o));
            __stcg(hb + off1, tfhi(h1o));
            if (WRITELIN) {
                float* hl = hlin + ((size_t)t * B_ + b0 + eb) * H_ + u0 + eul;
                __stcg((float2*)hl, make_float2(h0o, h1o));
            }
        }
    }
}

// ---------------- launch --------------------------------------------------------
extern "C" void kernel_launch(void* const* d_in, const int* in_sizes, int n_in,
                              void* d_out, int out_size)
{
    const float* x     = (const float*)d_in[0];
    const float* w_ih1 = (const float*)d_in[1];
    const float* w_hh1 = (const float*)d_in[2];
    const float* b_ih1 = (const float*)d_in[3];
    const float* b_hh1 = (const float*)d_in[4];
    const float* w_ih2 = (const float*)d_in[5];
    const float* w_hh2 = (const float*)d_in[6];
    const float* b_ih2 = (const float*)d_in[7];
    const float* b_hh2 = (const float*)d_in[8];
    const float* fc1_w = (const float*)d_in[9];
    const float* fc1_b = (const float*)d_in[10];
    const float* fc2_w = (const float*)d_in[11];
    const float* fc2_b = (const float*)d_in[12];
    float* out = (float*)d_out;

    float *xg, *xg2, *hsb, *h2l, *tmp, *wp1, *wp2;
    cudaGetSymbolAddress((void**)&xg,  g_xg);
    cudaGetSymbolAddress((void**)&xg2, g_xg2);
    cudaGetSymbolAddress((void**)&hsb, g_hs);
    cudaGetSymbolAddress((void**)&h2l, g_h2l);
    cudaGetSymbolAddress((void**)&tmp, g_tmp);
    cudaGetSymbolAddress((void**)&wp1, g_wp1);
    cudaGetSymbolAddress((void**)&wp2, g_wp2);

    const int SCAN1_SMEM = (64 * SST_ + 64 * SST_ + 2560) * (int)sizeof(float); // 118784
    const int SCAN2_SMEM = (32 * SST_ + 64 * SST_ + 2560) * (int)sizeof(float); // 91648
    cudaFuncSetAttribute((const void*)lstm_scan_tc<true, false>,
                         cudaFuncAttributeMaxDynamicSharedMemorySize, SCAN1_SMEM);
    cudaFuncSetAttribute((const void*)lstm_scan_tc<false, true>,
                         cudaFuncAttributeMaxDynamicSharedMemorySize, SCAN2_SMEM);

    const int GEMM_SMEM = 2 * TB2 * (int)sizeof(float);                 // 73728
    cudaFuncSetAttribute((const void*)gemm_tc<0>, cudaFuncAttributeMaxDynamicSharedMemorySize, GEMM_SMEM);
    cudaFuncSetAttribute((const void*)gemm_tc<1>, cudaFuncAttributeMaxDynamicSharedMemorySize, GEMM_SMEM);
    cudaFuncSetAttribute((const void*)gemm_tc<2>, cudaFuncAttributeMaxDynamicSharedMemorySize, GEMM_SMEM);

    const int MROWS = B_ * T_;                 // 153600
    const dim3 grows(13, MROWS / 128);
    const dim3 frows(3,  MROWS / 128);

    // 0. pad odd-K weights
    pad_w<<<(G_ * KP_ + 255) / 256, 256>>>(w_ih1, wp1, G_, I_);
    pad_w<<<(I_ * KP_ + 255) / 256, 256>>>(fc2_w, wp2, I_, I_);
    // 1. x -> [T*B, 160] zero-padded
    transpose_x<<<dim3((T_ + 31) / 32, KP_ / 32, B_), dim3(32, 8)>>>(x, tmp);
    // 2. xg1 = xt @ wp1^T + b_ih1 + b_hh1   (3xTF32, exact-ish)
    gemm_tc<0><<<grows, 256, GEMM_SMEM>>>(tmp, KP_, wp1, KP_, b_ih1, b_hh1, xg, KP_, G_, G_);
    // 3. layer-1 scan (single tf32; fused xg2 = h1 @ w_ih2^T)
    lstm_scan_tc<true, false><<<100, 256, SCAN1_SMEM>>>(
        xg, w_hh1, w_ih2, hsb, nullptr, xg2, nullptr, nullptr);
    // 4. layer-2 scan (adds b_ih2+b_hh2; writes linear h2 for fc1)
    lstm_scan_tc<false, true><<<100, 256, SCAN2_SMEM>>>(
        xg2, w_hh2, nullptr, hsb, h2l, nullptr, b_ih2, b_hh2);
    // 5. y1 = relu(h2 @ fc1_w^T + fc1_b) -> tmp[., 160]
    gemm_tc<1><<<frows, 256, GEMM_SMEM>>>(h2l, H_, fc1_w, H_, fc1_b, nullptr, tmp, H_, I_, KP_);
    // 6. out = sigmoid(y1 @ wp2^T + fc2_b), transposed store to [B,129,T]
    gemm_tc<2><<<frows, 256, GEMM_SMEM>>>(tmp, KP_, wp2, KP_, fc2_b, nullptr, out, KP_, I_, 0);
}

// round 9
// speedup vs baseline: 1.6512x; 1.2453x over previous
#include <cuda_runtime.h>
#include <cstdint>
#include <cstdio>

#define B_   256
#define T_   600
#define I_   129
#define H_   200
#define G_   800   // 4*H
#define KP_  160   // padded K for the I=129 operands
#define HPK_ 208   // packed h row: 13 kb2-groups * 16 floats
#define SST_ 212   // smem stride for packed rows (212 mod 32 = 20)

// ---------------- scratch (device globals; no cudaMalloc allowed) ----------------
__device__ float g_xg [(size_t)T_ * B_ * G_];     // xg1 (with biases)
__device__ float g_xg2[(size_t)T_ * B_ * G_];     // xg2 (with biases, from L1 wave)
__device__ float g_hs1[(size_t)T_ * B_ * HPK_];   // packed tf32 h, layer 1
__device__ float g_hs2[(size_t)T_ * B_ * HPK_];   // packed tf32 h, layer 2
__device__ float g_h2l[(size_t)T_ * B_ * H_];     // linear fp32 h2 (for fc1)
__device__ float g_tmp[(size_t)T_ * B_ * KP_];    // xt, later y1 (stride 160)
__device__ float g_wp1[G_ * KP_];
__device__ float g_wp2[I_ * KP_];

// barriers: 4 groups (L1 g0,g1; L2 g0,g1), 25 blocks each
__device__ unsigned g_cnt2[4] = {0, 0, 0, 0};
__device__ unsigned g_gen2[4] = {0, 0, 0, 0};
// L1 -> L2 progress flags (value = completed L1 step; reset by consumer at end)
__device__ unsigned g_l1prog[2][25];

// ---------------- fast activations ----------------
__device__ __forceinline__ float sigmf(float x) {
    return __fdividef(1.f, 1.f + __expf(-x));
}
__device__ __forceinline__ float tanh_fast(float x) {
    float e = __expf(2.f * x);
    return 1.f - __fdividef(2.f, e + 1.f);
}

// ---------------- tf32 helpers ----------------
__device__ __forceinline__ uint32_t f2tf32(float x) {
    uint32_t r;
    asm("cvt.rna.tf32.f32 %0, %1;" : "=r"(r) : "f"(x));
    return r;
}
__device__ __forceinline__ float tfhi(float v) { return __uint_as_float(f2tf32(v)); }
__device__ __forceinline__ uint32_t fu(float v) { return __float_as_uint(v); }

__device__ __forceinline__ void mma_tf32(float* d, const uint32_t* a, const uint32_t* b) {
    asm volatile(
        "mma.sync.aligned.m16n8k8.row.col.f32.tf32.tf32.f32 "
        "{%0,%1,%2,%3}, {%4,%5,%6,%7}, {%8,%9}, {%0,%1,%2,%3};"
        : "+f"(d[0]), "+f"(d[1]), "+f"(d[2]), "+f"(d[3])
        : "r"(a[0]), "r"(a[1]), "r"(a[2]), "r"(a[3]), "r"(b[0]), "r"(b[1]));
}

__device__ __forceinline__ void cpasync16(uint32_t dst, const void* src) {
    asm volatile("cp.async.cg.shared.global [%0], [%1], 16;" :: "r"(dst), "l"(src));
}

// interleaved 8-k split for the 3xTF32 GEMMs
__device__ __forceinline__ void split8(float4 p0, float4 p1, float4 q[4])
{
    float h0 = tfhi(p0.x), h1 = tfhi(p0.y), h2 = tfhi(p0.z), h3 = tfhi(p0.w);
    float g0 = tfhi(p1.x), g1 = tfhi(p1.y), g2 = tfhi(p1.z), g3 = tfhi(p1.w);
    q[0] = make_float4(h0, g0, tfhi(p0.x - h0), tfhi(p1.x - g0));
    q[1] = make_float4(h1, g1, tfhi(p0.y - h1), tfhi(p1.y - g1));
    q[2] = make_float4(h2, g2, tfhi(p0.z - h2), tfhi(p1.z - g2));
    q[3] = make_float4(h3, g3, tfhi(p0.w - h3), tfhi(p1.w - g3));
}

// ---------------- weight padding ----------------
__global__ void pad_w(const float* __restrict__ w, float* __restrict__ wp, int N, int K)
{
    int i = blockIdx.x * 256 + threadIdx.x;
    if (i < N * KP_) {
        int n = i / KP_, k = i - n * KP_;
        wp[i] = (k < K) ? w[(size_t)n * K + k] : 0.f;
    }
}

// ---------------- transpose x [B,I,T] -> xt [(t*B+b), 160] ----------------
__global__ void transpose_x(const float* __restrict__ x, float* __restrict__ xt)
{
    __shared__ float sm[32][33];
    const int b  = blockIdx.z;
    const int i0 = blockIdx.y * 32;
    const int t0 = blockIdx.x * 32;
    const int tx = threadIdx.x, ty = threadIdx.y;
#pragma unroll
    for (int s = 0; s < 32; s += 8) {
        int i = i0 + ty + s, t = t0 + tx;
        sm[ty + s][tx] = (i < I_ && t < T_) ? x[((size_t)b * I_ + i) * T_ + t] : 0.f;
    }
    __syncthreads();
#pragma unroll
    for (int s = 0; s < 32; s += 8) {
        int t = t0 + ty + s, i = i0 + tx;
        if (t < T_ && i < KP_)
            xt[((size_t)t * B_ + b) * KP_ + i] = sm[tx][ty + s];
    }
}

// ---------------- GEMM (3xTF32, ktile 16, double-buffered, 2 CTA/SM) -------------
#define TB2 9216

__device__ __forceinline__ void ld_regs(
    const float* __restrict__ A, int ldA,
    const float* __restrict__ W, int ldW,
    int m0, int n0, int N, int K, int kt, int tid,
    float4 ra[2], float4 rw[2])
{
    const float4 z = make_float4(0.f, 0.f, 0.f, 0.f);
    const int row = tid >> 1, kbl = tid & 1;
    int k = kt * 16 + kbl * 8;
    if (k + 8 <= K) {
        const float* p = A + (size_t)(m0 + row) * ldA + k;
        ra[0] = *(const float4*)p;
        ra[1] = *(const float4*)(p + 4);
    } else { ra[0] = z; ra[1] = z; }
    if (tid < 128) {
        int wr = tid >> 1;
        if (k + 8 <= K && n0 + wr < N) {
            const float* p = W + (size_t)(n0 + wr) * ldW + k;
            rw[0] = *(const float4*)p;
            rw[1] = *(const float4*)(p + 4);
        } else { rw[0] = z; rw[1] = z; }
    }
}

__device__ __forceinline__ void st_smem(float* buf, int tid, float4 ra[2], float4 rw[2])
{
    const int row = tid >> 1, kbl = tid & 1;
    {
        float4 q[4];
        split8(ra[0], ra[1], q);
        float4* da = (float4*)(buf + row * 48 + kbl * 16);
        int rot = row & 3;
#pragma unroll
        for (int j = 0; j < 4; ++j) { int jj = (rot + j) & 3; da[jj] = q[jj]; }
    }
    if (tid < 128) {
        int wr = tid >> 1;
        float4 q[4];
        split8(rw[0], rw[1], q);
        float4* dw = (float4*)(buf + 6144 + wr * 48 + kbl * 16);
        int rot = wr & 3;
#pragma unroll
        for (int j = 0; j < 4; ++j) { int jj = (rot + j) & 3; dw[jj] = q[jj]; }
    }
}

__device__ __forceinline__ void mma_tile16(const float* buf, int wm, int wn,
                                           int g4, int tg, float acc[2][4][4])
{
    const float* Sw = buf + 6144;
#pragma unroll
    for (int kk = 0; kk < 2; ++kk) {
        int koff = kk * 16 + tg * 4;
        uint32_t ah[2][4], al[2][4];
#pragma unroll
        for (int mf = 0; mf < 2; ++mf) {
            const float* pa = buf + (wm * 32 + mf * 16 + g4) * 48 + koff;
            float4 A0 = *(const float4*)pa;
            float4 A1 = *(const float4*)(pa + 8 * 48);
            ah[mf][0] = fu(A0.x); ah[mf][1] = fu(A1.x);
            ah[mf][2] = fu(A0.y); ah[mf][3] = fu(A1.y);
            al[mf][0] = fu(A0.z); al[mf][1] = fu(A1.z);
            al[mf][2] = fu(A0.w); al[mf][3] = fu(A1.w);
        }
#pragma unroll
        for (int nf = 0; nf < 4; ++nf) {
            const float* pb = Sw + (wn * 32 + nf * 8 + g4) * 48 + koff;
            float4 Bv = *(const float4*)pb;
            uint32_t bh[2] = {fu(Bv.x), fu(Bv.y)};
            uint32_t bl[2] = {fu(Bv.z), fu(Bv.w)};
            mma_tf32(acc[0][nf], ah[0], bh);
            mma_tf32(acc[0][nf], ah[0], bl);
            mma_tf32(acc[0][nf], al[0], bh);
            mma_tf32(acc[1][nf], ah[1], bh);
            mma_tf32(acc[1][nf], ah[1], bl);
            mma_tf32(acc[1][nf], al[1], bh);
        }
    }
}

template <int MODE>
__global__ void __launch_bounds__(256, 2) gemm_tc(
    const float* __restrict__ A, int ldA,
    const float* __restrict__ W, int ldW,
    const float* __restrict__ bias, const float* __restrict__ bias2,
    float* __restrict__ out, int K, int N, int ldOut)
{
    extern __shared__ float sm[];
    const int tid  = threadIdx.x;
    const int warp = tid >> 5, lane = tid & 31;
    const int wm = warp >> 1, wn = warp & 1;
    const int g4 = lane >> 2, tg = lane & 3;
    const int m0 = blockIdx.y * 128;
    const int n0 = blockIdx.x * 64;

    float acc[2][4][4] = {};
    float4 ra[2], rw[2];

    const int ktiles = (K + 15) >> 4;

    ld_regs(A, ldA, W, ldW, m0, n0, N, K, 0, tid, ra, rw);
    st_smem(sm, tid, ra, rw);
    __syncthreads();

    for (int kt = 0; kt < ktiles; ++kt) {
        if (kt + 1 < ktiles)
            ld_regs(A, ldA, W, ldW, m0, n0, N, K, kt + 1, tid, ra, rw);
        mma_tile16(sm + (kt & 1) * TB2, wm, wn, g4, tg, acc);
        if (kt + 1 < ktiles)
            st_smem(sm + ((kt + 1) & 1) * TB2, tid, ra, rw);
        __syncthreads();
    }

#pragma unroll
    for (int mf = 0; mf < 2; ++mf) {
        int m_a = m0 + wm * 32 + mf * 16 + g4;
#pragma unroll
        for (int nf = 0; nf < 4; ++nf) {
            int n = n0 + wn * 32 + nf * 8 + tg * 2;
#pragma unroll
            for (int half = 0; half < 2; ++half) {
                int m = m_a + half * 8;
                float v0 = acc[mf][nf][half * 2 + 0];
                float v1 = acc[mf][nf][half * 2 + 1];
                if (MODE == 0) {
                    if (n < N) {
                        float2 o;
                        o.x = v0 + bias[n] + bias2[n];
                        o.y = v1 + bias[n + 1] + bias2[n + 1];
                        *(float2*)(out + (size_t)m * ldOut + n) = o;
                    }
                } else if (MODE == 1) {
                    if (n < KP_) {
                        float2 o;
                        o.x = (n     < N) ? fmaxf(v0 + bias[n], 0.f)     : 0.f;
                        o.y = (n + 1 < N) ? fmaxf(v1 + bias[n + 1], 0.f) : 0.f;
                        *(float2*)(out + (size_t)m * ldOut + n) = o;
                    }
                } else {
                    int tt = m >> 8, b = m & 255;
                    if (n < N)
                        out[((size_t)b * I_ + n) * T_ + tt] = sigmf(v0 + bias[n]);
                    if (n + 1 < N)
                        out[((size_t)b * I_ + n + 1) * T_ + tt] = sigmf(v1 + bias[n + 1]);
                }
            }
        }
    }
}

// ---------------- wavefront LSTM: both layers in one persistent kernel ----------
// 100 blocks: blockIdx < 50 -> layer 1, else layer 2 (one step behind).
// Per layer: 2 batch groups x 128 batches, 25 unit-blocks (8 units = 32 gate cols).
// L1 fused-produces xg2 (+L2 biases); L2 consumes it via per-block progress flags.
// h exchanged in packed tf32 rows (208 floats); single-TF32 recurrence MMA.
__global__ void __launch_bounds__(256, 1) lstm_wave(
    const float* __restrict__ xg1, const float* __restrict__ whh1,
    const float* __restrict__ wih2, const float* __restrict__ whh2,
    const float* __restrict__ bi2,  const float* __restrict__ bh2,
    float* __restrict__ hs1, float* __restrict__ hs2,
    float* __restrict__ h2l, float* __restrict__ xg2)
{
    extern __shared__ float sm[];
    float* w_s  = sm;                   // 32*212
    float* w2_s = sm + 32 * SST_;       // 32*212 (L1 only)
    float* h_s  = sm + 64 * SST_;       // 128*212
    float* g_s  = sm + 192 * SST_;      // 128*40

    const int tid  = threadIdx.x;
    const int warp = tid >> 5, lane = tid & 31;
    const int g4 = lane >> 2, tg = lane & 3;
    const int wm = warp >> 1;           // 0..3 -> rows wm*32..wm*32+31
    const int wn = warp & 1;            // 0..1 -> cols wn*16..wn*16+15

    const int role = (blockIdx.x >= 50);        // 0 = L1, 1 = L2
    const int bid  = blockIdx.x - role * 50;
    const int grp  = bid / 25;
    const int ublk = bid - grp * 25;
    const int gb0  = grp * 128;
    const int u0   = ublk * 8;
    const int barid = role * 2 + grp;

    const float* xgsrc = role ? xg2 : xg1;
    const float* whh   = role ? whh2 : whh1;
    float* hsout = role ? hs2 : hs1;
    unsigned* flag = &g_l1prog[grp][ublk];

    // ---- stage weight slices (packed tf32, zero for k>=200) ----
    for (int i = 0; i < 7; ++i) {
        int lin = tid + 256 * i;
        if (lin < 1664) {
            int c = lin / 52, rem = lin - c * 52;
            int kb2 = rem >> 2, tgs = rem & 3;
            int grow = (c >> 3) * H_ + u0 + (c & 7);
            int k0 = kb2 * 16;
            int e0 = k0 + tgs, e1 = k0 + tgs + 4, e2 = k0 + 8 + tgs, e3 = k0 + 12 + tgs;
            const float* wr_ = whh + (size_t)grow * H_;
            float4 v;
            v.x = (e0 < H_) ? tfhi(wr_[e0]) : 0.f;
            v.y = (e1 < H_) ? tfhi(wr_[e1]) : 0.f;
            v.z = (e2 < H_) ? tfhi(wr_[e2]) : 0.f;
            v.w = (e3 < H_) ? tfhi(wr_[e3]) : 0.f;
            *(float4*)(w_s + c * SST_ + kb2 * 16 + tgs * 4) = v;
            if (!role) {
                const float* w2r = wih2 + (size_t)grow * H_;
                float4 u;
                u.x = (e0 < H_) ? tfhi(w2r[e0]) : 0.f;
                u.y = (e1 < H_) ? tfhi(w2r[e1]) : 0.f;
                u.z = (e2 < H_) ? tfhi(w2r[e2]) : 0.f;
                u.w = (e3 < H_) ? tfhi(w2r[e3]) : 0.f;
                *(float4*)(w2_s + c * SST_ + kb2 * 16 + tgs * 4) = u;
            }
        }
    }

    // L2 bias fold for xg2 writes (L1 role only); cols this thread stores
    const int nc0 = (wn * 2 + 0) * H_ + u0 + tg * 2;
    const int nc1 = (wn * 2 + 1) * H_ + u0 + tg * 2;
    float bf00 = 0.f, bf01 = 0.f, bf10 = 0.f, bf11 = 0.f;
    if (!role) {
        bf00 = bi2[nc0] + bh2[nc0];     bf01 = bi2[nc0 + 1] + bh2[nc0 + 1];
        bf10 = bi2[nc1] + bh2[nc1];     bf11 = bi2[nc1 + 1] + bh2[nc1 + 1];
    }

    // epilogue ownership: 1 batch x 4 units per thread
    const int eb  = tid >> 1;           // 0..127
    const int eul = (tid & 1) * 4;      // 0 or 4
    float cc0 = 0.f, cc1 = 0.f, cc2 = 0.f, cc3 = 0.f;
    const int ug = u0 + eul;
    const int rr = ug & 15;
    const int pbase = (ug >> 4) * 16 + ((rr < 8) ? (rr >> 2) : ((rr - 8) >> 2) + 2);

    const float* hA = h_s + (wm * 32 + g4) * SST_ + tg * 4;
    const float* wB0 = w_s + (wn * 16 + g4) * SST_ + tg * 4;
    const float* wB1 = wB0 + 8 * SST_;
    const float* vB0 = w2_s + (wn * 16 + g4) * SST_ + tg * 4;
    const float* vB1 = vB0 + 8 * SST_;
    const int rowM = gb0 + wm * 32 + g4;
    const uint32_t h_s_u32 = (uint32_t)__cvta_generic_to_shared(h_s);

    const int TEND = role ? T_ : T_ + 1;

    for (int t = 0; t < TEND; ++t) {
        const bool tail = (!role && t == T_);

        // L1: prefetch xg1(t) before the barrier (hides DRAM latency)
        float4 q0, q1, q2, q3;
        if (!role && !tail) {
            const float* xr = xgsrc + ((size_t)t * B_ + gb0 + eb) * G_ + u0 + eul;
            q0 = *(const float4*)(xr);
            q1 = *(const float4*)(xr + H_);
            q2 = *(const float4*)(xr + 2 * H_);
            q3 = *(const float4*)(xr + 3 * H_);
        }

        // group barrier (+ L2: wait for xg2(t) from its L1 partner)
        if (t > 0) {
            __syncthreads();
            if (tid == 0) {
                __threadfence();
                unsigned gen = *(volatile unsigned*)&g_gen2[barid];
                if (atomicAdd(&g_cnt2[barid], 1u) == 24u) {
                    atomicExch(&g_cnt2[barid], 0u);
                    __threadfence();
                    atomicAdd(&g_gen2[barid], 1u);
                } else {
                    while (*(volatile unsigned*)&g_gen2[barid] == gen) { }
                }
                if (role) {
                    while (*(volatile unsigned*)flag < (unsigned)(t + 1)) { }
                }
                __threadfence();
            }
            __syncthreads();
        } else if (role) {
            if (tid == 0) {
                while (*(volatile unsigned*)flag < 1u) { }
                __threadfence();
            }
            __syncthreads();
        }

        // L2: load xg2(t) now (after the wait)
        if (role) {
            const float* xr = xgsrc + ((size_t)t * B_ + gb0 + eb) * G_ + u0 + eul;
            q0 = *(const float4*)(xr);
            q1 = *(const float4*)(xr + H_);
            q2 = *(const float4*)(xr + 2 * H_);
            q3 = *(const float4*)(xr + 3 * H_);
        }

        // stage h(t-1): 128 packed rows
        if (t == 0) {
            float4 z = make_float4(0.f, 0.f, 0.f, 0.f);
            for (int lin = tid; lin < 6784; lin += 256)
                ((float4*)h_s)[lin] = z;
        } else {
            const float4* src = (const float4*)(hsout + ((size_t)(t - 1) * B_ + gb0) * HPK_);
#pragma unroll
            for (int i = 0; i < 26; ++i) {
                int lin = tid + 256 * i;               // 128*52 = 6656
                int row = lin / 52, rem = lin - row * 52;
                cpasync16(h_s_u32 + (row * SST_ + rem * 4) * 4, src + row * 52 + rem);
            }
            asm volatile("cp.async.commit_group;\ncp.async.wait_group 0;" ::: "memory");
        }
        __syncthreads();

        // MMA: M=128 x N=32 x K=200, single tf32
        float acc[2][2][4] = {};
        float xac[2][2][4] = {};
#pragma unroll
        for (int kb2 = 0; kb2 < 13; ++kb2) {
            float4 A0 = *(const float4*)(hA + kb2 * 16);
            float4 A1 = *(const float4*)(hA + kb2 * 16 + 8 * SST_);
            float4 A2 = *(const float4*)(hA + kb2 * 16 + 16 * SST_);
            float4 A3 = *(const float4*)(hA + kb2 * 16 + 24 * SST_);
            uint32_t aE0[4] = {fu(A0.x), fu(A1.x), fu(A0.y), fu(A1.y)};
            uint32_t aO0[4] = {fu(A0.z), fu(A1.z), fu(A0.w), fu(A1.w)};
            uint32_t aE1[4] = {fu(A2.x), fu(A3.x), fu(A2.y), fu(A3.y)};
            uint32_t aO1[4] = {fu(A2.z), fu(A3.z), fu(A2.w), fu(A3.w)};
            if (!tail) {
                float4 B0 = *(const float4*)(wB0 + kb2 * 16);
                float4 B1 = *(const float4*)(wB1 + kb2 * 16);
                uint32_t b0E[2] = {fu(B0.x), fu(B0.y)};
                uint32_t b0O[2] = {fu(B0.z), fu(B0.w)};
                uint32_t b1E[2] = {fu(B1.x), fu(B1.y)};
                uint32_t b1O[2] = {fu(B1.z), fu(B1.w)};
                mma_tf32(acc[0][0], aE0, b0E); mma_tf32(acc[0][0], aO0, b0O);
                mma_tf32(acc[1][0], aE1, b0E); mma_tf32(acc[1][0], aO1, b0O);
                mma_tf32(acc[0][1], aE0, b1E); mma_tf32(acc[0][1], aO0, b1O);
                mma_tf32(acc[1][1], aE1, b1E); mma_tf32(acc[1][1], aO1, b1O);
            }
            if (!role && t > 0) {
                float4 V0 = *(const float4*)(vB0 + kb2 * 16);
                float4 V1 = *(const float4*)(vB1 + kb2 * 16);
                uint32_t c0E[2] = {fu(V0.x), fu(V0.y)};
                uint32_t c0O[2] = {fu(V0.z), fu(V0.w)};
                uint32_t c1E[2] = {fu(V1.x), fu(V1.y)};
                uint32_t c1O[2] = {fu(V1.z), fu(V1.w)};
                mma_tf32(xac[0][0], aE0, c0E); mma_tf32(xac[0][0], aO0, c0O);
                mma_tf32(xac[1][0], aE1, c0E); mma_tf32(xac[1][0], aO1, c0O);
                mma_tf32(xac[0][1], aE0, c1E); mma_tf32(xac[0][1], aO0, c1O);
                mma_tf32(xac[1][1], aE1, c1E); mma_tf32(xac[1][1], aO1, c1O);
            }
        }

        // L1: write xg2(t-1) with L2 biases folded
        if (!role && t > 0) {
#pragma unroll
            for (int mf = 0; mf < 2; ++mf) {
                float* xo = xg2 + ((size_t)(t - 1) * B_ + rowM + mf * 16) * G_;
                __stcg((float2*)(xo + nc0),          make_float2(xac[mf][0][0] + bf00, xac[mf][0][1] + bf01));
                __stcg((float2*)(xo + nc1),          make_float2(xac[mf][1][0] + bf10, xac[mf][1][1] + bf11));
                __stcg((float2*)(xo + 8 * G_ + nc0), make_float2(xac[mf][0][2] + bf00, xac[mf][0][3] + bf01));
                __stcg((float2*)(xo + 8 * G_ + nc1), make_float2(xac[mf][1][2] + bf10, xac[mf][1][3] + bf11));
            }
        }
        if (tail) {
            __syncthreads();
            if (tid == 0) {
                __threadfence();
                *(volatile unsigned*)flag = (unsigned)t;   // = 600
            }
            break;
        }

        // accumulators -> g_s (stride 40)
#pragma unroll
        for (int mf = 0; mf < 2; ++mf) {
            float* d0 = g_s + (wm * 32 + mf * 16 + g4) * 40 + wn * 16 + tg * 2;
            *(float2*)(d0)              = make_float2(acc[mf][0][0], acc[mf][0][1]);
            *(float2*)(d0 + 8)          = make_float2(acc[mf][1][0], acc[mf][1][1]);
            *(float2*)(d0 + 8 * 40)     = make_float2(acc[mf][0][2], acc[mf][0][3]);
            *(float2*)(d0 + 8 * 40 + 8) = make_float2(acc[mf][1][2], acc[mf][1][3]);
        }
        __syncthreads();
        if (!role && t > 0 && tid == 0) {
            __threadfence();
            *(volatile unsigned*)flag = (unsigned)t;       // xg2(0..t-1) published
        }

        // gates + cell update: 1 batch x 4 units per thread
        {
            const float* gr = g_s + eb * 40 + eul;
            float iv, fv, gv, ov, h0, h1, h2, h3;
            iv = sigmf(gr[0] + q0.x);  fv = sigmf(gr[8] + q1.x);
            gv = tanh_fast(gr[16] + q2.x); ov = sigmf(gr[24] + q3.x);
            cc0 = fv * cc0 + iv * gv;  h0 = ov * tanh_fast(cc0);

            iv = sigmf(gr[1] + q0.y);  fv = sigmf(gr[9] + q1.y);
            gv = tanh_fast(gr[17] + q2.y); ov = sigmf(gr[25] + q3.y);
            cc1 = fv * cc1 + iv * gv;  h1 = ov * tanh_fast(cc1);

            iv = sigmf(gr[2] + q0.z);  fv = sigmf(gr[10] + q1.z);
            gv = tanh_fast(gr[18] + q2.z); ov = sigmf(gr[26] + q3.z);
            cc2 = fv * cc2 + iv * gv;  h2 = ov * tanh_fast(cc2);

            iv = sigmf(gr[3] + q0.w);  fv = sigmf(gr[11] + q1.w);
            gv = tanh_fast(gr[19] + q2.w); ov = sigmf(gr[27] + q3.w);
            cc3 = fv * cc3 + iv * gv;  h3 = ov * tanh_fast(cc3);

            float* hb = hsout + ((size_t)t * B_ + gb0 + eb) * HPK_;
            __stcg(hb + pbase,      tfhi(h0));
            __stcg(hb + pbase + 4,  tfhi(h1));
            __stcg(hb + pbase + 8,  tfhi(h2));
            __stcg(hb + pbase + 12, tfhi(h3));
            if (role) {
                float* hl = h2l + ((size_t)t * B_ + gb0 + eb) * H_ + u0 + eul;
                *(float4*)hl = make_float4(h0, h1, h2, h3);
            }
        }
    }

    // consumer resets the flag it used -> graph-replay safe
    if (role) {
        __syncthreads();
        if (tid == 0) *(volatile unsigned*)flag = 0u;
    }
}

// ---------------- launch --------------------------------------------------------
extern "C" void kernel_launch(void* const* d_in, const int* in_sizes, int n_in,
                              void* d_out, int out_size)
{
    const float* x     = (const float*)d_in[0];
    const float* w_ih1 = (const float*)d_in[1];
    const float* w_hh1 = (const float*)d_in[2];
    const float* b_ih1 = (const float*)d_in[3];
    const float* b_hh1 = (const float*)d_in[4];
    const float* w_ih2 = (const float*)d_in[5];
    const float* w_hh2 = (const float*)d_in[6];
    const float* b_ih2 = (const float*)d_in[7];
    const float* b_hh2 = (const float*)d_in[8];
    const float* fc1_w = (const float*)d_in[9];
    const float* fc1_b = (const float*)d_in[10];
    const float* fc2_w = (const float*)d_in[11];
    const float* fc2_b = (const float*)d_in[12];
    float* out = (float*)d_out;

    float *xg, *xg2, *hs1, *hs2, *h2l, *tmp, *wp1, *wp2;
    cudaGetSymbolAddress((void**)&xg,  g_xg);
    cudaGetSymbolAddress((void**)&xg2, g_xg2);
    cudaGetSymbolAddress((void**)&hs1, g_hs1);
    cudaGetSymbolAddress((void**)&hs2, g_hs2);
    cudaGetSymbolAddress((void**)&h2l, g_h2l);
    cudaGetSymbolAddress((void**)&tmp, g_tmp);
    cudaGetSymbolAddress((void**)&wp1, g_wp1);
    cudaGetSymbolAddress((void**)&wp2, g_wp2);

    const int WAVE_SMEM = (192 * SST_ + 128 * 40) * (int)sizeof(float); // 183296
    cudaFuncSetAttribute(lstm_wave, cudaFuncAttributeMaxDynamicSharedMemorySize, WAVE_SMEM);

    const int GEMM_SMEM = 2 * TB2 * (int)sizeof(float);                 // 73728
    cudaFuncSetAttribute((const void*)gemm_tc<0>, cudaFuncAttributeMaxDynamicSharedMemorySize, GEMM_SMEM);
    cudaFuncSetAttribute((const void*)gemm_tc<1>, cudaFuncAttributeMaxDynamicSharedMemorySize, GEMM_SMEM);
    cudaFuncSetAttribute((const void*)gemm_tc<2>, cudaFuncAttributeMaxDynamicSharedMemorySize, GEMM_SMEM);

    const int MROWS = B_ * T_;
    const dim3 grows(13, MROWS / 128);
    const dim3 frows(3,  MROWS / 128);

    // 0. pad odd-K weights
    pad_w<<<(G_ * KP_ + 255) / 256, 256>>>(w_ih1, wp1, G_, I_);
    pad_w<<<(I_ * KP_ + 255) / 256, 256>>>(fc2_w, wp2, I_, I_);
    // 1. x -> [T*B, 160] zero-padded
    transpose_x<<<dim3((T_ + 31) / 32, KP_ / 32, B_), dim3(32, 8)>>>(x, tmp);
    // 2. xg1 = xt @ wp1^T + b_ih1 + b_hh1
    gemm_tc<0><<<grows, 256, GEMM_SMEM>>>(tmp, KP_, wp1, KP_, b_ih1, b_hh1, xg, KP_, G_, G_);
    // 3. wavefront: L1 scan (fused xg2 with L2 biases) + L2 scan, overlapped
    lstm_wave<<<100, 256, WAVE_SMEM>>>(xg, w_hh1, w_ih2, w_hh2, b_ih2, b_hh2,
                                       hs1, hs2, h2l, xg2);
    // 4. y1 = relu(h2 @ fc1_w^T + fc1_b) -> tmp[., 160]
    gemm_tc<1><<<frows, 256, GEMM_SMEM>>>(h2l, H_, fc1_w, H_, fc1_b, nullptr, tmp, H_, I_, KP_);
    // 5. out = sigmoid(y1 @ wp2^T + fc2_b), transposed store to [B,129,T]
    gemm_tc<2><<<frows, 256, GEMM_SMEM>>>(tmp, KP_, wp2, KP_, fc2_b, nullptr, out, KP_, I_, 0);
}

// round 10
// speedup vs baseline: 2.2776x; 1.3794x over previous
#include <cuda_runtime.h>
#include <cstdint>
#include <cstdio>

#define B_   256
#define T_   600
#define I_   129
#define H_   200
#define G_   800   // 4*H
#define KP_  160   // padded K for the I=129 operands
#define HPW_ 104   // packed bf16 h row: 13 kb2-groups * 8 uint32 words

// ---------------- scratch (device globals; no cudaMalloc allowed) ----------------
__device__ float    g_xg [(size_t)T_ * B_ * G_];     // xg1 (with biases)
__device__ float    g_xg2[(size_t)T_ * B_ * G_];     // xg2 (with biases, from L1)
__device__ unsigned g_hs1[(size_t)T_ * B_ * HPW_];   // packed bf16 h, layer 1
__device__ unsigned g_hs2[(size_t)T_ * B_ * HPW_];   // packed bf16 h, layer 2
__device__ float    g_h2l[(size_t)T_ * B_ * H_];     // linear fp32 h2 (for fc1)
__device__ float    g_tmp[(size_t)T_ * B_ * KP_];    // xt, later y1 (stride 160)
__device__ float    g_wp1[G_ * KP_];
__device__ float    g_wp2[I_ * KP_];

// barriers: 4 groups (L1 g0,g1; L2 g0,g1), 25 blocks each
__device__ unsigned g_cnt2[4] = {0, 0, 0, 0};
__device__ unsigned g_gen2[4] = {0, 0, 0, 0};
// L1 -> L2 progress flags (completed L1 step; reset by consumer at end)
__device__ unsigned g_l1prog[2][25];

// ---------------- fast activations ----------------
__device__ __forceinline__ float sigmf(float x) {
    return __fdividef(1.f, 1.f + __expf(-x));
}
__device__ __forceinline__ float tanh_fast(float x) {
    float e = __expf(2.f * x);
    return 1.f - __fdividef(2.f, e + 1.f);
}

// ---------------- tf32 / bf16 helpers ----------------
__device__ __forceinline__ uint32_t f2tf32(float x) {
    uint32_t r;
    asm("cvt.rna.tf32.f32 %0, %1;" : "=r"(r) : "f"(x));
    return r;
}
__device__ __forceinline__ float tfhi(float v) { return __uint_as_float(f2tf32(v)); }
__device__ __forceinline__ uint32_t fu(float v) { return __float_as_uint(v); }

// bf16x2 with element0 = a (lower half), element1 = b
__device__ __forceinline__ uint32_t bf2(float a, float b) {
    uint32_t r;
    asm("cvt.rn.bf16x2.f32 %0, %1, %2;" : "=r"(r) : "f"(b), "f"(a));
    return r;
}

__device__ __forceinline__ void mma_tf32(float* d, const uint32_t* a, const uint32_t* b) {
    asm volatile(
        "mma.sync.aligned.m16n8k8.row.col.f32.tf32.tf32.f32 "
        "{%0,%1,%2,%3}, {%4,%5,%6,%7}, {%8,%9}, {%0,%1,%2,%3};"
        : "+f"(d[0]), "+f"(d[1]), "+f"(d[2]), "+f"(d[3])
        : "r"(a[0]), "r"(a[1]), "r"(a[2]), "r"(a[3]), "r"(b[0]), "r"(b[1]));
}
__device__ __forceinline__ void mma_bf16(float* d, const uint32_t* a, const uint32_t* b) {
    asm volatile(
        "mma.sync.aligned.m16n8k16.row.col.f32.bf16.bf16.f32 "
        "{%0,%1,%2,%3}, {%4,%5,%6,%7}, {%8,%9}, {%0,%1,%2,%3};"
        : "+f"(d[0]), "+f"(d[1]), "+f"(d[2]), "+f"(d[3])
        : "r"(a[0]), "r"(a[1]), "r"(a[2]), "r"(a[3]), "r"(b[0]), "r"(b[1]));
}

__device__ __forceinline__ void cpasync16(uint32_t dst, const void* src) {
    asm volatile("cp.async.cg.shared.global [%0], [%1], 16;" :: "r"(dst), "l"(src));
}

// interleaved 8-k split for the 3xTF32 GEMMs
__device__ __forceinline__ void split8(float4 p0, float4 p1, float4 q[4])
{
    float h0 = tfhi(p0.x), h1 = tfhi(p0.y), h2 = tfhi(p0.z), h3 = tfhi(p0.w);
    float g0 = tfhi(p1.x), g1 = tfhi(p1.y), g2 = tfhi(p1.z), g3 = tfhi(p1.w);
    q[0] = make_float4(h0, g0, tfhi(p0.x - h0), tfhi(p1.x - g0));
    q[1] = make_float4(h1, g1, tfhi(p0.y - h1), tfhi(p1.y - g1));
    q[2] = make_float4(h2, g2, tfhi(p0.z - h2), tfhi(p1.z - g2));
    q[3] = make_float4(h3, g3, tfhi(p0.w - h3), tfhi(p1.w - g3));
}

// ---------------- weight padding ----------------
__global__ void pad_w(const float* __restrict__ w, float* __restrict__ wp, int N, int K)
{
    int i = blockIdx.x * 256 + threadIdx.x;
    if (i < N * KP_) {
        int n = i / KP_, k = i - n * KP_;
        wp[i] = (k < K) ? w[(size_t)n * K + k] : 0.f;
    }
}

// ---------------- transpose x [B,I,T] -> xt [(t*B+b), 160] ----------------
__global__ void transpose_x(const float* __restrict__ x, float* __restrict__ xt)
{
    __shared__ float sm[32][33];
    const int b  = blockIdx.z;
    const int i0 = blockIdx.y * 32;
    const int t0 = blockIdx.x * 32;
    const int tx = threadIdx.x, ty = threadIdx.y;
#pragma unroll
    for (int s = 0; s < 32; s += 8) {
        int i = i0 + ty + s, t = t0 + tx;
        sm[ty + s][tx] = (i < I_ && t < T_) ? x[((size_t)b * I_ + i) * T_ + t] : 0.f;
    }
    __syncthreads();
#pragma unroll
    for (int s = 0; s < 32; s += 8) {
        int t = t0 + ty + s, i = i0 + tx;
        if (t < T_ && i < KP_)
            xt[((size_t)t * B_ + b) * KP_ + i] = sm[tx][ty + s];
    }
}

// ---------------- GEMM (3xTF32, ktile 16, double-buffered, 2 CTA/SM) -------------
#define TB2 9216

__device__ __forceinline__ void ld_regs(
    const float* __restrict__ A, int ldA,
    const float* __restrict__ W, int ldW,
    int m0, int n0, int N, int K, int kt, int tid,
    float4 ra[2], float4 rw[2])
{
    const float4 z = make_float4(0.f, 0.f, 0.f, 0.f);
    const int row = tid >> 1, kbl = tid & 1;
    int k = kt * 16 + kbl * 8;
    if (k + 8 <= K) {
        const float* p = A + (size_t)(m0 + row) * ldA + k;
        ra[0] = *(const float4*)p;
        ra[1] = *(const float4*)(p + 4);
    } else { ra[0] = z; ra[1] = z; }
    if (tid < 128) {
        int wr = tid >> 1;
        if (k + 8 <= K && n0 + wr < N) {
            const float* p = W + (size_t)(n0 + wr) * ldW + k;
            rw[0] = *(const float4*)p;
            rw[1] = *(const float4*)(p + 4);
        } else { rw[0] = z; rw[1] = z; }
    }
}

__device__ __forceinline__ void st_smem(float* buf, int tid, float4 ra[2], float4 rw[2])
{
    const int row = tid >> 1, kbl = tid & 1;
    {
        float4 q[4];
        split8(ra[0], ra[1], q);
        float4* da = (float4*)(buf + row * 48 + kbl * 16);
        int rot = row & 3;
#pragma unroll
        for (int j = 0; j < 4; ++j) { int jj = (rot + j) & 3; da[jj] = q[jj]; }
    }
    if (tid < 128) {
        int wr = tid >> 1;
        float4 q[4];
        split8(rw[0], rw[1], q);
        float4* dw = (float4*)(buf + 6144 + wr * 48 + kbl * 16);
        int rot = wr & 3;
#pragma unroll
        for (int j = 0; j < 4; ++j) { int jj = (rot + j) & 3; dw[jj] = q[jj]; }
    }
}

__device__ __forceinline__ void mma_tile16(const float* buf, int wm, int wn,
                                           int g4, int tg, float acc[2][4][4])
{
    const float* Sw = buf + 6144;
#pragma unroll
    for (int kk = 0; kk < 2; ++kk) {
        int koff = kk * 16 + tg * 4;
        uint32_t ah[2][4], al[2][4];
#pragma unroll
        for (int mf = 0; mf < 2; ++mf) {
            const float* pa = buf + (wm * 32 + mf * 16 + g4) * 48 + koff;
            float4 A0 = *(const float4*)pa;
            float4 A1 = *(const float4*)(pa + 8 * 48);
            ah[mf][0] = fu(A0.x); ah[mf][1] = fu(A1.x);
            ah[mf][2] = fu(A0.y); ah[mf][3] = fu(A1.y);
            al[mf][0] = fu(A0.z); al[mf][1] = fu(A1.z);
            al[mf][2] = fu(A0.w); al[mf][3] = fu(A1.w);
        }
#pragma unroll
        for (int nf = 0; nf < 4; ++nf) {
            const float* pb = Sw + (wn * 32 + nf * 8 + g4) * 48 + koff;
            float4 Bv = *(const float4*)pb;
            uint32_t bh[2] = {fu(Bv.x), fu(Bv.y)};
            uint32_t bl[2] = {fu(Bv.z), fu(Bv.w)};
            mma_tf32(acc[0][nf], ah[0], bh);
            mma_tf32(acc[0][nf], ah[0], bl);
            mma_tf32(acc[0][nf], al[0], bh);
            mma_tf32(acc[1][nf], ah[1], bh);
            mma_tf32(acc[1][nf], ah[1], bl);
            mma_tf32(acc[1][nf], al[1], bh);
        }
    }
}

template <int MODE>
__global__ void __launch_bounds__(256, 2) gemm_tc(
    const float* __restrict__ A, int ldA,
    const float* __restrict__ W, int ldW,
    const float* __restrict__ bias, const float* __restrict__ bias2,
    float* __restrict__ out, int K, int N, int ldOut)
{
    extern __shared__ float sm[];
    const int tid  = threadIdx.x;
    const int warp = tid >> 5, lane = tid & 31;
    const int wm = warp >> 1, wn = warp & 1;
    const int g4 = lane >> 2, tg = lane & 3;
    const int m0 = blockIdx.y * 128;
    const int n0 = blockIdx.x * 64;

    float acc[2][4][4] = {};
    float4 ra[2], rw[2];

    const int ktiles = (K + 15) >> 4;

    ld_regs(A, ldA, W, ldW, m0, n0, N, K, 0, tid, ra, rw);
    st_smem(sm, tid, ra, rw);
    __syncthreads();

    for (int kt = 0; kt < ktiles; ++kt) {
        if (kt + 1 < ktiles)
            ld_regs(A, ldA, W, ldW, m0, n0, N, K, kt + 1, tid, ra, rw);
        mma_tile16(sm + (kt & 1) * TB2, wm, wn, g4, tg, acc);
        if (kt + 1 < ktiles)
            st_smem(sm + ((kt + 1) & 1) * TB2, tid, ra, rw);
        __syncthreads();
    }

#pragma unroll
    for (int mf = 0; mf < 2; ++mf) {
        int m_a = m0 + wm * 32 + mf * 16 + g4;
#pragma unroll
        for (int nf = 0; nf < 4; ++nf) {
            int n = n0 + wn * 32 + nf * 8 + tg * 2;
#pragma unroll
            for (int half = 0; half < 2; ++half) {
                int m = m_a + half * 8;
                float v0 = acc[mf][nf][half * 2 + 0];
                float v1 = acc[mf][nf][half * 2 + 1];
                if (MODE == 0) {
                    if (n < N) {
                        float2 o;
                        o.x = v0 + bias[n] + bias2[n];
                        o.y = v1 + bias[n + 1] + bias2[n + 1];
                        *(float2*)(out + (size_t)m * ldOut + n) = o;
                    }
                } else if (MODE == 1) {
                    if (n < KP_) {
                        float2 o;
                        o.x = (n     < N) ? fmaxf(v0 + bias[n], 0.f)     : 0.f;
                        o.y = (n + 1 < N) ? fmaxf(v1 + bias[n + 1], 0.f) : 0.f;
                        *(float2*)(out + (size_t)m * ldOut + n) = o;
                    }
                } else {
                    int tt = m >> 8, b = m & 255;
                    if (n < N)
                        out[((size_t)b * I_ + n) * T_ + tt] = sigmf(v0 + bias[n]);
                    if (n + 1 < N)
                        out[((size_t)b * I_ + n + 1) * T_ + tt] = sigmf(v1 + bias[n + 1]);
                }
            }
        }
    }
}

// ---------------- wavefront LSTM (bf16 m16n8k16 recurrence) ---------------------
// 100 blocks: blockIdx < 50 -> layer 1, else layer 2 (runs behind via flags).
// Per layer: 2 batch groups x 128 batches, 25 unit-blocks (8 units = 32 gate cols).
// h/w packed bf16x2 word layout per 16-k group: [k0k1, k8k9, k2k3, k10k11,
// k4k5, k12k13, k6k7, k14k15] -> each MMA fragment is ONE contiguous LDS.64.
// Row stride = 104 words (416B = 32 mod 128B -> conflict-free per half-warp).
__global__ void __launch_bounds__(256, 1) lstm_wave(
    const float* __restrict__ xg1, const float* __restrict__ whh1,
    const float* __restrict__ wih2, const float* __restrict__ whh2,
    const float* __restrict__ bi2,  const float* __restrict__ bh2,
    unsigned* __restrict__ hs1, unsigned* __restrict__ hs2,
    float* __restrict__ h2l, float* __restrict__ xg2)
{
    extern __shared__ uint32_t smu[];
    uint32_t* w_su  = smu;                 // 32 cols * 104 words
    uint32_t* w2_su = smu + 3328;          // 32 cols * 104 (L1 only)
    uint32_t* h_su  = smu + 6656;          // 128 rows * 104
    float*    g_s   = (float*)(smu + 19968); // 128 * 40

    const int tid  = threadIdx.x;
    const int warp = tid >> 5, lane = tid & 31;
    const int g4 = lane >> 2, tg = lane & 3;
    const int wm = warp >> 1;              // 0..3 -> rows wm*32..+31
    const int wn = warp & 1;               // 0..1 -> cols wn*16..+15

    const int role = (blockIdx.x >= 50);
    const int bid  = blockIdx.x - role * 50;
    const int grp  = bid / 25;
    const int ublk = bid - grp * 25;
    const int gb0  = grp * 128;
    const int u0   = ublk * 8;
    const int barid = role * 2 + grp;

    const float* xgsrc = role ? xg2 : xg1;
    const float* whh   = role ? whh2 : whh1;
    unsigned* hsout = role ? hs2 : hs1;
    unsigned* flag = &g_l1prog[grp][ublk];

    // ---- stage weight slices: col c = gate*8+ul, packed bf16 (zero k>=200) ----
    for (int i = 0; i < 13; ++i) {
        int lin = tid + 256 * i;                      // 32 * 104 = 3328 words
        if (lin < 3328) {
            int c = lin / 104, rem = lin - c * 104;
            int kb2 = rem >> 3, w = rem & 7;
            int kl = (w & 1) ? (w + 7) : w;           // pair-interleaved layout
            int k0 = kb2 * 16 + kl;
            int grow = (c >> 3) * H_ + u0 + (c & 7);
            const float* wr_ = whh + (size_t)grow * H_;
            float v0 = (k0     < H_) ? wr_[k0]     : 0.f;
            float v1 = (k0 + 1 < H_) ? wr_[k0 + 1] : 0.f;
            w_su[c * 104 + kb2 * 8 + w] = bf2(v0, v1);
            if (!role) {
                const float* w2r = wih2 + (size_t)grow * H_;
                float u0v = (k0     < H_) ? w2r[k0]     : 0.f;
                float u1v = (k0 + 1 < H_) ? w2r[k0 + 1] : 0.f;
                w2_su[c * 104 + kb2 * 8 + w] = bf2(u0v, u1v);
            }
        }
    }

    // L2 bias fold for xg2 writes (L1 role only)
    const int nc0 = (wn * 2 + 0) * H_ + u0 + tg * 2;
    const int nc1 = (wn * 2 + 1) * H_ + u0 + tg * 2;
    float bf00 = 0.f, bf01 = 0.f, bf10 = 0.f, bf11 = 0.f;
    if (!role) {
        bf00 = bi2[nc0] + bh2[nc0];     bf01 = bi2[nc0 + 1] + bh2[nc0 + 1];
        bf10 = bi2[nc1] + bh2[nc1];     bf11 = bi2[nc1 + 1] + bh2[nc1 + 1];
    }

    // epilogue ownership: 1 batch x 4 units per thread
    const int eb  = tid >> 1;              // 0..127
    const int eul = (tid & 1) * 4;         // 0 or 4
    float cc0 = 0.f, cc1 = 0.f, cc2 = 0.f, cc3 = 0.f;
    const int ug = u0 + eul;
    const int jg = ug >> 4;                // 16-k group
    const int rr = ug & 15;                // 0,4,8,12
    const int p0 = rr >> 1;                // 0,2,4,6
    const int wo0 = (p0     < 4) ? 2 * p0       : 2 * (p0 - 4) + 1;
    const int wo1 = (p0 + 1 < 4) ? 2 * (p0 + 1) : 2 * (p0 - 3) + 1;

    const uint32_t* hA  = h_su + (wm * 32 + g4) * 104 + tg * 2;
    const uint32_t* wB0 = w_su + (wn * 16 + g4) * 104 + tg * 2;
    const uint32_t* wB1 = wB0 + 8 * 104;
    const uint32_t* vB0 = w2_su + (wn * 16 + g4) * 104 + tg * 2;
    const uint32_t* vB1 = vB0 + 8 * 104;
    const int rowM = gb0 + wm * 32 + g4;
    const uint32_t h_su32 = (uint32_t)__cvta_generic_to_shared(h_su);

    const int TEND = role ? T_ : T_ + 1;

    for (int t = 0; t < TEND; ++t) {
        const bool tail = (!role && t == T_);

        // L1: prefetch xg1(t) before the barrier
        float4 q0, q1, q2, q3;
        if (!role && !tail) {
            const float* xr = xgsrc + ((size_t)t * B_ + gb0 + eb) * G_ + u0 + eul;
            q0 = *(const float4*)(xr);
            q1 = *(const float4*)(xr + H_);
            q2 = *(const float4*)(xr + 2 * H_);
            q3 = *(const float4*)(xr + 3 * H_);
        }

        // group barrier (+ L2: wait for xg2(t))
        if (t > 0) {
            __syncthreads();
            if (tid == 0) {
                __threadfence();
                unsigned gen = *(volatile unsigned*)&g_gen2[barid];
                if (atomicAdd(&g_cnt2[barid], 1u) == 24u) {
                    atomicExch(&g_cnt2[barid], 0u);
                    __threadfence();
                    atomicAdd(&g_gen2[barid], 1u);
                } else {
                    while (*(volatile unsigned*)&g_gen2[barid] == gen) { }
                }
                if (role) {
                    while (*(volatile unsigned*)flag < (unsigned)(t + 1)) { }
                }
                __threadfence();
            }
            __syncthreads();
        } else if (role) {
            if (tid == 0) {
                while (*(volatile unsigned*)flag < 1u) { }
                __threadfence();
            }
            __syncthreads();
        }

        // L2: load xg2(t) after the wait
        if (role) {
            const float* xr = xgsrc + ((size_t)t * B_ + gb0 + eb) * G_ + u0 + eul;
            q0 = *(const float4*)(xr);
            q1 = *(const float4*)(xr + H_);
            q2 = *(const float4*)(xr + 2 * H_);
            q3 = *(const float4*)(xr + 3 * H_);
        }

        // stage h(t-1): 128 packed bf16 rows (26 x 16B each)
        if (t == 0) {
            uint4 z = make_uint4(0u, 0u, 0u, 0u);
            for (int lin = tid; lin < 3328; lin += 256)
                ((uint4*)h_su)[lin] = z;
        } else {
            const uint4* src = (const uint4*)(hsout + ((size_t)(t - 1) * B_ + gb0) * HPW_);
#pragma unroll
            for (int i = 0; i < 13; ++i) {
                int lin = tid + 256 * i;               // 128*26 = 3328
                int row = lin / 26, rem = lin - row * 26;
                cpasync16(h_su32 + (row * 104 + rem * 4) * 4, src + row * 26 + rem);
            }
            asm volatile("cp.async.commit_group;\ncp.async.wait_group 0;" ::: "memory");
        }
        __syncthreads();

        // MMA: M=128 x N=32 x K=208(eff 200), bf16 m16n8k16
        float acc[2][2][4] = {};
        float xac[2][2][4] = {};
#pragma unroll
        for (int kb2 = 0; kb2 < 13; ++kb2) {
            uint2 r0 = *(const uint2*)(hA + kb2 * 8);
            uint2 r1 = *(const uint2*)(hA + kb2 * 8 + 8 * 104);
            uint2 r2 = *(const uint2*)(hA + kb2 * 8 + 16 * 104);
            uint2 r3 = *(const uint2*)(hA + kb2 * 8 + 24 * 104);
            uint32_t a0[4] = {r0.x, r1.x, r0.y, r1.y};   // rows wm*32+g4, +8
            uint32_t a1[4] = {r2.x, r3.x, r2.y, r3.y};   // rows +16, +24
            if (!tail) {
                uint2 bb0 = *(const uint2*)(wB0 + kb2 * 8);
                uint2 bb1 = *(const uint2*)(wB1 + kb2 * 8);
                uint32_t b0[2] = {bb0.x, bb0.y};
                uint32_t b1[2] = {bb1.x, bb1.y};
                mma_bf16(acc[0][0], a0, b0);
                mma_bf16(acc[1][0], a1, b0);
                mma_bf16(acc[0][1], a0, b1);
                mma_bf16(acc[1][1], a1, b1);
            }
            if (!role && t > 0) {
                uint2 vv0 = *(const uint2*)(vB0 + kb2 * 8);
                uint2 vv1 = *(const uint2*)(vB1 + kb2 * 8);
                uint32_t v0[2] = {vv0.x, vv0.y};
                uint32_t v1[2] = {vv1.x, vv1.y};
                mma_bf16(xac[0][0], a0, v0);
                mma_bf16(xac[1][0], a1, v0);
                mma_bf16(xac[0][1], a0, v1);
                mma_bf16(xac[1][1], a1, v1);
            }
        }

        // L1: write xg2(t-1) with L2 biases folded
        if (!role && t > 0) {
#pragma unroll
            for (int mf = 0; mf < 2; ++mf) {
                float* xo = xg2 + ((size_t)(t - 1) * B_ + rowM + mf * 16) * G_;
                __stcg((float2*)(xo + nc0),          make_float2(xac[mf][0][0] + bf00, xac[mf][0][1] + bf01));
                __stcg((float2*)(xo + nc1),          make_float2(xac[mf][1][0] + bf10, xac[mf][1][1] + bf11));
                __stcg((float2*)(xo + 8 * G_ + nc0), make_float2(xac[mf][0][2] + bf00, xac[mf][0][3] + bf01));
                __stcg((float2*)(xo + 8 * G_ + nc1), make_float2(xac[mf][1][2] + bf10, xac[mf][1][3] + bf11));
            }
        }
        if (tail) {
            __syncthreads();
            if (tid == 0) {
                __threadfence();
                *(volatile unsigned*)flag = (unsigned)t;   // = 600
            }
            break;
        }

        // accumulators -> g_s (stride 40)
#pragma unroll
        for (int mf = 0; mf < 2; ++mf) {
            float* d0 = g_s + (wm * 32 + mf * 16 + g4) * 40 + wn * 16 + tg * 2;
            *(float2*)(d0)              = make_float2(acc[mf][0][0], acc[mf][0][1]);
            *(float2*)(d0 + 8)          = make_float2(acc[mf][1][0], acc[mf][1][1]);
            *(float2*)(d0 + 8 * 40)     = make_float2(acc[mf][0][2], acc[mf][0][3]);
            *(float2*)(d0 + 8 * 40 + 8) = make_float2(acc[mf][1][2], acc[mf][1][3]);
        }
        __syncthreads();
        if (!role && t > 0 && tid == 0) {
            __threadfence();
            *(volatile unsigned*)flag = (unsigned)t;       // xg2(0..t-1) published
        }

        // gates + cell update: 1 batch x 4 units per thread
        {
            const float* gr = g_s + eb * 40 + eul;
            float iv, fv, gv, ov, h0, h1, h2, h3;
            iv = sigmf(gr[0] + q0.x);  fv = sigmf(gr[8] + q1.x);
            gv = tanh_fast(gr[16] + q2.x); ov = sigmf(gr[24] + q3.x);
            cc0 = fv * cc0 + iv * gv;  h0 = ov * tanh_fast(cc0);

            iv = sigmf(gr[1] + q0.y);  fv = sigmf(gr[9] + q1.y);
            gv = tanh_fast(gr[17] + q2.y); ov = sigmf(gr[25] + q3.y);
            cc1 = fv * cc1 + iv * gv;  h1 = ov * tanh_fast(cc1);

            iv = sigmf(gr[2] + q0.z);  fv = sigmf(gr[10] + q1.z);
            gv = tanh_fast(gr[18] + q2.z); ov = sigmf(gr[26] + q3.z);
            cc2 = fv * cc2 + iv * gv;  h2 = ov * tanh_fast(cc2);

            iv = sigmf(gr[3] + q0.w);  fv = sigmf(gr[11] + q1.w);
            gv = tanh_fast(gr[19] + q2.w); ov = sigmf(gr[27] + q3.w);
            cc3 = fv * cc3 + iv * gv;  h3 = ov * tanh_fast(cc3);

            unsigned* hb = hsout + ((size_t)t * B_ + gb0 + eb) * HPW_ + jg * 8;
            __stcg(hb + wo0, bf2(h0, h1));
            __stcg(hb + wo1, bf2(h2, h3));
            if (role) {
                float* hl = h2l + ((size_t)t * B_ + gb0 + eb) * H_ + u0 + eul;
                *(float4*)hl = make_float4(h0, h1, h2, h3);
            }
        }
    }

    // consumer resets its flag -> graph-replay safe
    if (role) {
        __syncthreads();
        if (tid == 0) *(volatile unsigned*)flag = 0u;
    }
}

// ---------------- launch --------------------------------------------------------
extern "C" void kernel_launch(void* const* d_in, const int* in_sizes, int n_in,
                              void* d_out, int out_size)
{
    const float* x     = (const float*)d_in[0];
    const float* w_ih1 = (const float*)d_in[1];
    const float* w_hh1 = (const float*)d_in[2];
    const float* b_ih1 = (const float*)d_in[3];
    const float* b_hh1 = (const float*)d_in[4];
    const float* w_ih2 = (const float*)d_in[5];
    const float* w_hh2 = (const float*)d_in[6];
    const float* b_ih2 = (const float*)d_in[7];
    const float* b_hh2 = (const float*)d_in[8];
    const float* fc1_w = (const float*)d_in[9];
    const float* fc1_b = (const float*)d_in[10];
    const float* fc2_w = (const float*)d_in[11];
    const float* fc2_b = (const float*)d_in[12];
    float* out = (float*)d_out;

    float *xg, *xg2, *h2l, *tmp, *wp1, *wp2;
    unsigned *hs1, *hs2;
    cudaGetSymbolAddress((void**)&xg,  g_xg);
    cudaGetSymbolAddress((void**)&xg2, g_xg2);
    cudaGetSymbolAddress((void**)&hs1, g_hs1);
    cudaGetSymbolAddress((void**)&hs2, g_hs2);
    cudaGetSymbolAddress((void**)&h2l, g_h2l);
    cudaGetSymbolAddress((void**)&tmp, g_tmp);
    cudaGetSymbolAddress((void**)&wp1, g_wp1);
    cudaGetSymbolAddress((void**)&wp2, g_wp2);

    const int WAVE_SMEM = (19968 + 128 * 40) * 4;   // 100352 B
    cudaFuncSetAttribute(lstm_wave, cudaFuncAttributeMaxDynamicSharedMemorySize, WAVE_SMEM);

    const int GEMM_SMEM = 2 * TB2 * (int)sizeof(float);  // 73728
    cudaFuncSetAttribute((const void*)gemm_tc<0>, cudaFuncAttributeMaxDynamicSharedMemorySize, GEMM_SMEM);
    cudaFuncSetAttribute((const void*)gemm_tc<1>, cudaFuncAttributeMaxDynamicSharedMemorySize, GEMM_SMEM);
    cudaFuncSetAttribute((const void*)gemm_tc<2>, cudaFuncAttributeMaxDynamicSharedMemorySize, GEMM_SMEM);

    const int MROWS = B_ * T_;
    const dim3 grows(13, MROWS / 128);
    const dim3 frows(3,  MROWS / 128);

    // 0. pad odd-K weights
    pad_w<<<(G_ * KP_ + 255) / 256, 256>>>(w_ih1, wp1, G_, I_);
    pad_w<<<(I_ * KP_ + 255) / 256, 256>>>(fc2_w, wp2, I_, I_);
    // 1. x -> [T*B, 160] zero-padded
    transpose_x<<<dim3((T_ + 31) / 32, KP_ / 32, B_), dim3(32, 8)>>>(x, tmp);
    // 2. xg1 = xt @ wp1^T + b_ih1 + b_hh1   (3xTF32)
    gemm_tc<0><<<grows, 256, GEMM_SMEM>>>(tmp, KP_, wp1, KP_, b_ih1, b_hh1, xg, KP_, G_, G_);
    // 3. wavefront: L1 (bf16, fused xg2+L2 biases) + L2 (bf16), overlapped
    lstm_wave<<<100, 256, WAVE_SMEM>>>(xg, w_hh1, w_ih2, w_hh2, b_ih2, b_hh2,
                                       hs1, hs2, h2l, xg2);
    // 4. y1 = relu(h2 @ fc1_w^T + fc1_b) -> tmp[., 160]
    gemm_tc<1><<<frows, 256, GEMM_SMEM>>>(h2l, H_, fc1_w, H_, fc1_b, nullptr, tmp, H_, I_, KP_);
    // 5. out = sigmoid(y1 @ wp2^T + fc2_b), transposed store to [B,129,T]
    gemm_tc<2><<<frows, 256, GEMM_SMEM>>>(tmp, KP_, wp2, KP_, fc2_b, nullptr, out, KP_, I_, 0);
}

// round 11
// speedup vs baseline: 2.7084x; 1.1891x over previous
#include <cuda_runtime.h>
#include <cstdint>
#include <cstdio>

#define B_   256
#define T_   600
#define I_   129
#define H_   200
#define G_   800   // 4*H
#define KP_  160   // padded K for the I=129 operands
#define HPW_ 104   // packed bf16 h row: 13 kb2-groups * 8 uint32 words
#define XPW_ 80    // packed bf16 xt row: 10 kb2-groups * 8 words

// smem word offsets for the wave kernel
#define OFF_WHH  0        // 32*104
#define OFF_WIH2 3328     // 32*104
#define OFF_WIH1 6656     // 32*88 (stride 88, 80 used)
#define OFF_H    9472     // 128*104
#define OFF_XT   22784    // 128*88
#define OFF_GS   34048    // 128*40 floats
#define WAVE_WORDS 39168  // total words (156672 B)

// ---------------- scratch (device globals; no cudaMalloc allowed) ----------------
__device__ float    g_xg2[(size_t)T_ * B_ * G_];     // xg2 (with biases, from L1)
__device__ unsigned g_xtb[(size_t)T_ * B_ * XPW_];   // packed bf16 xt (49 MB)
__device__ unsigned g_hs1[(size_t)T_ * B_ * HPW_];   // packed bf16 h, layer 1
__device__ unsigned g_hs2[(size_t)T_ * B_ * HPW_];   // packed bf16 h, layer 2
__device__ float    g_h2l[(size_t)T_ * B_ * H_];     // linear fp32 h2 (for fc1)
__device__ float    g_tmp[(size_t)T_ * B_ * KP_];    // xt fp32, later y1 (stride 160)
__device__ float    g_wp2[I_ * KP_];                 // fc2_w padded to [129,160]

// barriers: 4 groups (L1 g0,g1; L2 g0,g1), 25 blocks each
__device__ unsigned g_cnt2[4] = {0, 0, 0, 0};
__device__ unsigned g_gen2[4] = {0, 0, 0, 0};
// L1 -> L2 progress flags (completed L1 step; reset by consumer at end)
__device__ unsigned g_l1prog[2][25];

// ---------------- fast activations ----------------
__device__ __forceinline__ float sigmf(float x) {
    return __fdividef(1.f, 1.f + __expf(-x));
}
__device__ __forceinline__ float tanh_fast(float x) {
    float e = __expf(2.f * x);
    return 1.f - __fdividef(2.f, e + 1.f);
}

// ---------------- tf32 / bf16 helpers ----------------
__device__ __forceinline__ uint32_t f2tf32(float x) {
    uint32_t r;
    asm("cvt.rna.tf32.f32 %0, %1;" : "=r"(r) : "f"(x));
    return r;
}
__device__ __forceinline__ float tfhi(float v) { return __uint_as_float(f2tf32(v)); }
__device__ __forceinline__ uint32_t fu(float v) { return __float_as_uint(v); }

// bf16x2 with element0 = a (lower half), element1 = b
__device__ __forceinline__ uint32_t bf2(float a, float b) {
    uint32_t r;
    asm("cvt.rn.bf16x2.f32 %0, %1, %2;" : "=r"(r) : "f"(b), "f"(a));
    return r;
}

__device__ __forceinline__ void mma_tf32(float* d, const uint32_t* a, const uint32_t* b) {
    asm volatile(
        "mma.sync.aligned.m16n8k8.row.col.f32.tf32.tf32.f32 "
        "{%0,%1,%2,%3}, {%4,%5,%6,%7}, {%8,%9}, {%0,%1,%2,%3};"
        : "+f"(d[0]), "+f"(d[1]), "+f"(d[2]), "+f"(d[3])
        : "r"(a[0]), "r"(a[1]), "r"(a[2]), "r"(a[3]), "r"(b[0]), "r"(b[1]));
}
__device__ __forceinline__ void mma_bf16(float* d, const uint32_t* a, const uint32_t* b) {
    asm volatile(
        "mma.sync.aligned.m16n8k16.row.col.f32.bf16.bf16.f32 "
        "{%0,%1,%2,%3}, {%4,%5,%6,%7}, {%8,%9}, {%0,%1,%2,%3};"
        : "+f"(d[0]), "+f"(d[1]), "+f"(d[2]), "+f"(d[3])
        : "r"(a[0]), "r"(a[1]), "r"(a[2]), "r"(a[3]), "r"(b[0]), "r"(b[1]));
}

__device__ __forceinline__ void cpasync16(uint32_t dst, const void* src) {
    asm volatile("cp.async.cg.shared.global [%0], [%1], 16;" :: "r"(dst), "l"(src));
}

// interleaved 8-k split for the 3xTF32 GEMMs
__device__ __forceinline__ void split8(float4 p0, float4 p1, float4 q[4])
{
    float h0 = tfhi(p0.x), h1 = tfhi(p0.y), h2 = tfhi(p0.z), h3 = tfhi(p0.w);
    float g0 = tfhi(p1.x), g1 = tfhi(p1.y), g2 = tfhi(p1.z), g3 = tfhi(p1.w);
    q[0] = make_float4(h0, g0, tfhi(p0.x - h0), tfhi(p1.x - g0));
    q[1] = make_float4(h1, g1, tfhi(p0.y - h1), tfhi(p1.y - g1));
    q[2] = make_float4(h2, g2, tfhi(p0.z - h2), tfhi(p1.z - g2));
    q[3] = make_float4(h3, g3, tfhi(p0.w - h3), tfhi(p1.w - g3));
}

// ---------------- weight padding ----------------
__global__ void pad_w(const float* __restrict__ w, float* __restrict__ wp, int N, int K)
{
    int i = blockIdx.x * 256 + threadIdx.x;
    if (i < N * KP_) {
        int n = i / KP_, k = i - n * KP_;
        wp[i] = (k < K) ? w[(size_t)n * K + k] : 0.f;
    }
}

// ---------------- transpose x [B,I,T] -> xt [(t*B+b), 160] ----------------
__global__ void transpose_x(const float* __restrict__ x, float* __restrict__ xt)
{
    __shared__ float sm[32][33];
    const int b  = blockIdx.z;
    const int i0 = blockIdx.y * 32;
    const int t0 = blockIdx.x * 32;
    const int tx = threadIdx.x, ty = threadIdx.y;
#pragma unroll
    for (int s = 0; s < 32; s += 8) {
        int i = i0 + ty + s, t = t0 + tx;
        sm[ty + s][tx] = (i < I_ && t < T_) ? x[((size_t)b * I_ + i) * T_ + t] : 0.f;
    }
    __syncthreads();
#pragma unroll
    for (int s = 0; s < 32; s += 8) {
        int t = t0 + ty + s, i = i0 + tx;
        if (t < T_ && i < KP_)
            xt[((size_t)t * B_ + b) * KP_ + i] = sm[tx][ty + s];
    }
}

// ---------------- pack xt fp32 [row,160] -> bf16 words [row,80] (MMA layout) -----
__global__ void pack_xt(const float* __restrict__ xt, unsigned* __restrict__ xtb)
{
    int i = blockIdx.x * 256 + threadIdx.x;          // word index
    if (i < T_ * B_ * XPW_) {
        int row = i / XPW_, rem = i - row * XPW_;
        int kb2 = rem >> 3, w = rem & 7;
        int kl = (w & 1) ? (w + 7) : w;              // pair-interleaved layout
        int k0 = kb2 * 16 + kl;
        const float* p = xt + (size_t)row * KP_ + k0;
        xtb[i] = bf2(p[0], p[1]);
    }
}

// ---------------- GEMM (3xTF32, ktile 16, double-buffered, 2 CTA/SM) -------------
#define TB2 9216

__device__ __forceinline__ void ld_regs(
    const float* __restrict__ A, int ldA,
    const float* __restrict__ W, int ldW,
    int m0, int n0, int N, int K, int kt, int tid,
    float4 ra[2], float4 rw[2])
{
    const float4 z = make_float4(0.f, 0.f, 0.f, 0.f);
    const int row = tid >> 1, kbl = tid & 1;
    int k = kt * 16 + kbl * 8;
    if (k + 8 <= K) {
        const float* p = A + (size_t)(m0 + row) * ldA + k;
        ra[0] = *(const float4*)p;
        ra[1] = *(const float4*)(p + 4);
    } else { ra[0] = z; ra[1] = z; }
    if (tid < 128) {
        int wr = tid >> 1;
        if (k + 8 <= K && n0 + wr < N) {
            const float* p = W + (size_t)(n0 + wr) * ldW + k;
            rw[0] = *(const float4*)p;
            rw[1] = *(const float4*)(p + 4);
        } else { rw[0] = z; rw[1] = z; }
    }
}

__device__ __forceinline__ void st_smem(float* buf, int tid, float4 ra[2], float4 rw[2])
{
    const int row = tid >> 1, kbl = tid & 1;
    {
        float4 q[4];
        split8(ra[0], ra[1], q);
        float4* da = (float4*)(buf + row * 48 + kbl * 16);
        int rot = row & 3;
#pragma unroll
        for (int j = 0; j < 4; ++j) { int jj = (rot + j) & 3; da[jj] = q[jj]; }
    }
    if (tid < 128) {
        int wr = tid >> 1;
        float4 q[4];
        split8(rw[0], rw[1], q);
        float4* dw = (float4*)(buf + 6144 + wr * 48 + kbl * 16);
        int rot = wr & 3;
#pragma unroll
        for (int j = 0; j < 4; ++j) { int jj = (rot + j) & 3; dw[jj] = q[jj]; }
    }
}

__device__ __forceinline__ void mma_tile16(const float* buf, int wm, int wn,
                                           int g4, int tg, float acc[2][4][4])
{
    const float* Sw = buf + 6144;
#pragma unroll
    for (int kk = 0; kk < 2; ++kk) {
        int koff = kk * 16 + tg * 4;
        uint32_t ah[2][4], al[2][4];
#pragma unroll
        for (int mf = 0; mf < 2; ++mf) {
            const float* pa = buf + (wm * 32 + mf * 16 + g4) * 48 + koff;
            float4 A0 = *(const float4*)pa;
            float4 A1 = *(const float4*)(pa + 8 * 48);
            ah[mf][0] = fu(A0.x); ah[mf][1] = fu(A1.x);
            ah[mf][2] = fu(A0.y); ah[mf][3] = fu(A1.y);
            al[mf][0] = fu(A0.z); al[mf][1] = fu(A1.z);
            al[mf][2] = fu(A0.w); al[mf][3] = fu(A1.w);
        }
#pragma unroll
        for (int nf = 0; nf < 4; ++nf) {
            const float* pb = Sw + (wn * 32 + nf * 8 + g4) * 48 + koff;
            float4 Bv = *(const float4*)pb;
            uint32_t bh[2] = {fu(Bv.x), fu(Bv.y)};
            uint32_t bl[2] = {fu(Bv.z), fu(Bv.w)};
            mma_tf32(acc[0][nf], ah[0], bh);
            mma_tf32(acc[0][nf], ah[0], bl);
            mma_tf32(acc[0][nf], al[0], bh);
            mma_tf32(acc[1][nf], ah[1], bh);
            mma_tf32(acc[1][nf], ah[1], bl);
            mma_tf32(acc[1][nf], al[1], bh);
        }
    }
}

template <int MODE>
__global__ void __launch_bounds__(256, 2) gemm_tc(
    const float* __restrict__ A, int ldA,
    const float* __restrict__ W, int ldW,
    const float* __restrict__ bias,
    float* __restrict__ out, int K, int N, int ldOut)
{
    extern __shared__ float sm[];
    const int tid  = threadIdx.x;
    const int warp = tid >> 5, lane = tid & 31;
    const int wm = warp >> 1, wn = warp & 1;
    const int g4 = lane >> 2, tg = lane & 3;
    const int m0 = blockIdx.y * 128;
    const int n0 = blockIdx.x * 64;

    float acc[2][4][4] = {};
    float4 ra[2], rw[2];

    const int ktiles = (K + 15) >> 4;

    ld_regs(A, ldA, W, ldW, m0, n0, N, K, 0, tid, ra, rw);
    st_smem(sm, tid, ra, rw);
    __syncthreads();

    for (int kt = 0; kt < ktiles; ++kt) {
        if (kt + 1 < ktiles)
            ld_regs(A, ldA, W, ldW, m0, n0, N, K, kt + 1, tid, ra, rw);
        mma_tile16(sm + (kt & 1) * TB2, wm, wn, g4, tg, acc);
        if (kt + 1 < ktiles)
            st_smem(sm + ((kt + 1) & 1) * TB2, tid, ra, rw);
        __syncthreads();
    }

#pragma unroll
    for (int mf = 0; mf < 2; ++mf) {
        int m_a = m0 + wm * 32 + mf * 16 + g4;
#pragma unroll
        for (int nf = 0; nf < 4; ++nf) {
            int n = n0 + wn * 32 + nf * 8 + tg * 2;
#pragma unroll
            for (int half = 0; half < 2; ++half) {
                int m = m_a + half * 8;
                float v0 = acc[mf][nf][half * 2 + 0];
                float v1 = acc[mf][nf][half * 2 + 1];
                if (MODE == 1) {
                    if (n < KP_) {
                        float2 o;
                        o.x = (n     < N) ? fmaxf(v0 + bias[n], 0.f)     : 0.f;
                        o.y = (n + 1 < N) ? fmaxf(v1 + bias[n + 1], 0.f) : 0.f;
                        *(float2*)(out + (size_t)m * ldOut + n) = o;
                    }
                } else {
                    int tt = m >> 8, b = m & 255;
                    if (n < N)
                        out[((size_t)b * I_ + n) * T_ + tt] = sigmf(v0 + bias[n]);
                    if (n + 1 < N)
                        out[((size_t)b * I_ + n + 1) * T_ + tt] = sigmf(v1 + bias[n + 1]);
                }
            }
        }
    }
}

// ---------------- wavefront LSTM (bf16, xg1 GEMM fused into L1) -----------------
// 100 blocks: blockIdx < 50 -> layer 1, else layer 2 (runs behind via flags).
// Per layer: 2 batch groups x 128 batches, 25 unit-blocks (8 units = 32 gate cols).
// L1 per step t: acc = xt(t)@w_ih1^T (10 kb2) + h(t-1)@w_hh1^T (13 kb2); gates add
// biases from registers. xt tile prefetched via cp.async BEFORE the barrier.
// L1 also fused-computes xg2(t-1) = h(t-1)@w_ih2^T (+L2 biases) for the L2 wave.
__global__ void __launch_bounds__(256, 1) lstm_wave(
    const unsigned* __restrict__ xtb,
    const float* __restrict__ wih1, const float* __restrict__ bi1,
    const float* __restrict__ bh1,  const float* __restrict__ whh1,
    const float* __restrict__ wih2, const float* __restrict__ whh2,
    const float* __restrict__ bi2,  const float* __restrict__ bh2,
    unsigned* __restrict__ hs1, unsigned* __restrict__ hs2,
    float* __restrict__ h2l, float* __restrict__ xg2)
{
    extern __shared__ uint32_t smu[];
    uint32_t* w_su  = smu + OFF_WHH;
    uint32_t* w2_su = smu + OFF_WIH2;
    uint32_t* w1_su = smu + OFF_WIH1;
    uint32_t* h_su  = smu + OFF_H;
    uint32_t* xt_su = smu + OFF_XT;
    float*    g_s   = (float*)(smu + OFF_GS);

    const int tid  = threadIdx.x;
    const int warp = tid >> 5, lane = tid & 31;
    const int g4 = lane >> 2, tg = lane & 3;
    const int wm = warp >> 1;              // 0..3 -> rows wm*32..+31
    const int wn = warp & 1;               // 0..1 -> cols wn*16..+15

    const int role = (blockIdx.x >= 50);
    const int bid  = blockIdx.x - role * 50;
    const int grp  = bid / 25;
    const int ublk = bid - grp * 25;
    const int gb0  = grp * 128;
    const int u0   = ublk * 8;
    const int barid = role * 2 + grp;

    const float* whh = role ? whh2 : whh1;
    unsigned* hsout = role ? hs2 : hs1;
    unsigned* flag = &g_l1prog[grp][ublk];

    // ---- stage recurrent weight slices: col c = gate*8+ul, packed bf16 ----
    for (int i = 0; i < 13; ++i) {
        int lin = tid + 256 * i;                      // 32 * 104 = 3328 words
        if (lin < 3328) {
            int c = lin / 104, rem = lin - c * 104;
            int kb2 = rem >> 3, w = rem & 7;
            int kl = (w & 1) ? (w + 7) : w;
            int k0 = kb2 * 16 + kl;
            int grow = (c >> 3) * H_ + u0 + (c & 7);
            const float* wr_ = whh + (size_t)grow * H_;
            float v0 = (k0     < H_) ? wr_[k0]     : 0.f;
            float v1 = (k0 + 1 < H_) ? wr_[k0 + 1] : 0.f;
            w_su[c * 104 + kb2 * 8 + w] = bf2(v0, v1);
            if (!role) {
                const float* w2r = wih2 + (size_t)grow * H_;
                float u0v = (k0     < H_) ? w2r[k0]     : 0.f;
                float u1v = (k0 + 1 < H_) ? w2r[k0 + 1] : 0.f;
                w2_su[c * 104 + kb2 * 8 + w] = bf2(u0v, u1v);
            }
        }
    }
    // ---- stage w_ih1 slice (L1 only): 32 cols x 80 words, stride 88 ----
    if (!role) {
        for (int i = 0; i < 10; ++i) {
            int lin = tid + 256 * i;                  // 32 * 80 = 2560 words
            if (lin < 2560) {
                int c = lin / 80, rem = lin - c * 80;
                int kb2 = rem >> 3, w = rem & 7;
                int kl = (w & 1) ? (w + 7) : w;
                int k0 = kb2 * 16 + kl;
                int grow = (c >> 3) * H_ + u0 + (c & 7);
                const float* w1r = wih1 + (size_t)grow * I_;
                float v0 = (k0     < I_) ? w1r[k0]     : 0.f;
                float v1 = (k0 + 1 < I_) ? w1r[k0 + 1] : 0.f;
                w1_su[c * 88 + kb2 * 8 + w] = bf2(v0, v1);
            }
        }
    }

    // L2 bias fold for xg2 writes (L1 role only)
    const int nc0 = (wn * 2 + 0) * H_ + u0 + tg * 2;
    const int nc1 = (wn * 2 + 1) * H_ + u0 + tg * 2;
    float bf00 = 0.f, bf01 = 0.f, bf10 = 0.f, bf11 = 0.f;
    if (!role) {
        bf00 = bi2[nc0] + bh2[nc0];     bf01 = bi2[nc0 + 1] + bh2[nc0 + 1];
        bf10 = bi2[nc1] + bh2[nc1];     bf11 = bi2[nc1 + 1] + bh2[nc1 + 1];
    }

    // epilogue ownership: 1 batch x 4 units per thread
    const int eb  = tid >> 1;              // 0..127
    const int eul = (tid & 1) * 4;         // 0 or 4
    float cc0 = 0.f, cc1 = 0.f, cc2 = 0.f, cc3 = 0.f;
    const int ug = u0 + eul;
    const int jg = ug >> 4;
    const int rr = ug & 15;
    const int p0 = rr >> 1;
    const int wo0 = (p0     < 4) ? 2 * p0       : 2 * (p0 - 4) + 1;
    const int wo1 = (p0 + 1 < 4) ? 2 * (p0 + 1) : 2 * (p0 - 3) + 1;

    // L1 gate biases (constant per thread): 4 units x 4 gates
    float4 bq0, bq1, bq2, bq3;
    if (!role) {
        const float* bA = bi1; const float* bB = bh1;
        bq0 = make_float4(bA[0*H_+ug]+bB[0*H_+ug], bA[0*H_+ug+1]+bB[0*H_+ug+1],
                          bA[0*H_+ug+2]+bB[0*H_+ug+2], bA[0*H_+ug+3]+bB[0*H_+ug+3]);
        bq1 = make_float4(bA[1*H_+ug]+bB[1*H_+ug], bA[1*H_+ug+1]+bB[1*H_+ug+1],
                          bA[1*H_+ug+2]+bB[1*H_+ug+2], bA[1*H_+ug+3]+bB[1*H_+ug+3]);
        bq2 = make_float4(bA[2*H_+ug]+bB[2*H_+ug], bA[2*H_+ug+1]+bB[2*H_+ug+1],
                          bA[2*H_+ug+2]+bB[2*H_+ug+2], bA[2*H_+ug+3]+bB[2*H_+ug+3]);
        bq3 = make_float4(bA[3*H_+ug]+bB[3*H_+ug], bA[3*H_+ug+1]+bB[3*H_+ug+1],
                          bA[3*H_+ug+2]+bB[3*H_+ug+2], bA[3*H_+ug+3]+bB[3*H_+ug+3]);
    }

    const uint32_t* hA  = h_su + (wm * 32 + g4) * 104 + tg * 2;
    const uint32_t* xA  = xt_su + (wm * 32 + g4) * 88 + tg * 2;
    const uint32_t* wB0 = w_su + (wn * 16 + g4) * 104 + tg * 2;
    const uint32_t* wB1 = wB0 + 8 * 104;
    const uint32_t* vB0 = w2_su + (wn * 16 + g4) * 104 + tg * 2;
    const uint32_t* vB1 = vB0 + 8 * 104;
    const uint32_t* uB0 = w1_su + (wn * 16 + g4) * 88 + tg * 2;
    const uint32_t* uB1 = uB0 + 8 * 88;
    const int rowM = gb0 + wm * 32 + g4;
    const uint32_t h_su32  = (uint32_t)__cvta_generic_to_shared(h_su);
    const uint32_t xt_su32 = (uint32_t)__cvta_generic_to_shared(xt_su);

    const int TEND = role ? T_ : T_ + 1;

    for (int t = 0; t < TEND; ++t) {
        const bool tail = (!role && t == T_);

        // L1: prefetch xt(t) tile BEFORE the barrier (no recurrence dependency)
        if (!role && !tail) {
            const uint4* src = (const uint4*)(xtb + ((size_t)t * B_ + gb0) * XPW_);
#pragma unroll
            for (int i = 0; i < 10; ++i) {
                int lin = tid + 256 * i;               // 128*20 = 2560
                int row = lin / 20, rem = lin - row * 20;
                cpasync16(xt_su32 + (row * 88 + rem * 4) * 4, src + row * 20 + rem);
            }
            asm volatile("cp.async.commit_group;" ::: "memory");
        }

        // group barrier (+ L2: wait for xg2(t))
        if (t > 0) {
            __syncthreads();
            if (tid == 0) {
                __threadfence();
                unsigned gen = *(volatile unsigned*)&g_gen2[barid];
                if (atomicAdd(&g_cnt2[barid], 1u) == 24u) {
                    atomicExch(&g_cnt2[barid], 0u);
                    __threadfence();
                    atomicAdd(&g_gen2[barid], 1u);
                } else {
                    while (*(volatile unsigned*)&g_gen2[barid] == gen) { }
                }
                if (role) {
                    while (*(volatile unsigned*)flag < (unsigned)(t + 1)) { }
                }
                __threadfence();
            }
            __syncthreads();
        } else if (role) {
            if (tid == 0) {
                while (*(volatile unsigned*)flag < 1u) { }
                __threadfence();
            }
            __syncthreads();
        }

        // L2: load xg2(t) after the wait (includes all biases)
        float4 q0, q1, q2, q3;
        if (role) {
            const float* xr = xg2 + ((size_t)t * B_ + gb0 + eb) * G_ + u0 + eul;
            q0 = *(const float4*)(xr);
            q1 = *(const float4*)(xr + H_);
            q2 = *(const float4*)(xr + 2 * H_);
            q3 = *(const float4*)(xr + 3 * H_);
        } else {
            q0 = bq0; q1 = bq1; q2 = bq2; q3 = bq3;
        }

        // stage h(t-1): 128 packed bf16 rows
        if (t == 0) {
            uint4 z = make_uint4(0u, 0u, 0u, 0u);
            for (int lin = tid; lin < 3328; lin += 256)
                ((uint4*)h_su)[lin] = z;
        } else {
            const uint4* src = (const uint4*)(hsout + ((size_t)(t - 1) * B_ + gb0) * HPW_);
#pragma unroll
            for (int i = 0; i < 13; ++i) {
                int lin = tid + 256 * i;               // 128*26 = 3328
                int row = lin / 26, rem = lin - row * 26;
                cpasync16(h_su32 + (row * 104 + rem * 4) * 4, src + row * 26 + rem);
            }
            asm volatile("cp.async.commit_group;" ::: "memory");
        }
        asm volatile("cp.async.wait_group 0;" ::: "memory");  // xt + h both done
        __syncthreads();

        // MMA: acc = xt(t)@wih1 (L1) + h(t-1)@whh; xac = h(t-1)@wih2 (L1 fused)
        float acc[2][2][4] = {};
        float xac[2][2][4] = {};
        if (!role && !tail) {
#pragma unroll
            for (int kb2 = 0; kb2 < 10; ++kb2) {
                uint2 r0 = *(const uint2*)(xA + kb2 * 8);
                uint2 r1 = *(const uint2*)(xA + kb2 * 8 + 8 * 88);
                uint2 r2 = *(const uint2*)(xA + kb2 * 8 + 16 * 88);
                uint2 r3 = *(const uint2*)(xA + kb2 * 8 + 24 * 88);
                uint32_t a0[4] = {r0.x, r1.x, r0.y, r1.y};
                uint32_t a1[4] = {r2.x, r3.x, r2.y, r3.y};
                uint2 bb0 = *(const uint2*)(uB0 + kb2 * 8);
                uint2 bb1 = *(const uint2*)(uB1 + kb2 * 8);
                uint32_t b0[2] = {bb0.x, bb0.y};
                uint32_t b1[2] = {bb1.x, bb1.y};
                mma_bf16(acc[0][0], a0, b0);
                mma_bf16(acc[1][0], a1, b0);
                mma_bf16(acc[0][1], a0, b1);
                mma_bf16(acc[1][1], a1, b1);
            }
        }
#pragma unroll
        for (int kb2 = 0; kb2 < 13; ++kb2) {
            uint2 r0 = *(const uint2*)(hA + kb2 * 8);
            uint2 r1 = *(const uint2*)(hA + kb2 * 8 + 8 * 104);
            uint2 r2 = *(const uint2*)(hA + kb2 * 8 + 16 * 104);
            uint2 r3 = *(const uint2*)(hA + kb2 * 8 + 24 * 104);
            uint32_t a0[4] = {r0.x, r1.x, r0.y, r1.y};
            uint32_t a1[4] = {r2.x, r3.x, r2.y, r3.y};
            if (!tail) {
                uint2 bb0 = *(const uint2*)(wB0 + kb2 * 8);
                uint2 bb1 = *(const uint2*)(wB1 + kb2 * 8);
                uint32_t b0[2] = {bb0.x, bb0.y};
                uint32_t b1[2] = {bb1.x, bb1.y};
                mma_bf16(acc[0][0], a0, b0);
                mma_bf16(acc[1][0], a1, b0);
                mma_bf16(acc[0][1], a0, b1);
                mma_bf16(acc[1][1], a1, b1);
            }
            if (!role && t > 0) {
                uint2 vv0 = *(const uint2*)(vB0 + kb2 * 8);
                uint2 vv1 = *(const uint2*)(vB1 + kb2 * 8);
                uint32_t v0[2] = {vv0.x, vv0.y};
                uint32_t v1[2] = {vv1.x, vv1.y};
                mma_bf16(xac[0][0], a0, v0);
                mma_bf16(xac[1][0], a1, v0);
                mma_bf16(xac[0][1], a0, v1);
                mma_bf16(xac[1][1], a1, v1);
            }
        }

        // L1: write xg2(t-1) with L2 biases folded
        if (!role && t > 0) {
#pragma unroll
            for (int mf = 0; mf < 2; ++mf) {
                float* xo = xg2 + ((size_t)(t - 1) * B_ + rowM + mf * 16) * G_;
                __stcg((float2*)(xo + nc0),          make_float2(xac[mf][0][0] + bf00, xac[mf][0][1] + bf01));
                __stcg((float2*)(xo + nc1),          make_float2(xac[mf][1][0] + bf10, xac[mf][1][1] + bf11));
                __stcg((float2*)(xo + 8 * G_ + nc0), make_float2(xac[mf][0][2] + bf00, xac[mf][0][3] + bf01));
                __stcg((float2*)(xo + 8 * G_ + nc1), make_float2(xac[mf][1][2] + bf10, xac[mf][1][3] + bf11));
            }
        }
        if (tail) {
            __syncthreads();
            if (tid == 0) {
                __threadfence();
                *(volatile unsigned*)flag = (unsigned)t;   // = 600
            }
            break;
        }

        // accumulators -> g_s (stride 40)
#pragma unroll
        for (int mf = 0; mf < 2; ++mf) {
            float* d0 = g_s + (wm * 32 + mf * 16 + g4) * 40 + wn * 16 + tg * 2;
            *(float2*)(d0)              = make_float2(acc[mf][0][0], acc[mf][0][1]);
            *(float2*)(d0 + 8)          = make_float2(acc[mf][1][0], acc[mf][1][1]);
            *(float2*)(d0 + 8 * 40)     = make_float2(acc[mf][0][2], acc[mf][0][3]);
            *(float2*)(d0 + 8 * 40 + 8) = make_float2(acc[mf][1][2], acc[mf][1][3]);
        }
        __syncthreads();
        if (!role && t > 0 && tid == 0) {
            __threadfence();
            *(volatile unsigned*)flag = (unsigned)t;       // xg2(0..t-1) published
        }

        // gates + cell update: 1 batch x 4 units per thread
        {
            const float* gr = g_s + eb * 40 + eul;
            float iv, fv, gv, ov, h0, h1, h2, h3;
            iv = sigmf(gr[0] + q0.x);  fv = sigmf(gr[8] + q1.x);
            gv = tanh_fast(gr[16] + q2.x); ov = sigmf(gr[24] + q3.x);
            cc0 = fv * cc0 + iv * gv;  h0 = ov * tanh_fast(cc0);

            iv = sigmf(gr[1] + q0.y);  fv = sigmf(gr[9] + q1.y);
            gv = tanh_fast(gr[17] + q2.y); ov = sigmf(gr[25] + q3.y);
            cc1 = fv * cc1 + iv * gv;  h1 = ov * tanh_fast(cc1);

            iv = sigmf(gr[2] + q0.z);  fv = sigmf(gr[10] + q1.z);
            gv = tanh_fast(gr[18] + q2.z); ov = sigmf(gr[26] + q3.z);
            cc2 = fv * cc2 + iv * gv;  h2 = ov * tanh_fast(cc2);

            iv = sigmf(gr[3] + q0.w);  fv = sigmf(gr[11] + q1.w);
            gv = tanh_fast(gr[19] + q2.w); ov = sigmf(gr[27] + q3.w);
            cc3 = fv * cc3 + iv * gv;  h3 = ov * tanh_fast(cc3);

            unsigned* hb = hsout + ((size_t)t * B_ + gb0 + eb) * HPW_ + jg * 8;
            __stcg(hb + wo0, bf2(h0, h1));
            __stcg(hb + wo1, bf2(h2, h3));
            if (role) {
                float* hl = h2l + ((size_t)t * B_ + gb0 + eb) * H_ + u0 + eul;
                *(float4*)hl = make_float4(h0, h1, h2, h3);
            }
        }
    }

    // consumer resets its flag -> graph-replay safe
    if (role) {
        __syncthreads();
        if (tid == 0) *(volatile unsigned*)flag = 0u;
    }
}

// ---------------- launch --------------------------------------------------------
extern "C" void kernel_launch(void* const* d_in, const int* in_sizes, int n_in,
                              void* d_out, int out_size)
{
    const float* x     = (const float*)d_in[0];
    const float* w_ih1 = (const float*)d_in[1];
    const float* w_hh1 = (const float*)d_in[2];
    const float* b_ih1 = (const float*)d_in[3];
    const float* b_hh1 = (const float*)d_in[4];
    const float* w_ih2 = (const float*)d_in[5];
    const float* w_hh2 = (const float*)d_in[6];
    const float* b_ih2 = (const float*)d_in[7];
    const float* b_hh2 = (const float*)d_in[8];
    const float* fc1_w = (const float*)d_in[9];
    const float* fc1_b = (const float*)d_in[10];
    const float* fc2_w = (const float*)d_in[11];
    const float* fc2_b = (const float*)d_in[12];
    float* out = (float*)d_out;

    float *xg2, *h2l, *tmp, *wp2;
    unsigned *hs1, *hs2, *xtb;
    cudaGetSymbolAddress((void**)&xg2, g_xg2);
    cudaGetSymbolAddress((void**)&xtb, g_xtb);
    cudaGetSymbolAddress((void**)&hs1, g_hs1);
    cudaGetSymbolAddress((void**)&hs2, g_hs2);
    cudaGetSymbolAddress((void**)&h2l, g_h2l);
    cudaGetSymbolAddress((void**)&tmp, g_tmp);
    cudaGetSymbolAddress((void**)&wp2, g_wp2);

    const int WAVE_SMEM = WAVE_WORDS * 4;            // 156672 B
    cudaFuncSetAttribute(lstm_wave, cudaFuncAttributeMaxDynamicSharedMemorySize, WAVE_SMEM);

    const int GEMM_SMEM = 2 * TB2 * (int)sizeof(float);  // 73728
    cudaFuncSetAttribute((const void*)gemm_tc<1>, cudaFuncAttributeMaxDynamicSharedMemorySize, GEMM_SMEM);
    cudaFuncSetAttribute((const void*)gemm_tc<2>, cudaFuncAttributeMaxDynamicSharedMemorySize, GEMM_SMEM);

    const int MROWS = B_ * T_;
    const dim3 frows(3, MROWS / 128);

    // 0. pad fc2_w to [129,160]
    pad_w<<<(I_ * KP_ + 255) / 256, 256>>>(fc2_w, wp2, I_, I_);
    // 1. x -> [T*B, 160] fp32
    transpose_x<<<dim3((T_ + 31) / 32, KP_ / 32, B_), dim3(32, 8)>>>(x, tmp);
    // 2. pack xt -> bf16 MMA-word layout
    pack_xt<<<(T_ * B_ * XPW_ + 255) / 256, 256>>>(tmp, xtb);
    // 3. wavefront: L1 (xg1 fused in + xg2 fused out) + L2, overlapped
    lstm_wave<<<100, 256, WAVE_SMEM>>>(xtb, w_ih1, b_ih1, b_hh1, w_hh1,
                                       w_ih2, w_hh2, b_ih2, b_hh2,
                                       hs1, hs2, h2l, xg2);
    // 4. y1 = relu(h2 @ fc1_w^T + fc1_b) -> tmp[., 160]
    gemm_tc<1><<<frows, 256, GEMM_SMEM>>>(h2l, H_, fc1_w, H_, fc1_b, tmp, H_, I_, KP_);
    // 5. out = sigmoid(y1 @ wp2^T + fc2_b), transposed store to [B,129,T]
    gemm_tc<2><<<frows, 256, GEMM_SMEM>>>(tmp, KP_, wp2, KP_, fc2_b, out, KP_, I_, 0);
}

// round 13
// speedup vs baseline: 2.8569x; 1.0549x over previous
#include <cuda_runtime.h>
#include <cstdint>
#include <cstdio>

#define B_   256
#define T_   600
#define I_   129
#define H_   200
#define G_   800   // 4*H
#define KP_  160   // padded K for the I=129 operands
#define HPW_ 104   // packed bf16 h row: 13 kb2-groups * 8 uint32 words
#define XPW_ 80    // packed bf16 xt row: 10 kb2-groups * 8 words

// smem word offsets for the wave kernel
#define OFF_WHH  0        // 32*104
#define OFF_WIH2 3328     // 32*104
#define OFF_WIH1 6656     // 32*88 (stride 88, 80 used)
#define OFF_H    9472     // 128*104
#define OFF_XT   22784    // 128*88
#define OFF_GS   34048    // 128*40 floats
#define WAVE_WORDS 39168  // total words (156672 B)

// ---------------- scratch (device globals; no cudaMalloc allowed) ----------------
__device__ float    g_xg2[(size_t)T_ * B_ * G_];     // xg2 (with biases, from L1)
__device__ unsigned g_xtb[(size_t)T_ * B_ * XPW_];   // packed bf16 xt (49 MB)
__device__ unsigned g_hs1[(size_t)T_ * B_ * HPW_];   // packed bf16 h, layer 1
__device__ unsigned g_hs2[(size_t)T_ * B_ * HPW_];   // packed bf16 h, layer 2
__device__ float    g_h2l[(size_t)T_ * B_ * H_];     // linear fp32 h2 (for fc1)
__device__ float    g_tmp[(size_t)T_ * B_ * KP_];    // xt fp32, later y1 (stride 160)
__device__ float    g_wp2[I_ * KP_];                 // fc2_w padded to [129,160]

// legacy counter barrier (only used for the end-of-kernel drain/reset)
__device__ unsigned g_cnt2[4] = {0, 0, 0, 0};
__device__ unsigned g_gen2[4] = {0, 0, 0, 0};
// per-step arrival epochs: [barid][block]; value = completed step + 1
__device__ unsigned g_arr[4][25];
// L1 -> L2 progress flags (completed L1 xg2 step; reset by consumer at end)
__device__ unsigned g_l1prog[2][25];

// ---------------- fast activations ----------------
__device__ __forceinline__ float sigmf(float x) {
    return __fdividef(1.f, 1.f + __expf(-x));
}
__device__ __forceinline__ float tanh_fast(float x) {
    float e = __expf(2.f * x);
    return 1.f - __fdividef(2.f, e + 1.f);
}

// ---------------- tf32 / bf16 helpers ----------------
__device__ __forceinline__ uint32_t f2tf32(float x) {
    uint32_t r;
    asm("cvt.rna.tf32.f32 %0, %1;" : "=r"(r) : "f"(x));
    return r;
}
__device__ __forceinline__ float tfhi(float v) { return __uint_as_float(f2tf32(v)); }
__device__ __forceinline__ uint32_t fu(float v) { return __float_as_uint(v); }

// bf16x2 with element0 = a (lower half), element1 = b
__device__ __forceinline__ uint32_t bf2(float a, float b) {
    uint32_t r;
    asm("cvt.rn.bf16x2.f32 %0, %1, %2;" : "=r"(r) : "f"(b), "f"(a));
    return r;
}

// scoped release/acquire for the flag protocol
__device__ __forceinline__ void st_release_gpu(unsigned* p, unsigned v) {
    asm volatile("st.release.gpu.u32 [%0], %1;" :: "l"(p), "r"(v) : "memory");
}
__device__ __forceinline__ unsigned ld_acquire_gpu(const unsigned* p) {
    unsigned v;
    asm volatile("ld.acquire.gpu.u32 %0, [%1];" : "=r"(v) : "l"(p) : "memory");
    return v;
}

__device__ __forceinline__ void mma_tf32(float* d, const uint32_t* a, const uint32_t* b) {
    asm volatile(
        "mma.sync.aligned.m16n8k8.row.col.f32.tf32.tf32.f32 "
        "{%0,%1,%2,%3}, {%4,%5,%6,%7}, {%8,%9}, {%0,%1,%2,%3};"
        : "+f"(d[0]), "+f"(d[1]), "+f"(d[2]), "+f"(d[3])
        : "r"(a[0]), "r"(a[1]), "r"(a[2]), "r"(a[3]), "r"(b[0]), "r"(b[1]));
}
__device__ __forceinline__ void mma_bf16(float* d, const uint32_t* a, const uint32_t* b) {
    asm volatile(
        "mma.sync.aligned.m16n8k16.row.col.f32.bf16.bf16.f32 "
        "{%0,%1,%2,%3}, {%4,%5,%6,%7}, {%8,%9}, {%0,%1,%2,%3};"
        : "+f"(d[0]), "+f"(d[1]), "+f"(d[2]), "+f"(d[3])
        : "r"(a[0]), "r"(a[1]), "r"(a[2]), "r"(a[3]), "r"(b[0]), "r"(b[1]));
}

__device__ __forceinline__ void cpasync16(uint32_t dst, const void* src) {
    asm volatile("cp.async.cg.shared.global [%0], [%1], 16;" :: "r"(dst), "l"(src));
}

// interleaved 8-k split for the 3xTF32 GEMMs
__device__ __forceinline__ void split8(float4 p0, float4 p1, float4 q[4])
{
    float h0 = tfhi(p0.x), h1 = tfhi(p0.y), h2 = tfhi(p0.z), h3 = tfhi(p0.w);
    float g0 = tfhi(p1.x), g1 = tfhi(p1.y), g2 = tfhi(p1.z), g3 = tfhi(p1.w);
    q[0] = make_float4(h0, g0, tfhi(p0.x - h0), tfhi(p1.x - g0));
    q[1] = make_float4(h1, g1, tfhi(p0.y - h1), tfhi(p1.y - g1));
    q[2] = make_float4(h2, g2, tfhi(p0.z - h2), tfhi(p1.z - g2));
    q[3] = make_float4(h3, g3, tfhi(p0.w - h3), tfhi(p1.w - g3));
}

// ---------------- weight padding ----------------
__global__ void pad_w(const float* __restrict__ w, float* __restrict__ wp, int N, int K)
{
    int i = blockIdx.x * 256 + threadIdx.x;
    if (i < N * KP_) {
        int n = i / KP_, k = i - n * KP_;
        wp[i] = (k < K) ? w[(size_t)n * K + k] : 0.f;
    }
}

// ---------------- transpose x [B,I,T] -> xt [(t*B+b), 160] ----------------
__global__ void transpose_x(const float* __restrict__ x, float* __restrict__ xt)
{
    __shared__ float sm[32][33];
    const int b  = blockIdx.z;
    const int i0 = blockIdx.y * 32;
    const int t0 = blockIdx.x * 32;
    const int tx = threadIdx.x, ty = threadIdx.y;
#pragma unroll
    for (int s = 0; s < 32; s += 8) {
        int i = i0 + ty + s, t = t0 + tx;
        sm[ty + s][tx] = (i < I_ && t < T_) ? x[((size_t)b * I_ + i) * T_ + t] : 0.f;
    }
    __syncthreads();
#pragma unroll
    for (int s = 0; s < 32; s += 8) {
        int t = t0 + ty + s, i = i0 + tx;
        if (t < T_ && i < KP_)
            xt[((size_t)t * B_ + b) * KP_ + i] = sm[tx][ty + s];
    }
}

// ---------------- pack xt fp32 [row,160] -> bf16 words [row,80] (MMA layout) -----
__global__ void pack_xt(const float* __restrict__ xt, unsigned* __restrict__ xtb)
{
    int i = blockIdx.x * 256 + threadIdx.x;          // word index
    if (i < T_ * B_ * XPW_) {
        int row = i / XPW_, rem = i - row * XPW_;
        int kb2 = rem >> 3, w = rem & 7;
        int kl = (w & 1) ? (w + 7) : w;              // pair-interleaved layout
        int k0 = kb2 * 16 + kl;
        const float* p = xt + (size_t)row * KP_ + k0;
        xtb[i] = bf2(p[0], p[1]);
    }
}

// ---------------- GEMM (3xTF32, ktile 16, double-buffered, 2 CTA/SM) -------------
#define TB2 9216

__device__ __forceinline__ void ld_regs(
    const float* __restrict__ A, int ldA,
    const float* __restrict__ W, int ldW,
    int m0, int n0, int N, int K, int kt, int tid,
    float4 ra[2], float4 rw[2])
{
    const float4 z = make_float4(0.f, 0.f, 0.f, 0.f);
    const int row = tid >> 1, kbl = tid & 1;
    int k = kt * 16 + kbl * 8;
    if (k + 8 <= K) {
        const float* p = A + (size_t)(m0 + row) * ldA + k;
        ra[0] = *(const float4*)p;
        ra[1] = *(const float4*)(p + 4);
    } else { ra[0] = z; ra[1] = z; }
    if (tid < 128) {
        int wr = tid >> 1;
        if (k + 8 <= K && n0 + wr < N) {
            const float* p = W + (size_t)(n0 + wr) * ldW + k;
            rw[0] = *(const float4*)p;
            rw[1] = *(const float4*)(p + 4);
        } else { rw[0] = z; rw[1] = z; }
    }
}

__device__ __forceinline__ void st_smem(float* buf, int tid, float4 ra[2], float4 rw[2])
{
    const int row = tid >> 1, kbl = tid & 1;
    {
        float4 q[4];
        split8(ra[0], ra[1], q);
        float4* da = (float4*)(buf + row * 48 + kbl * 16);
        int rot = row & 3;
#pragma unroll
        for (int j = 0; j < 4; ++j) { int jj = (rot + j) & 3; da[jj] = q[jj]; }
    }
    if (tid < 128) {
        int wr = tid >> 1;
        float4 q[4];
        split8(rw[0], rw[1], q);
        float4* dw = (float4*)(buf + 6144 + wr * 48 + kbl * 16);
        int rot = wr & 3;
#pragma unroll
        for (int j = 0; j < 4; ++j) { int jj = (rot + j) & 3; dw[jj] = q[jj]; }
    }
}

__device__ __forceinline__ void mma_tile16(const float* buf, int wm, int wn,
                                           int g4, int tg, float acc[2][4][4])
{
    const float* Sw = buf + 6144;
#pragma unroll
    for (int kk = 0; kk < 2; ++kk) {
        int koff = kk * 16 + tg * 4;
        uint32_t ah[2][4], al[2][4];
#pragma unroll
        for (int mf = 0; mf < 2; ++mf) {
            const float* pa = buf + (wm * 32 + mf * 16 + g4) * 48 + koff;
            float4 A0 = *(const float4*)pa;
            float4 A1 = *(const float4*)(pa + 8 * 48);
            ah[mf][0] = fu(A0.x); ah[mf][1] = fu(A1.x);
            ah[mf][2] = fu(A0.y); ah[mf][3] = fu(A1.y);
            al[mf][0] = fu(A0.z); al[mf][1] = fu(A1.z);
            al[mf][2] = fu(A0.w); al[mf][3] = fu(A1.w);
        }
#pragma unroll
        for (int nf = 0; nf < 4; ++nf) {
            const float* pb = Sw + (wn * 32 + nf * 8 + g4) * 48 + koff;
            float4 Bv = *(const float4*)pb;
            uint32_t bh[2] = {fu(Bv.x), fu(Bv.y)};
            uint32_t bl[2] = {fu(Bv.z), fu(Bv.w)};
            mma_tf32(acc[0][nf], ah[0], bh);
            mma_tf32(acc[0][nf], ah[0], bl);
            mma_tf32(acc[0][nf], al[0], bh);
            mma_tf32(acc[1][nf], ah[1], bh);
            mma_tf32(acc[1][nf], ah[1], bl);
            mma_tf32(acc[1][nf], al[1], bh);
        }
    }
}

template <int MODE>
__global__ void __launch_bounds__(256, 2) gemm_tc(
    const float* __restrict__ A, int ldA,
    const float* __restrict__ W, int ldW,
    const float* __restrict__ bias,
    float* __restrict__ out, int K, int N, int ldOut)
{
    extern __shared__ float sm[];
    const int tid  = threadIdx.x;
    const int warp = tid >> 5, lane = tid & 31;
    const int wm = warp >> 1, wn = warp & 1;
    const int g4 = lane >> 2, tg = lane & 3;
    const int m0 = blockIdx.y * 128;
    const int n0 = blockIdx.x * 64;

    float acc[2][4][4] = {};
    float4 ra[2], rw[2];

    const int ktiles = (K + 15) >> 4;

    ld_regs(A, ldA, W, ldW, m0, n0, N, K, 0, tid, ra, rw);
    st_smem(sm, tid, ra, rw);
    __syncthreads();

    for (int kt = 0; kt < ktiles; ++kt) {
        if (kt + 1 < ktiles)
            ld_regs(A, ldA, W, ldW, m0, n0, N, K, kt + 1, tid, ra, rw);
        mma_tile16(sm + (kt & 1) * TB2, wm, wn, g4, tg, acc);
        if (kt + 1 < ktiles)
            st_smem(sm + ((kt + 1) & 1) * TB2, tid, ra, rw);
        __syncthreads();
    }

#pragma unroll
    for (int mf = 0; mf < 2; ++mf) {
        int m_a = m0 + wm * 32 + mf * 16 + g4;
#pragma unroll
        for (int nf = 0; nf < 4; ++nf) {
            int n = n0 + wn * 32 + nf * 8 + tg * 2;
#pragma unroll
            for (int half = 0; half < 2; ++half) {
                int m = m_a + half * 8;
                float v0 = acc[mf][nf][half * 2 + 0];
                float v1 = acc[mf][nf][half * 2 + 1];
                if (MODE == 1) {
                    if (n < KP_) {
                        float2 o;
                        o.x = (n     < N) ? fmaxf(v0 + bias[n], 0.f)     : 0.f;
                        o.y = (n + 1 < N) ? fmaxf(v1 + bias[n + 1], 0.f) : 0.f;
                        *(float2*)(out + (size_t)m * ldOut + n) = o;
                    }
                } else {
                    int tt = m >> 8, b = m & 255;
                    if (n < N)
                        out[((size_t)b * I_ + n) * T_ + tt] = sigmf(v0 + bias[n]);
                    if (n + 1 < N)
                        out[((size_t)b * I_ + n + 1) * T_ + tt] = sigmf(v1 + bias[n + 1]);
                }
            }
        }
    }
}

// ---------------- wavefront LSTM (bf16, flag-array acquire/release barrier) -----
// 100 blocks: blockIdx < 50 -> layer 1, else layer 2 (runs behind via prog flags).
// Per layer: 2 batch groups x 128 batches, 25 unit-blocks (8 units = 32 gate cols).
// Sync per step: each block releases arrive[self]=t+1 (one st.release.gpu after
// __syncthreads); warp 0 lanes 0..24 acquire-poll one peer each with nanosleep
// backoff. No atomics, no MEMBAR on the hot path. Epochs are monotonic within a
// launch; an end-of-kernel counter barrier lets each block reset its own slot.
__global__ void __launch_bounds__(256, 1) lstm_wave(
    const unsigned* __restrict__ xtb,
    const float* __restrict__ wih1, const float* __restrict__ bi1,
    const float* __restrict__ bh1,  const float* __restrict__ whh1,
    const float* __restrict__ wih2, const float* __restrict__ whh2,
    const float* __restrict__ bi2,  const float* __restrict__ bh2,
    unsigned* __restrict__ hs1, unsigned* __restrict__ hs2,
    float* __restrict__ h2l, float* __restrict__ xg2)
{
    extern __shared__ uint32_t smu[];
    uint32_t* w_su  = smu + OFF_WHH;
    uint32_t* w2_su = smu + OFF_WIH2;
    uint32_t* w1_su = smu + OFF_WIH1;
    uint32_t* h_su  = smu + OFF_H;
    uint32_t* xt_su = smu + OFF_XT;
    float*    g_s   = (float*)(smu + OFF_GS);

    const int tid  = threadIdx.x;
    const int warp = tid >> 5, lane = tid & 31;
    const int g4 = lane >> 2, tg = lane & 3;
    const int wm = warp >> 1;              // 0..3 -> rows wm*32..+31
    const int wn = warp & 1;               // 0..1 -> cols wn*16..+15

    const int role = (blockIdx.x >= 50);
    const int bid  = blockIdx.x - role * 50;
    const int grp  = bid / 25;
    const int ublk = bid - grp * 25;
    const int gb0  = grp * 128;
    const int u0   = ublk * 8;
    const int barid = role * 2 + grp;

    const float* whh = role ? whh2 : whh1;
    unsigned* hsout = role ? hs2 : hs1;
    unsigned* flag = &g_l1prog[grp][ublk];

    // ---- stage recurrent weight slices: col c = gate*8+ul, packed bf16 ----
    for (int i = 0; i < 13; ++i) {
        int lin = tid + 256 * i;                      // 32 * 104 = 3328 words
        if (lin < 3328) {
            int c = lin / 104, rem = lin - c * 104;
            int kb2 = rem >> 3, w = rem & 7;
            int kl = (w & 1) ? (w + 7) : w;
            int k0 = kb2 * 16 + kl;
            int grow = (c >> 3) * H_ + u0 + (c & 7);
            const float* wr_ = whh + (size_t)grow * H_;
            float v0 = (k0     < H_) ? wr_[k0]     : 0.f;
            float v1 = (k0 + 1 < H_) ? wr_[k0 + 1] : 0.f;
            w_su[c * 104 + kb2 * 8 + w] = bf2(v0, v1);
            if (!role) {
                const float* w2r = wih2 + (size_t)grow * H_;
                float u0v = (k0     < H_) ? w2r[k0]     : 0.f;
                float u1v = (k0 + 1 < H_) ? w2r[k0 + 1] : 0.f;
                w2_su[c * 104 + kb2 * 8 + w] = bf2(u0v, u1v);
            }
        }
    }
    // ---- stage w_ih1 slice (L1 only): 32 cols x 80 words, stride 88 ----
    if (!role) {
        for (int i = 0; i < 10; ++i) {
            int lin = tid + 256 * i;                  // 32 * 80 = 2560 words
            if (lin < 2560) {
                int c = lin / 80, rem = lin - c * 80;
                int kb2 = rem >> 3, w = rem & 7;
                int kl = (w & 1) ? (w + 7) : w;
                int k0 = kb2 * 16 + kl;
                int grow = (c >> 3) * H_ + u0 + (c & 7);
                const float* w1r = wih1 + (size_t)grow * I_;
                float v0 = (k0     < I_) ? w1r[k0]     : 0.f;
                float v1 = (k0 + 1 < I_) ? w1r[k0 + 1] : 0.f;
                w1_su[c * 88 + kb2 * 8 + w] = bf2(v0, v1);
            }
        }
    }

    // L2 bias fold for xg2 writes (L1 role only)
    const int nc0 = (wn * 2 + 0) * H_ + u0 + tg * 2;
    const int nc1 = (wn * 2 + 1) * H_ + u0 + tg * 2;
    float bf00 = 0.f, bf01 = 0.f, bf10 = 0.f, bf11 = 0.f;
    if (!role) {
        bf00 = bi2[nc0] + bh2[nc0];     bf01 = bi2[nc0 + 1] + bh2[nc0 + 1];
        bf10 = bi2[nc1] + bh2[nc1];     bf11 = bi2[nc1 + 1] + bh2[nc1 + 1];
    }

    // epilogue ownership: 1 batch x 4 units per thread
    const int eb  = tid >> 1;              // 0..127
    const int eul = (tid & 1) * 4;         // 0 or 4
    float cc0 = 0.f, cc1 = 0.f, cc2 = 0.f, cc3 = 0.f;
    const int ug = u0 + eul;
    const int jg = ug >> 4;
    const int rr = ug & 15;
    const int p0 = rr >> 1;
    const int wo0 = (p0     < 4) ? 2 * p0       : 2 * (p0 - 4) + 1;
    const int wo1 = (p0 + 1 < 4) ? 2 * (p0 + 1) : 2 * (p0 - 3) + 1;

    // L1 gate biases (constant per thread): 4 units x 4 gates
    float4 bq0, bq1, bq2, bq3;
    if (!role) {
        const float* bA = bi1; const float* bB = bh1;
        bq0 = make_float4(bA[0*H_+ug]+bB[0*H_+ug], bA[0*H_+ug+1]+bB[0*H_+ug+1],
                          bA[0*H_+ug+2]+bB[0*H_+ug+2], bA[0*H_+ug+3]+bB[0*H_+ug+3]);
        bq1 = make_float4(bA[1*H_+ug]+bB[1*H_+ug], bA[1*H_+ug+1]+bB[1*H_+ug+1],
                          bA[1*H_+ug+2]+bB[1*H_+ug+2], bA[1*H_+ug+3]+bB[1*H_+ug+3]);
        bq2 = make_float4(bA[2*H_+ug]+bB[2*H_+ug], bA[2*H_+ug+1]+bB[2*H_+ug+1],
                          bA[2*H_+ug+2]+bB[2*H_+ug+2], bA[2*H_+ug+3]+bB[2*H_+ug+3]);
        bq3 = make_float4(bA[3*H_+ug]+bB[3*H_+ug], bA[3*H_+ug+1]+bB[3*H_+ug+1],
                          bA[3*H_+ug+2]+bB[3*H_+ug+2], bA[3*H_+ug+3]+bB[3*H_+ug+3]);
    }

    const uint32_t* hA  = h_su + (wm * 32 + g4) * 104 + tg * 2;
    const uint32_t* xA  = xt_su + (wm * 32 + g4) * 88 + tg * 2;
    const uint32_t* wB0 = w_su + (wn * 16 + g4) * 104 + tg * 2;
    const uint32_t* wB1 = wB0 + 8 * 104;
    const uint32_t* vB0 = w2_su + (wn * 16 + g4) * 104 + tg * 2;
    const uint32_t* vB1 = vB0 + 8 * 104;
    const uint32_t* uB0 = w1_su + (wn * 16 + g4) * 88 + tg * 2;
    const uint32_t* uB1 = uB0 + 8 * 88;
    const int rowM = gb0 + wm * 32 + g4;
    const uint32_t h_su32  = (uint32_t)__cvta_generic_to_shared(h_su);
    const uint32_t xt_su32 = (uint32_t)__cvta_generic_to_shared(xt_su);

    const int TEND = role ? T_ : T_ + 1;

    for (int t = 0; t < TEND; ++t) {
        const bool tail = (!role && t == T_);

        // L1: prefetch xt(t) tile BEFORE the waits (no recurrence dependency)
        if (!role && !tail) {
            const uint4* src = (const uint4*)(xtb + ((size_t)t * B_ + gb0) * XPW_);
#pragma unroll
            for (int i = 0; i < 10; ++i) {
                int lin = tid + 256 * i;               // 128*20 = 2560
                int row = lin / 20, rem = lin - row * 20;
                cpasync16(xt_su32 + (row * 88 + rem * 4) * 4, src + row * 20 + rem);
            }
            asm volatile("cp.async.commit_group;" ::: "memory");
        }

        // ---- decentralized barrier: acquire-poll peer epochs (+ prog for L2) ----
        if (t > 0) {
            if (warp == 0) {
                if (lane < 25) {
                    const unsigned* f = &g_arr[barid][lane];
                    while (ld_acquire_gpu(f) < (unsigned)t) { __nanosleep(32); }
                }
                if (role && lane == 25) {
                    while (ld_acquire_gpu(flag) < (unsigned)(t + 1)) { __nanosleep(32); }
                }
            }
            __syncthreads();
        } else if (role) {
            if (tid == 0) {
                while (ld_acquire_gpu(flag) < 1u) { __nanosleep(32); }
            }
            __syncthreads();
        }

        // L2: load xg2(t) after the wait (includes all biases)
        float4 q0, q1, q2, q3;
        if (role) {
            const float* xr = xg2 + ((size_t)t * B_ + gb0 + eb) * G_ + u0 + eul;
            q0 = *(const float4*)(xr);
            q1 = *(const float4*)(xr + H_);
            q2 = *(const float4*)(xr + 2 * H_);
            q3 = *(const float4*)(xr + 3 * H_);
        } else {
            q0 = bq0; q1 = bq1; q2 = bq2; q3 = bq3;
        }

        // stage h(t-1): 128 packed bf16 rows
        if (t == 0) {
            uint4 z = make_uint4(0u, 0u, 0u, 0u);
            for (int lin = tid; lin < 3328; lin += 256)
                ((uint4*)h_su)[lin] = z;
        } else {
            const uint4* src = (const uint4*)(hsout + ((size_t)(t - 1) * B_ + gb0) * HPW_);
#pragma unroll
            for (int i = 0; i < 13; ++i) {
                int lin = tid + 256 * i;               // 128*26 = 3328
                int row = lin / 26, rem = lin - row * 26;
                cpasync16(h_su32 + (row * 104 + rem * 4) * 4, src + row * 26 + rem);
            }
            asm volatile("cp.async.commit_group;" ::: "memory");
        }
        asm volatile("cp.async.wait_group 0;" ::: "memory");  // xt + h both done
        __syncthreads();

        // MMA: acc = xt(t)@wih1 (L1) + h(t-1)@whh; xac = h(t-1)@wih2 (L1 fused)
        float acc[2][2][4] = {};
        float xac[2][2][4] = {};
        if (!role && !tail) {
#pragma unroll
            for (int kb2 = 0; kb2 < 10; ++kb2) {
                uint2 r0 = *(const uint2*)(xA + kb2 * 8);
                uint2 r1 = *(const uint2*)(xA + kb2 * 8 + 8 * 88);
                uint2 r2 = *(const uint2*)(xA + kb2 * 8 + 16 * 88);
                uint2 r3 = *(const uint2*)(xA + kb2 * 8 + 24 * 88);
                uint32_t a0[4] = {r0.x, r1.x, r0.y, r1.y};
                uint32_t a1[4] = {r2.x, r3.x, r2.y, r3.y};
                uint2 bb0 = *(const uint2*)(uB0 + kb2 * 8);
                uint2 bb1 = *(const uint2*)(uB1 + kb2 * 8);
                uint32_t b0[2] = {bb0.x, bb0.y};
                uint32_t b1[2] = {bb1.x, bb1.y};
                mma_bf16(acc[0][0], a0, b0);
                mma_bf16(acc[1][0], a1, b0);
                mma_bf16(acc[0][1], a0, b1);
                mma_bf16(acc[1][1], a1, b1);
            }
        }
#pragma unroll
        for (int kb2 = 0; kb2 < 13; ++kb2) {
            uint2 r0 = *(const uint2*)(hA + kb2 * 8);
            uint2 r1 = *(const uint2*)(hA + kb2 * 8 + 8 * 104);
            uint2 r2 = *(const uint2*)(hA + kb2 * 8 + 16 * 104);
            uint2 r3 = *(const uint2*)(hA + kb2 * 8 + 24 * 104);
            uint32_t a0[4] = {r0.x, r1.x, r0.y, r1.y};
            uint32_t a1[4] = {r2.x, r3.x, r2.y, r3.y};
            if (!tail) {
                uint2 bb0 = *(const uint2*)(wB0 + kb2 * 8);
                uint2 bb1 = *(const uint2*)(wB1 + kb2 * 8);
                uint32_t b0[2] = {bb0.x, bb0.y};
                uint32_t b1[2] = {bb1.x, bb1.y};
                mma_bf16(acc[0][0], a0, b0);
                mma_bf16(acc[1][0], a1, b0);
                mma_bf16(acc[0][1], a0, b1);
                mma_bf16(acc[1][1], a1, b1);
            }
            if (!role && t > 0) {
                uint2 vv0 = *(const uint2*)(vB0 + kb2 * 8);
                uint2 vv1 = *(const uint2*)(vB1 + kb2 * 8);
                uint32_t v0[2] = {vv0.x, vv0.y};
                uint32_t v1[2] = {vv1.x, vv1.y};
                mma_bf16(xac[0][0], a0, v0);
                mma_bf16(xac[1][0], a1, v0);
                mma_bf16(xac[0][1], a0, v1);
                mma_bf16(xac[1][1], a1, v1);
            }
        }

        // L1: write xg2(t-1) with L2 biases folded
        if (!role && t > 0) {
#pragma unroll
            for (int mf = 0; mf < 2; ++mf) {
                float* xo = xg2 + ((size_t)(t - 1) * B_ + rowM + mf * 16) * G_;
                __stcg((float2*)(xo + nc0),          make_float2(xac[mf][0][0] + bf00, xac[mf][0][1] + bf01));
                __stcg((float2*)(xo + nc1),          make_float2(xac[mf][1][0] + bf10, xac[mf][1][1] + bf11));
                __stcg((float2*)(xo + 8 * G_ + nc0), make_float2(xac[mf][0][2] + bf00, xac[mf][0][3] + bf01));
                __stcg((float2*)(xo + 8 * G_ + nc1), make_float2(xac[mf][1][2] + bf10, xac[mf][1][3] + bf11));
            }
        }
        if (tail) {
            __syncthreads();               // all xg2(599) stores done
            if (tid == 0) st_release_gpu(flag, (unsigned)t);   // prog = 600
            break;
        }

        // accumulators -> g_s (stride 40)
#pragma unroll
        for (int mf = 0; mf < 2; ++mf) {
            float* d0 = g_s + (wm * 32 + mf * 16 + g4) * 40 + wn * 16 + tg * 2;
            *(float2*)(d0)              = make_float2(acc[mf][0][0], acc[mf][0][1]);
            *(float2*)(d0 + 8)          = make_float2(acc[mf][1][0], acc[mf][1][1]);
            *(float2*)(d0 + 8 * 40)     = make_float2(acc[mf][0][2], acc[mf][0][3]);
            *(float2*)(d0 + 8 * 40 + 8) = make_float2(acc[mf][1][2], acc[mf][1][3]);
        }
        __syncthreads();
        if (!role && t > 0 && tid == 0)
            st_release_gpu(flag, (unsigned)t);     // xg2(0..t-1) published

        // gates + cell update: 1 batch x 4 units per thread
        {
            const float* gr = g_s + eb * 40 + eul;
            float iv, fv, gv, ov, h0, h1, h2, h3;
            iv = sigmf(gr[0] + q0.x);  fv = sigmf(gr[8] + q1.x);
            gv = tanh_fast(gr[16] + q2.x); ov = sigmf(gr[24] + q3.x);
            cc0 = fv * cc0 + iv * gv;  h0 = ov * tanh_fast(cc0);

            iv = sigmf(gr[1] + q0.y);  fv = sigmf(gr[9] + q1.y);
            gv = tanh_fast(gr[17] + q2.y); ov = sigmf(gr[25] + q3.y);
            cc1 = fv * cc1 + iv * gv;  h1 = ov * tanh_fast(cc1);

            iv = sigmf(gr[2] + q0.z);  fv = sigmf(gr[10] + q1.z);
            gv = tanh_fast(gr[18] + q2.z); ov = sigmf(gr[26] + q3.z);
            cc2 = fv * cc2 + iv * gv;  h2 = ov * tanh_fast(cc2);

            iv = sigmf(gr[3] + q0.w);  fv = sigmf(gr[11] + q1.w);
            gv = tanh_fast(gr[19] + q2.w); ov = sigmf(gr[27] + q3.w);
            cc3 = fv * cc3 + iv * gv;  h3 = ov * tanh_fast(cc3);

            unsigned* hb = hsout + ((size_t)t * B_ + gb0 + eb) * HPW_ + jg * 8;
            __stcg(hb + wo0, bf2(h0, h1));
            __stcg(hb + wo1, bf2(h2, h3));
            if (role) {
                float* hl = h2l + ((size_t)t * B_ + gb0 + eb) * H_ + u0 + eul;
                *(float4*)hl = make_float4(h0, h1, h2, h3);
            }
        }

        // publish arrival: h(t) of this block's units is visible
        __syncthreads();
        if (tid == 0) st_release_gpu(&g_arr[barid][ublk], (unsigned)(t + 1));
    }

    // ---- drain + reset (replay-safe): legacy counter barrier per group ----
    __syncthreads();
    if (tid == 0) {
        __threadfence();
        unsigned gen = *(volatile unsigned*)&g_gen2[barid];
        if (atomicAdd(&g_cnt2[barid], 1u) == 24u) {
            atomicExch(&g_cnt2[barid], 0u);
            __threadfence();
            atomicAdd(&g_gen2[barid], 1u);
        } else {
            while (*(volatile unsigned*)&g_gen2[barid] == gen) { __nanosleep(32); }
        }
        // all group peers are past their final polls -> safe to reset own slot
        g_arr[barid][ublk] = 0u;
        if (role) *(volatile unsigned*)flag = 0u;   // consumer resets prog
    }
}

// ---------------- launch --------------------------------------------------------
extern "C" void kernel_launch(void* const* d_in, const int* in_sizes, int n_in,
                              void* d_out, int out_size)
{
    const float* x     = (const float*)d_in[0];
    const float* w_ih1 = (const float*)d_in[1];
    const float* w_hh1 = (const float*)d_in[2];
    const float* b_ih1 = (const float*)d_in[3];
    const float* b_hh1 = (const float*)d_in[4];
    const float* w_ih2 = (const float*)d_in[5];
    const float* w_hh2 = (const float*)d_in[6];
    const float* b_ih2 = (const float*)d_in[7];
    const float* b_hh2 = (const float*)d_in[8];
    const float* fc1_w = (const float*)d_in[9];
    const float* fc1_b = (const float*)d_in[10];
    const float* fc2_w = (const float*)d_in[11];
    const float* fc2_b = (const float*)d_in[12];
    float* out = (float*)d_out;

    float *xg2, *h2l, *tmp, *wp2;
    unsigned *hs1, *hs2, *xtb;
    cudaGetSymbolAddress((void**)&xg2, g_xg2);
    cudaGetSymbolAddress((void**)&xtb, g_xtb);
    cudaGetSymbolAddress((void**)&hs1, g_hs1);
    cudaGetSymbolAddress((void**)&hs2, g_hs2);
    cudaGetSymbolAddress((void**)&h2l, g_h2l);
    cudaGetSymbolAddress((void**)&tmp, g_tmp);
    cudaGetSymbolAddress((void**)&wp2, g_wp2);

    const int WAVE_SMEM = WAVE_WORDS * 4;            // 156672 B
    cudaFuncSetAttribute(lstm_wave, cudaFuncAttributeMaxDynamicSharedMemorySize, WAVE_SMEM);

    const int GEMM_SMEM = 2 * TB2 * (int)sizeof(float);  // 73728
    cudaFuncSetAttribute((const void*)gemm_tc<1>, cudaFuncAttributeMaxDynamicSharedMemorySize, GEMM_SMEM);
    cudaFuncSetAttribute((const void*)gemm_tc<2>, cudaFuncAttributeMaxDynamicSharedMemorySize, GEMM_SMEM);

    const int MROWS = B_ * T_;
    const dim3 frows(3, MROWS / 128);

    // 0. pad fc2_w to [129,160]
    pad_w<<<(I_ * KP_ + 255) / 256, 256>>>(fc2_w, wp2, I_, I_);
    // 1. x -> [T*B, 160] fp32
    transpose_x<<<dim3((T_ + 31) / 32, KP_ / 32, B_), dim3(32, 8)>>>(x, tmp);
    // 2. pack xt -> bf16 MMA-word layout
    pack_xt<<<(T_ * B_ * XPW_ + 255) / 256, 256>>>(tmp, xtb);
    // 3. wavefront: L1 (xg1 fused in + xg2 fused out) + L2, overlapped
    lstm_wave<<<100, 256, WAVE_SMEM>>>(xtb, w_ih1, b_ih1, b_hh1, w_hh1,
                                       w_ih2, w_hh2, b_ih2, b_hh2,
                                       hs1, hs2, h2l, xg2);
    // 4. y1 = relu(h2 @ fc1_w^T + fc1_b) -> tmp[., 160]
    gemm_tc<1><<<frows, 256, GEMM_SMEM>>>(h2l, H_, fc1_w, H_, fc1_b, tmp, H_, I_, KP_);
    // 5. out = sigmoid(y1 @ wp2^T + fc2_b), transposed store to [B,129,T]
    gemm_tc<2><<<frows, 256, GEMM_SMEM>>>(tmp, KP_, wp2, KP_, fc2_b, out, KP_, I_, 0);
}

// round 14
// speedup vs baseline: 3.4233x; 1.1982x over previous
#include <cuda_runtime.h>
#include <cstdint>
#include <cstdio>

#define B_   256
#define T_   600
#define I_   129
#define H_   200
#define G_   800   // 4*H
#define KP_  160   // padded K for the I=129 operands
#define HPW_ 104   // packed bf16 h row: 13 kb2-groups * 8 uint32 words
#define XPW_ 80    // packed bf16 xt row: 10 kb2-groups * 8 words

// smem word offsets for the wave kernel
#define OFF_WHH  0        // 32*104
#define OFF_WIH2 3328     // 32*104
#define OFF_WIH1 6656     // 32*88 (stride 88, 80 used)
#define OFF_H    9472     // 128*104
#define OFF_XT   22784    // 128*88
#define OFF_GS   34048    // 128*40 floats
#define WAVE_WORDS 39168  // total words (156672 B)

// ---------------- scratch (device globals; no cudaMalloc allowed) ----------------
__device__ float    g_xg2[(size_t)T_ * B_ * G_];     // xg2 (with biases, from L1)
__device__ unsigned g_xtb[(size_t)T_ * B_ * XPW_];   // packed bf16 xt (49 MB)
__device__ unsigned g_hs1[(size_t)T_ * B_ * HPW_];   // packed bf16 h, layer 1
__device__ unsigned g_hs2[(size_t)T_ * B_ * HPW_];   // packed bf16 h, layer 2
__device__ float    g_h2l[(size_t)T_ * B_ * H_];     // linear fp32 h2 (for fc1)
__device__ float    g_tmp[(size_t)T_ * B_ * KP_];    // xt fp32, later y1 (stride 160)
__device__ float    g_wp2[I_ * KP_];                 // fc2_w padded to [129,160]

// legacy counter barrier (only used for the end-of-kernel drain/reset)
__device__ unsigned g_cnt2[4] = {0, 0, 0, 0};
__device__ unsigned g_gen2[4] = {0, 0, 0, 0};
// per-step arrival epochs: [barid][block]; value = completed step + 1
__device__ unsigned g_arr[4][25];
// L1 -> L2 progress flags (completed L1 xg2 step; reset by consumer at end)
__device__ unsigned g_l1prog[2][25];

// ---------------- fast activations ----------------
__device__ __forceinline__ float sigmf(float x) {
    return __fdividef(1.f, 1.f + __expf(-x));
}
__device__ __forceinline__ float tanh_fast(float x) {
    float e = __expf(2.f * x);
    return 1.f - __fdividef(2.f, e + 1.f);
}

// ---------------- tf32 / bf16 helpers ----------------
__device__ __forceinline__ uint32_t f2tf32(float x) {
    uint32_t r;
    asm("cvt.rna.tf32.f32 %0, %1;" : "=r"(r) : "f"(x));
    return r;
}
__device__ __forceinline__ float tfhi(float v) { return __uint_as_float(f2tf32(v)); }
__device__ __forceinline__ uint32_t fu(float v) { return __float_as_uint(v); }

// bf16x2 with element0 = a (lower half), element1 = b
__device__ __forceinline__ uint32_t bf2(float a, float b) {
    uint32_t r;
    asm("cvt.rn.bf16x2.f32 %0, %1, %2;" : "=r"(r) : "f"(b), "f"(a));
    return r;
}

// scoped release/acquire for the flag protocol
__device__ __forceinline__ void st_release_gpu(unsigned* p, unsigned v) {
    asm volatile("st.release.gpu.u32 [%0], %1;" :: "l"(p), "r"(v) : "memory");
}
__device__ __forceinline__ unsigned ld_acquire_gpu(const unsigned* p) {
    unsigned v;
    asm volatile("ld.acquire.gpu.u32 %0, [%1];" : "=r"(v) : "l"(p) : "memory");
    return v;
}

__device__ __forceinline__ void mma_tf32(float* d, const uint32_t* a, const uint32_t* b) {
    asm volatile(
        "mma.sync.aligned.m16n8k8.row.col.f32.tf32.tf32.f32 "
        "{%0,%1,%2,%3}, {%4,%5,%6,%7}, {%8,%9}, {%0,%1,%2,%3};"
        : "+f"(d[0]), "+f"(d[1]), "+f"(d[2]), "+f"(d[3])
        : "r"(a[0]), "r"(a[1]), "r"(a[2]), "r"(a[3]), "r"(b[0]), "r"(b[1]));
}
__device__ __forceinline__ void mma_bf16(float* d, const uint32_t* a, const uint32_t* b) {
    asm volatile(
        "mma.sync.aligned.m16n8k16.row.col.f32.bf16.bf16.f32 "
        "{%0,%1,%2,%3}, {%4,%5,%6,%7}, {%8,%9}, {%0,%1,%2,%3};"
        : "+f"(d[0]), "+f"(d[1]), "+f"(d[2]), "+f"(d[3])
        : "r"(a[0]), "r"(a[1]), "r"(a[2]), "r"(a[3]), "r"(b[0]), "r"(b[1]));
}

__device__ __forceinline__ void cpasync16(uint32_t dst, const void* src) {
    asm volatile("cp.async.cg.shared.global [%0], [%1], 16;" :: "r"(dst), "l"(src));
}

// interleaved 8-k split for the 3xTF32 GEMMs
__device__ __forceinline__ void split8(float4 p0, float4 p1, float4 q[4])
{
    float h0 = tfhi(p0.x), h1 = tfhi(p0.y), h2 = tfhi(p0.z), h3 = tfhi(p0.w);
    float g0 = tfhi(p1.x), g1 = tfhi(p1.y), g2 = tfhi(p1.z), g3 = tfhi(p1.w);
    q[0] = make_float4(h0, g0, tfhi(p0.x - h0), tfhi(p1.x - g0));
    q[1] = make_float4(h1, g1, tfhi(p0.y - h1), tfhi(p1.y - g1));
    q[2] = make_float4(h2, g2, tfhi(p0.z - h2), tfhi(p1.z - g2));
    q[3] = make_float4(h3, g3, tfhi(p0.w - h3), tfhi(p1.w - g3));
}

// ---------------- weight padding ----------------
__global__ void pad_w(const float* __restrict__ w, float* __restrict__ wp, int N, int K)
{
    int i = blockIdx.x * 256 + threadIdx.x;
    if (i < N * KP_) {
        int n = i / KP_, k = i - n * KP_;
        wp[i] = (k < K) ? w[(size_t)n * K + k] : 0.f;
    }
}

// ---------------- transpose x [B,I,T] -> xt [(t*B+b), 160] ----------------
__global__ void transpose_x(const float* __restrict__ x, float* __restrict__ xt)
{
    __shared__ float sm[32][33];
    const int b  = blockIdx.z;
    const int i0 = blockIdx.y * 32;
    const int t0 = blockIdx.x * 32;
    const int tx = threadIdx.x, ty = threadIdx.y;
#pragma unroll
    for (int s = 0; s < 32; s += 8) {
        int i = i0 + ty + s, t = t0 + tx;
        sm[ty + s][tx] = (i < I_ && t < T_) ? x[((size_t)b * I_ + i) * T_ + t] : 0.f;
    }
    __syncthreads();
#pragma unroll
    for (int s = 0; s < 32; s += 8) {
        int t = t0 + ty + s, i = i0 + tx;
        if (t < T_ && i < KP_)
            xt[((size_t)t * B_ + b) * KP_ + i] = sm[tx][ty + s];
    }
}

// ---------------- pack xt fp32 [row,160] -> bf16 words [row,80] (MMA layout) -----
__global__ void pack_xt(const float* __restrict__ xt, unsigned* __restrict__ xtb)
{
    int i = blockIdx.x * 256 + threadIdx.x;          // word index
    if (i < T_ * B_ * XPW_) {
        int row = i / XPW_, rem = i - row * XPW_;
        int kb2 = rem >> 3, w = rem & 7;
        int kl = (w & 1) ? (w + 7) : w;              // pair-interleaved layout
        int k0 = kb2 * 16 + kl;
        const float* p = xt + (size_t)row * KP_ + k0;
        xtb[i] = bf2(p[0], p[1]);
    }
}

// ---------------- GEMM (3xTF32, ktile 16, double-buffered, 2 CTA/SM) -------------
#define TB2 9216

__device__ __forceinline__ void ld_regs(
    const float* __restrict__ A, int ldA,
    const float* __restrict__ W, int ldW,
    int m0, int n0, int N, int K, int kt, int tid,
    float4 ra[2], float4 rw[2])
{
    const float4 z = make_float4(0.f, 0.f, 0.f, 0.f);
    const int row = tid >> 1, kbl = tid & 1;
    int k = kt * 16 + kbl * 8;
    if (k + 8 <= K) {
        const float* p = A + (size_t)(m0 + row) * ldA + k;
        ra[0] = *(const float4*)p;
        ra[1] = *(const float4*)(p + 4);
    } else { ra[0] = z; ra[1] = z; }
    if (tid < 128) {
        int wr = tid >> 1;
        if (k + 8 <= K && n0 + wr < N) {
            const float* p = W + (size_t)(n0 + wr) * ldW + k;
            rw[0] = *(const float4*)p;
            rw[1] = *(const float4*)(p + 4);
        } else { rw[0] = z; rw[1] = z; }
    }
}

__device__ __forceinline__ void st_smem(float* buf, int tid, float4 ra[2], float4 rw[2])
{
    const int row = tid >> 1, kbl = tid & 1;
    {
        float4 q[4];
        split8(ra[0], ra[1], q);
        float4* da = (float4*)(buf + row * 48 + kbl * 16);
        int rot = row & 3;
#pragma unroll
        for (int j = 0; j < 4; ++j) { int jj = (rot + j) & 3; da[jj] = q[jj]; }
    }
    if (tid < 128) {
        int wr = tid >> 1;
        float4 q[4];
        split8(rw[0], rw[1], q);
        float4* dw = (float4*)(buf + 6144 + wr * 48 + kbl * 16);
        int rot = wr & 3;
#pragma unroll
        for (int j = 0; j < 4; ++j) { int jj = (rot + j) & 3; dw[jj] = q[jj]; }
    }
}

__device__ __forceinline__ void mma_tile16(const float* buf, int wm, int wn,
                                           int g4, int tg, float acc[2][4][4])
{
    const float* Sw = buf + 6144;
#pragma unroll
    for (int kk = 0; kk < 2; ++kk) {
        int koff = kk * 16 + tg * 4;
        uint32_t ah[2][4], al[2][4];
#pragma unroll
        for (int mf = 0; mf < 2; ++mf) {
            const float* pa = buf + (wm * 32 + mf * 16 + g4) * 48 + koff;
            float4 A0 = *(const float4*)pa;
            float4 A1 = *(const float4*)(pa + 8 * 48);
            ah[mf][0] = fu(A0.x); ah[mf][1] = fu(A1.x);
            ah[mf][2] = fu(A0.y); ah[mf][3] = fu(A1.y);
            al[mf][0] = fu(A0.z); al[mf][1] = fu(A1.z);
            al[mf][2] = fu(A0.w); al[mf][3] = fu(A1.w);
        }
#pragma unroll
        for (int nf = 0; nf < 4; ++nf) {
            const float* pb = Sw + (wn * 32 + nf * 8 + g4) * 48 + koff;
            float4 Bv = *(const float4*)pb;
            uint32_t bh[2] = {fu(Bv.x), fu(Bv.y)};
            uint32_t bl[2] = {fu(Bv.z), fu(Bv.w)};
            mma_tf32(acc[0][nf], ah[0], bh);
            mma_tf32(acc[0][nf], ah[0], bl);
            mma_tf32(acc[0][nf], al[0], bh);
            mma_tf32(acc[1][nf], ah[1], bh);
            mma_tf32(acc[1][nf], ah[1], bl);
            mma_tf32(acc[1][nf], al[1], bh);
        }
    }
}

template <int MODE>
__global__ void __launch_bounds__(256, 2) gemm_tc(
    const float* __restrict__ A, int ldA,
    const float* __restrict__ W, int ldW,
    const float* __restrict__ bias,
    float* __restrict__ out, int K, int N, int ldOut)
{
    extern __shared__ float sm[];
    const int tid  = threadIdx.x;
    const int warp = tid >> 5, lane = tid & 31;
    const int wm = warp >> 1, wn = warp & 1;
    const int g4 = lane >> 2, tg = lane & 3;
    const int m0 = blockIdx.y * 128;
    const int n0 = blockIdx.x * 64;

    float acc[2][4][4] = {};
    float4 ra[2], rw[2];

    const int ktiles = (K + 15) >> 4;

    ld_regs(A, ldA, W, ldW, m0, n0, N, K, 0, tid, ra, rw);
    st_smem(sm, tid, ra, rw);
    __syncthreads();

    for (int kt = 0; kt < ktiles; ++kt) {
        if (kt + 1 < ktiles)
            ld_regs(A, ldA, W, ldW, m0, n0, N, K, kt + 1, tid, ra, rw);
        mma_tile16(sm + (kt & 1) * TB2, wm, wn, g4, tg, acc);
        if (kt + 1 < ktiles)
            st_smem(sm + ((kt + 1) & 1) * TB2, tid, ra, rw);
        __syncthreads();
    }

#pragma unroll
    for (int mf = 0; mf < 2; ++mf) {
        int m_a = m0 + wm * 32 + mf * 16 + g4;
#pragma unroll
        for (int nf = 0; nf < 4; ++nf) {
            int n = n0 + wn * 32 + nf * 8 + tg * 2;
#pragma unroll
            for (int half = 0; half < 2; ++half) {
                int m = m_a + half * 8;
                float v0 = acc[mf][nf][half * 2 + 0];
                float v1 = acc[mf][nf][half * 2 + 1];
                if (MODE == 1) {
                    if (n < KP_) {
                        float2 o;
                        o.x = (n     < N) ? fmaxf(v0 + bias[n], 0.f)     : 0.f;
                        o.y = (n + 1 < N) ? fmaxf(v1 + bias[n + 1], 0.f) : 0.f;
                        *(float2*)(out + (size_t)m * ldOut + n) = o;
                    }
                } else {
                    int tt = m >> 8, b = m & 255;
                    if (n < N)
                        out[((size_t)b * I_ + n) * T_ + tt] = sigmf(v0 + bias[n]);
                    if (n + 1 < N)
                        out[((size_t)b * I_ + n + 1) * T_ + tt] = sigmf(v1 + bias[n + 1]);
                }
            }
        }
    }
}

// ---------------- wavefront LSTM (bf16, latency-reordered critical path) --------
// 100 blocks: blockIdx < 50 -> layer 1, else layer 2 (runs behind via prog flags).
// Per layer: 2 batch groups x 128 batches, 25 unit-blocks (8 units = 32 gate cols).
// Critical-path ordering (L1): barrier -> stage h (cp.async) overlapped with xt
// MMAs (xt committed as its own group) -> h MMAs -> epilogue -> publish h(t);
// the xg2 production (xac MMAs + stores + prog release) is DEFERRED after the
// publish -- L2 consumes it a step later, so it has slack.
__global__ void __launch_bounds__(256, 1) lstm_wave(
    const unsigned* __restrict__ xtb,
    const float* __restrict__ wih1, const float* __restrict__ bi1,
    const float* __restrict__ bh1,  const float* __restrict__ whh1,
    const float* __restrict__ wih2, const float* __restrict__ whh2,
    const float* __restrict__ bi2,  const float* __restrict__ bh2,
    unsigned* __restrict__ hs1, unsigned* __restrict__ hs2,
    float* __restrict__ h2l, float* __restrict__ xg2)
{
    extern __shared__ uint32_t smu[];
    uint32_t* w_su  = smu + OFF_WHH;
    uint32_t* w2_su = smu + OFF_WIH2;
    uint32_t* w1_su = smu + OFF_WIH1;
    uint32_t* h_su  = smu + OFF_H;
    uint32_t* xt_su = smu + OFF_XT;
    float*    g_s   = (float*)(smu + OFF_GS);

    const int tid  = threadIdx.x;
    const int warp = tid >> 5, lane = tid & 31;
    const int g4 = lane >> 2, tg = lane & 3;
    const int wm = warp >> 1;              // 0..3 -> rows wm*32..+31
    const int wn = warp & 1;               // 0..1 -> cols wn*16..+15

    const int role = (blockIdx.x >= 50);
    const int bid  = blockIdx.x - role * 50;
    const int grp  = bid / 25;
    const int ublk = bid - grp * 25;
    const int gb0  = grp * 128;
    const int u0   = ublk * 8;
    const int barid = role * 2 + grp;

    const float* whh = role ? whh2 : whh1;
    unsigned* hsout = role ? hs2 : hs1;
    unsigned* flag = &g_l1prog[grp][ublk];

    // ---- stage recurrent weight slices: col c = gate*8+ul, packed bf16 ----
    for (int i = 0; i < 13; ++i) {
        int lin = tid + 256 * i;                      // 32 * 104 = 3328 words
        if (lin < 3328) {
            int c = lin / 104, rem = lin - c * 104;
            int kb2 = rem >> 3, w = rem & 7;
            int kl = (w & 1) ? (w + 7) : w;
            int k0 = kb2 * 16 + kl;
            int grow = (c >> 3) * H_ + u0 + (c & 7);
            const float* wr_ = whh + (size_t)grow * H_;
            float v0 = (k0     < H_) ? wr_[k0]     : 0.f;
            float v1 = (k0 + 1 < H_) ? wr_[k0 + 1] : 0.f;
            w_su[c * 104 + kb2 * 8 + w] = bf2(v0, v1);
            if (!role) {
                const float* w2r = wih2 + (size_t)grow * H_;
                float u0v = (k0     < H_) ? w2r[k0]     : 0.f;
                float u1v = (k0 + 1 < H_) ? w2r[k0 + 1] : 0.f;
                w2_su[c * 104 + kb2 * 8 + w] = bf2(u0v, u1v);
            }
        }
    }
    // ---- stage w_ih1 slice (L1 only): 32 cols x 80 words, stride 88 ----
    if (!role) {
        for (int i = 0; i < 10; ++i) {
            int lin = tid + 256 * i;                  // 32 * 80 = 2560 words
            if (lin < 2560) {
                int c = lin / 80, rem = lin - c * 80;
                int kb2 = rem >> 3, w = rem & 7;
                int kl = (w & 1) ? (w + 7) : w;
                int k0 = kb2 * 16 + kl;
                int grow = (c >> 3) * H_ + u0 + (c & 7);
                const float* w1r = wih1 + (size_t)grow * I_;
                float v0 = (k0     < I_) ? w1r[k0]     : 0.f;
                float v1 = (k0 + 1 < I_) ? w1r[k0 + 1] : 0.f;
                w1_su[c * 88 + kb2 * 8 + w] = bf2(v0, v1);
            }
        }
    }

    // L2 bias fold for xg2 writes (L1 role only)
    const int nc0 = (wn * 2 + 0) * H_ + u0 + tg * 2;
    const int nc1 = (wn * 2 + 1) * H_ + u0 + tg * 2;
    float bf00 = 0.f, bf01 = 0.f, bf10 = 0.f, bf11 = 0.f;
    if (!role) {
        bf00 = bi2[nc0] + bh2[nc0];     bf01 = bi2[nc0 + 1] + bh2[nc0 + 1];
        bf10 = bi2[nc1] + bh2[nc1];     bf11 = bi2[nc1 + 1] + bh2[nc1 + 1];
    }

    // epilogue ownership: 1 batch x 4 units per thread
    const int eb  = tid >> 1;              // 0..127
    const int eul = (tid & 1) * 4;         // 0 or 4
    float cc0 = 0.f, cc1 = 0.f, cc2 = 0.f, cc3 = 0.f;
    const int ug = u0 + eul;
    const int jg = ug >> 4;
    const int rr = ug & 15;
    const int p0 = rr >> 1;
    const int wo0 = (p0     < 4) ? 2 * p0       : 2 * (p0 - 4) + 1;
    const int wo1 = (p0 + 1 < 4) ? 2 * (p0 + 1) : 2 * (p0 - 3) + 1;

    // L1 gate biases (constant per thread): 4 units x 4 gates
    float4 bq0, bq1, bq2, bq3;
    if (!role) {
        const float* bA = bi1; const float* bB = bh1;
        bq0 = make_float4(bA[0*H_+ug]+bB[0*H_+ug], bA[0*H_+ug+1]+bB[0*H_+ug+1],
                          bA[0*H_+ug+2]+bB[0*H_+ug+2], bA[0*H_+ug+3]+bB[0*H_+ug+3]);
        bq1 = make_float4(bA[1*H_+ug]+bB[1*H_+ug], bA[1*H_+ug+1]+bB[1*H_+ug+1],
                          bA[1*H_+ug+2]+bB[1*H_+ug+2], bA[1*H_+ug+3]+bB[1*H_+ug+3]);
        bq2 = make_float4(bA[2*H_+ug]+bB[2*H_+ug], bA[2*H_+ug+1]+bB[2*H_+ug+1],
                          bA[2*H_+ug+2]+bB[2*H_+ug+2], bA[2*H_+ug+3]+bB[2*H_+ug+3]);
        bq3 = make_float4(bA[3*H_+ug]+bB[3*H_+ug], bA[3*H_+ug+1]+bB[3*H_+ug+1],
                          bA[3*H_+ug+2]+bB[3*H_+ug+2], bA[3*H_+ug+3]+bB[3*H_+ug+3]);
    }

    const uint32_t* hA  = h_su + (wm * 32 + g4) * 104 + tg * 2;
    const uint32_t* xA  = xt_su + (wm * 32 + g4) * 88 + tg * 2;
    const uint32_t* wB0 = w_su + (wn * 16 + g4) * 104 + tg * 2;
    const uint32_t* wB1 = wB0 + 8 * 104;
    const uint32_t* vB0 = w2_su + (wn * 16 + g4) * 104 + tg * 2;
    const uint32_t* vB1 = vB0 + 8 * 104;
    const uint32_t* uB0 = w1_su + (wn * 16 + g4) * 88 + tg * 2;
    const uint32_t* uB1 = uB0 + 8 * 88;
    const int rowM = gb0 + wm * 32 + g4;
    const uint32_t h_su32  = (uint32_t)__cvta_generic_to_shared(h_su);
    const uint32_t xt_su32 = (uint32_t)__cvta_generic_to_shared(xt_su);

    const int TEND = role ? T_ : T_ + 1;

    for (int t = 0; t < TEND; ++t) {
        const bool tail = (!role && t == T_);

        // L1: prefetch xt(t) tile BEFORE the waits (own cp.async group)
        if (!role && !tail) {
            const uint4* src = (const uint4*)(xtb + ((size_t)t * B_ + gb0) * XPW_);
#pragma unroll
            for (int i = 0; i < 10; ++i) {
                int lin = tid + 256 * i;               // 128*20 = 2560
                int row = lin / 20, rem = lin - row * 20;
                cpasync16(xt_su32 + (row * 88 + rem * 4) * 4, src + row * 20 + rem);
            }
            asm volatile("cp.async.commit_group;" ::: "memory");
        }

        // ---- decentralized barrier: acquire-poll peer epochs (+ prog for L2) ----
        if (t > 0) {
            if (warp == 0) {
                if (lane < 25) {
                    const unsigned* f = &g_arr[barid][lane];
                    while (ld_acquire_gpu(f) < (unsigned)t) { __nanosleep(32); }
                }
                if (role && lane == 25) {
                    while (ld_acquire_gpu(flag) < (unsigned)(t + 1)) { __nanosleep(32); }
                }
            }
            __syncthreads();
        } else if (role) {
            if (tid == 0) {
                while (ld_acquire_gpu(flag) < 1u) { __nanosleep(32); }
            }
            __syncthreads();
        }

        // L2: load xg2(t) after the wait (consumed only in epilogue; ILP hides it)
        float4 q0, q1, q2, q3;
        if (role) {
            const float* xr = xg2 + ((size_t)t * B_ + gb0 + eb) * G_ + u0 + eul;
            q0 = *(const float4*)(xr);
            q1 = *(const float4*)(xr + H_);
            q2 = *(const float4*)(xr + 2 * H_);
            q3 = *(const float4*)(xr + 3 * H_);
        } else {
            q0 = bq0; q1 = bq1; q2 = bq2; q3 = bq3;
        }

        // stage h(t-1): 128 packed bf16 rows (second cp.async group)
        if (t == 0) {
            uint4 z = make_uint4(0u, 0u, 0u, 0u);
            for (int lin = tid; lin < 3328; lin += 256)
                ((uint4*)h_su)[lin] = z;
        } else {
            const uint4* src = (const uint4*)(hsout + ((size_t)(t - 1) * B_ + gb0) * HPW_);
#pragma unroll
            for (int i = 0; i < 13; ++i) {
                int lin = tid + 256 * i;               // 128*26 = 3328
                int row = lin / 26, rem = lin - row * 26;
                cpasync16(h_su32 + (row * 104 + rem * 4) * 4, src + row * 26 + rem);
            }
            asm volatile("cp.async.commit_group;" ::: "memory");
        }

        float acc[2][2][4] = {};

        if (!role && !tail) {
            // wait for xt only (h group may still be in flight) -> overlap
            if (t == 0) { asm volatile("cp.async.wait_group 0;" ::: "memory"); }
            else        { asm volatile("cp.async.wait_group 1;" ::: "memory"); }
            __syncthreads();
#pragma unroll
            for (int kb2 = 0; kb2 < 10; ++kb2) {
                uint2 r0 = *(const uint2*)(xA + kb2 * 8);
                uint2 r1 = *(const uint2*)(xA + kb2 * 8 + 8 * 88);
                uint2 r2 = *(const uint2*)(xA + kb2 * 8 + 16 * 88);
                uint2 r3 = *(const uint2*)(xA + kb2 * 8 + 24 * 88);
                uint32_t a0[4] = {r0.x, r1.x, r0.y, r1.y};
                uint32_t a1[4] = {r2.x, r3.x, r2.y, r3.y};
                uint2 bb0 = *(const uint2*)(uB0 + kb2 * 8);
                uint2 bb1 = *(const uint2*)(uB1 + kb2 * 8);
                uint32_t b0[2] = {bb0.x, bb0.y};
                uint32_t b1[2] = {bb1.x, bb1.y};
                mma_bf16(acc[0][0], a0, b0);
                mma_bf16(acc[1][0], a1, b0);
                mma_bf16(acc[0][1], a0, b1);
                mma_bf16(acc[1][1], a1, b1);
            }
            asm volatile("cp.async.wait_group 0;" ::: "memory");
            __syncthreads();
        } else {
            asm volatile("cp.async.wait_group 0;" ::: "memory");
            __syncthreads();
        }

        if (tail) {
            // final xg2(T-1) from staged h(T-1)
            float xac[2][2][4] = {};
#pragma unroll
            for (int kb2 = 0; kb2 < 13; ++kb2) {
                uint2 r0 = *(const uint2*)(hA + kb2 * 8);
                uint2 r1 = *(const uint2*)(hA + kb2 * 8 + 8 * 104);
                uint2 r2 = *(const uint2*)(hA + kb2 * 8 + 16 * 104);
                uint2 r3 = *(const uint2*)(hA + kb2 * 8 + 24 * 104);
                uint32_t a0[4] = {r0.x, r1.x, r0.y, r1.y};
                uint32_t a1[4] = {r2.x, r3.x, r2.y, r3.y};
                uint2 vv0 = *(const uint2*)(vB0 + kb2 * 8);
                uint2 vv1 = *(const uint2*)(vB1 + kb2 * 8);
                uint32_t v0[2] = {vv0.x, vv0.y};
                uint32_t v1[2] = {vv1.x, vv1.y};
                mma_bf16(xac[0][0], a0, v0);
                mma_bf16(xac[1][0], a1, v0);
                mma_bf16(xac[0][1], a0, v1);
                mma_bf16(xac[1][1], a1, v1);
            }
#pragma unroll
            for (int mf = 0; mf < 2; ++mf) {
                float* xo = xg2 + ((size_t)(t - 1) * B_ + rowM + mf * 16) * G_;
                __stcg((float2*)(xo + nc0),          make_float2(xac[mf][0][0] + bf00, xac[mf][0][1] + bf01));
                __stcg((float2*)(xo + nc1),          make_float2(xac[mf][1][0] + bf10, xac[mf][1][1] + bf11));
                __stcg((float2*)(xo + 8 * G_ + nc0), make_float2(xac[mf][0][2] + bf00, xac[mf][0][3] + bf01));
                __stcg((float2*)(xo + 8 * G_ + nc1), make_float2(xac[mf][1][2] + bf10, xac[mf][1][3] + bf11));
            }
            __syncthreads();               // all xg2(599) stores done
            if (tid == 0) st_release_gpu(flag, (unsigned)t);   // prog = 600
            break;
        }

        // recurrence MMAs: acc += h(t-1) @ whh^T
#pragma unroll
        for (int kb2 = 0; kb2 < 13; ++kb2) {
            uint2 r0 = *(const uint2*)(hA + kb2 * 8);
            uint2 r1 = *(const uint2*)(hA + kb2 * 8 + 8 * 104);
            uint2 r2 = *(const uint2*)(hA + kb2 * 8 + 16 * 104);
            uint2 r3 = *(const uint2*)(hA + kb2 * 8 + 24 * 104);
            uint32_t a0[4] = {r0.x, r1.x, r0.y, r1.y};
            uint32_t a1[4] = {r2.x, r3.x, r2.y, r3.y};
            uint2 bb0 = *(const uint2*)(wB0 + kb2 * 8);
            uint2 bb1 = *(const uint2*)(wB1 + kb2 * 8);
            uint32_t b0[2] = {bb0.x, bb0.y};
            uint32_t b1[2] = {bb1.x, bb1.y};
            mma_bf16(acc[0][0], a0, b0);
            mma_bf16(acc[1][0], a1, b0);
            mma_bf16(acc[0][1], a0, b1);
            mma_bf16(acc[1][1], a1, b1);
        }

        // accumulators -> g_s (stride 40)
#pragma unroll
        for (int mf = 0; mf < 2; ++mf) {
            float* d0 = g_s + (wm * 32 + mf * 16 + g4) * 40 + wn * 16 + tg * 2;
            *(float2*)(d0)              = make_float2(acc[mf][0][0], acc[mf][0][1]);
            *(float2*)(d0 + 8)          = make_float2(acc[mf][1][0], acc[mf][1][1]);
            *(float2*)(d0 + 8 * 40)     = make_float2(acc[mf][0][2], acc[mf][0][3]);
            *(float2*)(d0 + 8 * 40 + 8) = make_float2(acc[mf][1][2], acc[mf][1][3]);
        }
        __syncthreads();

        // gates + cell update: 1 batch x 4 units per thread
        {
            const float* gr = g_s + eb * 40 + eul;
            float iv, fv, gv, ov, h0, h1, h2, h3;
            iv = sigmf(gr[0] + q0.x);  fv = sigmf(gr[8] + q1.x);
            gv = tanh_fast(gr[16] + q2.x); ov = sigmf(gr[24] + q3.x);
            cc0 = fv * cc0 + iv * gv;  h0 = ov * tanh_fast(cc0);

            iv = sigmf(gr[1] + q0.y);  fv = sigmf(gr[9] + q1.y);
            gv = tanh_fast(gr[17] + q2.y); ov = sigmf(gr[25] + q3.y);
            cc1 = fv * cc1 + iv * gv;  h1 = ov * tanh_fast(cc1);

            iv = sigmf(gr[2] + q0.z);  fv = sigmf(gr[10] + q1.z);
            gv = tanh_fast(gr[18] + q2.z); ov = sigmf(gr[26] + q3.z);
            cc2 = fv * cc2 + iv * gv;  h2 = ov * tanh_fast(cc2);

            iv = sigmf(gr[3] + q0.w);  fv = sigmf(gr[11] + q1.w);
            gv = tanh_fast(gr[19] + q2.w); ov = sigmf(gr[27] + q3.w);
            cc3 = fv * cc3 + iv * gv;  h3 = ov * tanh_fast(cc3);

            unsigned* hb = hsout + ((size_t)t * B_ + gb0 + eb) * HPW_ + jg * 8;
            __stcg(hb + wo0, bf2(h0, h1));
            __stcg(hb + wo1, bf2(h2, h3));
            if (role) {
                float* hl = h2l + ((size_t)t * B_ + gb0 + eb) * H_ + u0 + eul;
                *(float4*)hl = make_float4(h0, h1, h2, h3);
            }
        }

        // publish arrival ASAP: h(t) of this block's units is visible
        __syncthreads();
        if (tid == 0) st_release_gpu(&g_arr[barid][ublk], (unsigned)(t + 1));

        // ---- DEFERRED xg2 production (off the recurrence critical path) ----
        if (!role && t > 0) {
            float xac[2][2][4] = {};
#pragma unroll
            for (int kb2 = 0; kb2 < 13; ++kb2) {
                uint2 r0 = *(const uint2*)(hA + kb2 * 8);
                uint2 r1 = *(const uint2*)(hA + kb2 * 8 + 8 * 104);
                uint2 r2 = *(const uint2*)(hA + kb2 * 8 + 16 * 104);
                uint2 r3 = *(const uint2*)(hA + kb2 * 8 + 24 * 104);
                uint32_t a0[4] = {r0.x, r1.x, r0.y, r1.y};
                uint32_t a1[4] = {r2.x, r3.x, r2.y, r3.y};
                uint2 vv0 = *(const uint2*)(vB0 + kb2 * 8);
                uint2 vv1 = *(const uint2*)(vB1 + kb2 * 8);
                uint32_t v0[2] = {vv0.x, vv0.y};
                uint32_t v1[2] = {vv1.x, vv1.y};
                mma_bf16(xac[0][0], a0, v0);
                mma_bf16(xac[1][0], a1, v0);
                mma_bf16(xac[0][1], a0, v1);
                mma_bf16(xac[1][1], a1, v1);
            }
#pragma unroll
            for (int mf = 0; mf < 2; ++mf) {
                float* xo = xg2 + ((size_t)(t - 1) * B_ + rowM + mf * 16) * G_;
                __stcg((float2*)(xo + nc0),          make_float2(xac[mf][0][0] + bf00, xac[mf][0][1] + bf01));
                __stcg((float2*)(xo + nc1),          make_float2(xac[mf][1][0] + bf10, xac[mf][1][1] + bf11));
                __stcg((float2*)(xo + 8 * G_ + nc0), make_float2(xac[mf][0][2] + bf00, xac[mf][0][3] + bf01));
                __stcg((float2*)(xo + 8 * G_ + nc1), make_float2(xac[mf][1][2] + bf10, xac[mf][1][3] + bf11));
            }
            __syncthreads();               // order all threads' xg2 stores
            if (tid == 0) st_release_gpu(flag, (unsigned)t);   // xg2(0..t-1) out
        }
    }

    // ---- drain + reset (replay-safe): legacy counter barrier per group ----
    __syncthreads();
    if (tid == 0) {
        __threadfence();
        unsigned gen = *(volatile unsigned*)&g_gen2[barid];
        if (atomicAdd(&g_cnt2[barid], 1u) == 24u) {
            atomicExch(&g_cnt2[barid], 0u);
            __threadfence();
            atomicAdd(&g_gen2[barid], 1u);
        } else {
            while (*(volatile unsigned*)&g_gen2[barid] == gen) { __nanosleep(32); }
        }
        // all group peers are past their final polls -> safe to reset own slot
        g_arr[barid][ublk] = 0u;
        if (role) *(volatile unsigned*)flag = 0u;   // consumer resets prog
    }
}

// ---------------- launch --------------------------------------------------------
extern "C" void kernel_launch(void* const* d_in, const int* in_sizes, int n_in,
                              void* d_out, int out_size)
{
    const float* x     = (const float*)d_in[0];
    const float* w_ih1 = (const float*)d_in[1];
    const float* w_hh1 = (const float*)d_in[2];
    const float* b_ih1 = (const float*)d_in[3];
    const float* b_hh1 = (const float*)d_in[4];
    const float* w_ih2 = (const float*)d_in[5];
    const float* w_hh2 = (const float*)d_in[6];
    const float* b_ih2 = (const float*)d_in[7];
    const float* b_hh2 = (const float*)d_in[8];
    const float* fc1_w = (const float*)d_in[9];
    const float* fc1_b = (const float*)d_in[10];
    const float* fc2_w = (const float*)d_in[11];
    const float* fc2_b = (const float*)d_in[12];
    float* out = (float*)d_out;

    float *xg2, *h2l, *tmp, *wp2;
    unsigned *hs1, *hs2, *xtb;
    cudaGetSymbolAddress((void**)&xg2, g_xg2);
    cudaGetSymbolAddress((void**)&xtb, g_xtb);
    cudaGetSymbolAddress((void**)&hs1, g_hs1);
    cudaGetSymbolAddress((void**)&hs2, g_hs2);
    cudaGetSymbolAddress((void**)&h2l, g_h2l);
    cudaGetSymbolAddress((void**)&tmp, g_tmp);
    cudaGetSymbolAddress((void**)&wp2, g_wp2);

    const int WAVE_SMEM = WAVE_WORDS * 4;            // 156672 B
    cudaFuncSetAttribute(lstm_wave, cudaFuncAttributeMaxDynamicSharedMemorySize, WAVE_SMEM);

    const int GEMM_SMEM = 2 * TB2 * (int)sizeof(float);  // 73728
    cudaFuncSetAttribute((const void*)gemm_tc<1>, cudaFuncAttributeMaxDynamicSharedMemorySize, GEMM_SMEM);
    cudaFuncSetAttribute((const void*)gemm_tc<2>, cudaFuncAttributeMaxDynamicSharedMemorySize, GEMM_SMEM);

    const int MROWS = B_ * T_;
    const dim3 frows(3, MROWS / 128);

    // 0. pad fc2_w to [129,160]
    pad_w<<<(I_ * KP_ + 255) / 256, 256>>>(fc2_w, wp2, I_, I_);
    // 1. x -> [T*B, 160] fp32
    transpose_x<<<dim3((T_ + 31) / 32, KP_ / 32, B_), dim3(32, 8)>>>(x, tmp);
    // 2. pack xt -> bf16 MMA-word layout
    pack_xt<<<(T_ * B_ * XPW_ + 255) / 256, 256>>>(tmp, xtb);
    // 3. wavefront: L1 (xg1 fused in + deferred xg2 out) + L2, overlapped
    lstm_wave<<<100, 256, WAVE_SMEM>>>(xtb, w_ih1, b_ih1, b_hh1, w_hh1,
                                       w_ih2, w_hh2, b_ih2, b_hh2,
                                       hs1, hs2, h2l, xg2);
    // 4. y1 = relu(h2 @ fc1_w^T + fc1_b) -> tmp[., 160]
    gemm_tc<1><<<frows, 256, GEMM_SMEM>>>(h2l, H_, fc1_w, H_, fc1_b, tmp, H_, I_, KP_);
    // 5. out = sigmoid(y1 @ wp2^T + fc2_b), transposed store to [B,129,T]
    gemm_tc<2><<<frows, 256, GEMM_SMEM>>>(tmp, KP_, wp2, KP_, fc2_b, out, KP_, I_, 0);
}

// round 15
// speedup vs baseline: 3.4484x; 1.0073x over previous
#include <cuda_runtime.h>
#include <cstdint>
#include <cstdio>

#define B_   256
#define T_   600
#define I_   129
#define H_   200
#define G_   800   // 4*H
#define KP_  160   // padded K for the I=129 operands
#define HPW_ 104   // packed bf16 h row: 13 kb2-groups * 8 uint32 words
#define XPW_ 80    // packed bf16 xt row: 10 kb2-groups * 8 words

// wave-role smem word offsets
#define OFF_WHH  0        // 32*104
#define OFF_WIH2 3328     // 32*104
#define OFF_WIH1 6656     // 32*88 (stride 88, 80 used)
#define OFF_H    9472     // 128*104
#define OFF_XT   22784    // 128*88
#define OFF_GS   34048    // 128*40 floats
// FC-role layout: [0, 2*TB2) staging, y1 at 2*TB2 (128*164 floats)
#define TB2      9216
#define OFF_Y1   18432
#define SMEM_WORDS 39424  // max(wave 39168, fc 39424) -> 157696 B

// ---------------- scratch (device globals; no cudaMalloc allowed) ----------------
__device__ float    g_xg2[(size_t)T_ * B_ * G_];     // xg2 (with biases, from L1)
__device__ unsigned g_xtb[(size_t)T_ * B_ * XPW_];   // packed bf16 xt
__device__ unsigned g_hs1[(size_t)T_ * B_ * HPW_];   // packed bf16 h, layer 1
__device__ unsigned g_hs2[(size_t)T_ * B_ * HPW_];   // packed bf16 h, layer 2
__device__ float    g_h2l[(size_t)T_ * B_ * H_];     // linear fp32 h2 (for fc)
__device__ float    g_wp2[I_ * KP_];                 // fc2_w padded to [129,160]

// single end-of-kernel drain barrier (all blocks)
__device__ unsigned g_cnt = 0;
__device__ unsigned g_gen = 0;
// per-step arrival epochs: [barid][block]; value = completed step + 1
__device__ unsigned g_arr[4][25];
// L1 -> L2 progress flags (completed L1 xg2 step)
__device__ unsigned g_l1prog[2][25];

// ---------------- fast activations ----------------
__device__ __forceinline__ float sigmf(float x) {
    return __fdividef(1.f, 1.f + __expf(-x));
}
__device__ __forceinline__ float tanh_fast(float x) {
    float e = __expf(2.f * x);
    return 1.f - __fdividef(2.f, e + 1.f);
}

// ---------------- tf32 / bf16 helpers ----------------
__device__ __forceinline__ uint32_t f2tf32(float x) {
    uint32_t r;
    asm("cvt.rna.tf32.f32 %0, %1;" : "=r"(r) : "f"(x));
    return r;
}
__device__ __forceinline__ float tfhi(float v) { return __uint_as_float(f2tf32(v)); }
__device__ __forceinline__ uint32_t fu(float v) { return __float_as_uint(v); }

__device__ __forceinline__ uint32_t bf2(float a, float b) {
    uint32_t r;
    asm("cvt.rn.bf16x2.f32 %0, %1, %2;" : "=r"(r) : "f"(b), "f"(a));
    return r;
}

__device__ __forceinline__ void st_release_gpu(unsigned* p, unsigned v) {
    asm volatile("st.release.gpu.u32 [%0], %1;" :: "l"(p), "r"(v) : "memory");
}
__device__ __forceinline__ unsigned ld_acquire_gpu(const unsigned* p) {
    unsigned v;
    asm volatile("ld.acquire.gpu.u32 %0, [%1];" : "=r"(v) : "l"(p) : "memory");
    return v;
}

__device__ __forceinline__ void mma_tf32(float* d, const uint32_t* a, const uint32_t* b) {
    asm volatile(
        "mma.sync.aligned.m16n8k8.row.col.f32.tf32.tf32.f32 "
        "{%0,%1,%2,%3}, {%4,%5,%6,%7}, {%8,%9}, {%0,%1,%2,%3};"
        : "+f"(d[0]), "+f"(d[1]), "+f"(d[2]), "+f"(d[3])
        : "r"(a[0]), "r"(a[1]), "r"(a[2]), "r"(a[3]), "r"(b[0]), "r"(b[1]));
}
__device__ __forceinline__ void mma_bf16(float* d, const uint32_t* a, const uint32_t* b) {
    asm volatile(
        "mma.sync.aligned.m16n8k16.row.col.f32.bf16.bf16.f32 "
        "{%0,%1,%2,%3}, {%4,%5,%6,%7}, {%8,%9}, {%0,%1,%2,%3};"
        : "+f"(d[0]), "+f"(d[1]), "+f"(d[2]), "+f"(d[3])
        : "r"(a[0]), "r"(a[1]), "r"(a[2]), "r"(a[3]), "r"(b[0]), "r"(b[1]));
}

__device__ __forceinline__ void cpasync16(uint32_t dst, const void* src) {
    asm volatile("cp.async.cg.shared.global [%0], [%1], 16;" :: "r"(dst), "l"(src));
}

// interleaved 8-k split for the 3xTF32 FC GEMMs
__device__ __forceinline__ void split8(float4 p0, float4 p1, float4 q[4])
{
    float h0 = tfhi(p0.x), h1 = tfhi(p0.y), h2 = tfhi(p0.z), h3 = tfhi(p0.w);
    float g0 = tfhi(p1.x), g1 = tfhi(p1.y), g2 = tfhi(p1.z), g3 = tfhi(p1.w);
    q[0] = make_float4(h0, g0, tfhi(p0.x - h0), tfhi(p1.x - g0));
    q[1] = make_float4(h1, g1, tfhi(p0.y - h1), tfhi(p1.y - g1));
    q[2] = make_float4(h2, g2, tfhi(p0.z - h2), tfhi(p1.z - g2));
    q[3] = make_float4(h3, g3, tfhi(p0.w - h3), tfhi(p1.w - g3));
}

// ---------------- weight padding ----------------
__global__ void pad_w(const float* __restrict__ w, float* __restrict__ wp, int N, int K)
{
    int i = blockIdx.x * 256 + threadIdx.x;
    if (i < N * KP_) {
        int n = i / KP_, k = i - n * KP_;
        wp[i] = (k < K) ? w[(size_t)n * K + k] : 0.f;
    }
}

// ---------------- fused transpose + bf16 pack: x[B,129,T] -> xtb words ----------
__global__ void transpose_pack(const float* __restrict__ x, unsigned* __restrict__ xtb)
{
    __shared__ float sm[32][33];
    const int b  = blockIdx.z;
    const int i0 = blockIdx.y * 32;                 // 0,32,64,96,128
    const int t0 = blockIdx.x * 32;
    const int tx = threadIdx.x, ty = threadIdx.y;   // (32,8)
#pragma unroll
    for (int s = 0; s < 32; s += 8) {
        int i = i0 + ty + s, t = t0 + tx;
        sm[ty + s][tx] = (i < I_ && t < T_) ? x[((size_t)b * I_ + i) * T_ + t] : 0.f;
    }
    __syncthreads();
#pragma unroll
    for (int j = 0; j < 2; ++j) {
        int widx = (ty * 32 + tx) + 256 * j;        // 0..511
        int tl = widx >> 4, rem16 = widx & 15;
        int kb2l = rem16 >> 3, w = rem16 & 7;
        int kl = (w & 1) ? (w + 7) : w;             // pair-interleaved layout
        int il = kb2l * 16 + kl;                    // 0..30 (pairs il, il+1)
        int t = t0 + tl;
        if (t < T_) {
            unsigned v = bf2(sm[il][tl], sm[il + 1][tl]);
            xtb[((size_t)t * B_ + b) * XPW_ + (i0 >> 4) * 8 + kb2l * 8 + w] = v;
        }
    }
}

// ---------------- 3xTF32 GEMM building blocks (FC role) --------------------------
__device__ __forceinline__ void ld_regs(
    const float* __restrict__ A, int ldA,
    const float* __restrict__ W, int ldW,
    int m0, int n0, int N, int K, int kt, int tid,
    float4 ra[2], float4 rw[2])
{
    const float4 z = make_float4(0.f, 0.f, 0.f, 0.f);
    const int row = tid >> 1, kbl = tid & 1;
    int k = kt * 16 + kbl * 8;
    if (k + 8 <= K) {
        const float* p = A + (size_t)(m0 + row) * ldA + k;
        ra[0] = *(const float4*)p;
        ra[1] = *(const float4*)(p + 4);
    } else { ra[0] = z; ra[1] = z; }
    if (tid < 128) {
        int wr = tid >> 1;
        if (k + 8 <= K && n0 + wr < N) {
            const float* p = W + (size_t)(n0 + wr) * ldW + k;
            rw[0] = *(const float4*)p;
            rw[1] = *(const float4*)(p + 4);
        } else { rw[0] = z; rw[1] = z; }
    }
}

// A from smem y1 (stride 164), W from global wp2 (K=160 exact)
__device__ __forceinline__ void ld_regs_y1(
    const float* __restrict__ y1s, const float* __restrict__ W,
    int n0, int kt, int tid, float4 ra[2], float4 rw[2])
{
    const float4 z = make_float4(0.f, 0.f, 0.f, 0.f);
    const int row = tid >> 1, kbl = tid & 1;
    int k = kt * 16 + kbl * 8;
    const float* p = y1s + row * 164 + k;
    ra[0] = *(const float4*)p;
    ra[1] = *(const float4*)(p + 4);
    if (tid < 128) {
        int wr = tid >> 1;
        if (n0 + wr < I_) {
            const float* q = W + (size_t)(n0 + wr) * KP_ + k;
            rw[0] = *(const float4*)q;
            rw[1] = *(const float4*)(q + 4);
        } else { rw[0] = z; rw[1] = z; }
    }
}

__device__ __forceinline__ void st_smem(float* buf, int tid, float4 ra[2], float4 rw[2])
{
    const int row = tid >> 1, kbl = tid & 1;
    {
        float4 q[4];
        split8(ra[0], ra[1], q);
        float4* da = (float4*)(buf + row * 48 + kbl * 16);
        int rot = row & 3;
#pragma unroll
        for (int j = 0; j < 4; ++j) { int jj = (rot + j) & 3; da[jj] = q[jj]; }
    }
    if (tid < 128) {
        int wr = tid >> 1;
        float4 q[4];
        split8(rw[0], rw[1], q);
        float4* dw = (float4*)(buf + 6144 + wr * 48 + kbl * 16);
        int rot = wr & 3;
#pragma unroll
        for (int j = 0; j < 4; ++j) { int jj = (rot + j) & 3; dw[jj] = q[jj]; }
    }
}

__device__ __forceinline__ void mma_tile16(const float* buf, int wm, int wn,
                                           int g4, int tg, float acc[2][4][4])
{
    const float* Sw = buf + 6144;
#pragma unroll
    for (int kk = 0; kk < 2; ++kk) {
        int koff = kk * 16 + tg * 4;
        uint32_t ah[2][4], al[2][4];
#pragma unroll
        for (int mf = 0; mf < 2; ++mf) {
            const float* pa = buf + (wm * 32 + mf * 16 + g4) * 48 + koff;
            float4 A0 = *(const float4*)pa;
            float4 A1 = *(const float4*)(pa + 8 * 48);
            ah[mf][0] = fu(A0.x); ah[mf][1] = fu(A1.x);
            ah[mf][2] = fu(A0.y); ah[mf][3] = fu(A1.y);
            al[mf][0] = fu(A0.z); al[mf][1] = fu(A1.z);
            al[mf][2] = fu(A0.w); al[mf][3] = fu(A1.w);
        }
#pragma unroll
        for (int nf = 0; nf < 4; ++nf) {
            const float* pb = Sw + (wn * 32 + nf * 8 + g4) * 48 + koff;
            float4 Bv = *(const float4*)pb;
            uint32_t bh[2] = {fu(Bv.x), fu(Bv.y)};
            uint32_t bl[2] = {fu(Bv.z), fu(Bv.w)};
            mma_tf32(acc[0][nf], ah[0], bh);
            mma_tf32(acc[0][nf], ah[0], bl);
            mma_tf32(acc[0][nf], al[0], bh);
            mma_tf32(acc[1][nf], ah[1], bh);
            mma_tf32(acc[1][nf], ah[1], bl);
            mma_tf32(acc[1][nf], al[1], bh);
        }
    }
}

// ---------------- unified persistent kernel --------------------------------------
// grid 148: [0,50) L1 wave, [50,100) L2 wave, [100,148) FC consumers.
// L1/L2: per layer 2 batch groups x 25 unit-blocks; bf16 recurrence, deferred xg2.
// FC: polls L2 arrival epochs (read-only) and runs fc1(relu)+fc2(sigmoid, transposed
// store) for (t, grp) tiles as h2 becomes available. Single 148-block drain barrier
// at the end; owners then reset their flags (replay-safe).
__global__ void __launch_bounds__(256, 1) lstm_fused(
    const unsigned* __restrict__ xtb,
    const float* __restrict__ wih1, const float* __restrict__ bi1,
    const float* __restrict__ bh1,  const float* __restrict__ whh1,
    const float* __restrict__ wih2, const float* __restrict__ whh2,
    const float* __restrict__ bi2,  const float* __restrict__ bh2,
    unsigned* __restrict__ hs1, unsigned* __restrict__ hs2,
    float* __restrict__ h2l, float* __restrict__ xg2,
    const float* __restrict__ fc1_w, const float* __restrict__ fc1_b,
    const float* __restrict__ wp2,   const float* __restrict__ fc2_b,
    float* __restrict__ out)
{
    extern __shared__ uint32_t smu[];
    const int tid  = threadIdx.x;
    const int warp = tid >> 5, lane = tid & 31;
    const int g4 = lane >> 2, tg = lane & 3;
    const int wm = warp >> 1;
    const int wn = warp & 1;

    const int bx = blockIdx.x;
    const bool fcrole = (bx >= 100);
    int barid = 0, ublk = 0, isL2 = 0;

    if (fcrole) {
        // ================= FC role =================
        float* smf = (float*)smu;
        float* y1s = smf + OFF_Y1;          // 128 x 164
        const int fcid = bx - 100;          // 0..47

        for (int it = fcid; it < 2 * T_; it += 48) {
            const int t   = it >> 1;
            const int grp = it & 1;
            const int r0  = t * B_ + grp * 128;

            // wait until all 25 L2 blocks of this group finished step t
            if (warp == 0 && lane < 25) {
                const unsigned* f = &g_arr[2 + grp][lane];
                while (ld_acquire_gpu(f) < (unsigned)(t + 1)) { __nanosleep(64); }
            }
            __syncthreads();

            float4 ra[2], rw[2];
            // ---- fc1: y1 = relu(h2 @ fc1_w^T + b1), cols 129..159 zero ----
#pragma unroll 1
            for (int nt = 0; nt < 3; ++nt) {
                int n0 = nt * 64;
                float acc[2][4][4] = {};
                ld_regs(h2l, H_, fc1_w, H_, r0, n0, I_, H_, 0, tid, ra, rw);
                st_smem(smf, tid, ra, rw);
                __syncthreads();
#pragma unroll 1
                for (int kt = 0; kt < 13; ++kt) {
                    if (kt + 1 < 13)
                        ld_regs(h2l, H_, fc1_w, H_, r0, n0, I_, H_, kt + 1, tid, ra, rw);
                    mma_tile16(smf + (kt & 1) * TB2, wm, wn, g4, tg, acc);
                    if (kt + 1 < 13)
                        st_smem(smf + ((kt + 1) & 1) * TB2, tid, ra, rw);
                    __syncthreads();
                }
#pragma unroll
                for (int mf = 0; mf < 2; ++mf) {
                    int m_a = wm * 32 + mf * 16 + g4;
#pragma unroll
                    for (int nf = 0; nf < 4; ++nf) {
                        int n = n0 + wn * 32 + nf * 8 + tg * 2;
#pragma unroll
                        for (int half = 0; half < 2; ++half) {
                            int m = m_a + half * 8;
                            if (n < KP_) {
                                float v0 = acc[mf][nf][half * 2 + 0];
                                float v1 = acc[mf][nf][half * 2 + 1];
                                y1s[m * 164 + n]     = (n     < I_) ? fmaxf(v0 + fc1_b[n], 0.f)     : 0.f;
                                y1s[m * 164 + n + 1] = (n + 1 < I_) ? fmaxf(v1 + fc1_b[n + 1], 0.f) : 0.f;
                            }
                        }
                    }
                }
                __syncthreads();
            }

            // ---- fc2: out = sigmoid(y1 @ wp2^T + b2), transposed [B,129,T] ----
#pragma unroll 1
            for (int nt = 0; nt < 3; ++nt) {
                int n0 = nt * 64;
                float acc[2][4][4] = {};
                ld_regs_y1(y1s, wp2, n0, 0, tid, ra, rw);
                st_smem(smf, tid, ra, rw);
                __syncthreads();
#pragma unroll 1
                for (int kt = 0; kt < 10; ++kt) {
                    if (kt + 1 < 10)
                        ld_regs_y1(y1s, wp2, n0, kt + 1, tid, ra, rw);
                    mma_tile16(smf + (kt & 1) * TB2, wm, wn, g4, tg, acc);
                    if (kt + 1 < 10)
                        st_smem(smf + ((kt + 1) & 1) * TB2, tid, ra, rw);
                    __syncthreads();
                }
#pragma unroll
                for (int mf = 0; mf < 2; ++mf) {
                    int m_a = wm * 32 + mf * 16 + g4;
#pragma unroll
                    for (int nf = 0; nf < 4; ++nf) {
                        int n = n0 + wn * 32 + nf * 8 + tg * 2;
#pragma unroll
                        for (int half = 0; half < 2; ++half) {
                            int m = m_a + half * 8;
                            int b = grp * 128 + m;
                            float v0 = acc[mf][nf][half * 2 + 0];
                            float v1 = acc[mf][nf][half * 2 + 1];
                            if (n < I_)
                                out[((size_t)b * I_ + n) * T_ + t] = sigmf(v0 + fc2_b[n]);
                            if (n + 1 < I_)
                                out[((size_t)b * I_ + n + 1) * T_ + t] = sigmf(v1 + fc2_b[n + 1]);
                        }
                    }
                }
                __syncthreads();
            }
        }
    } else {
        // ================= wave roles (L1/L2) =================
        uint32_t* w_su  = smu + OFF_WHH;
        uint32_t* w2_su = smu + OFF_WIH2;
        uint32_t* w1_su = smu + OFF_WIH1;
        uint32_t* h_su  = smu + OFF_H;
        uint32_t* xt_su = smu + OFF_XT;
        float*    g_s   = (float*)(smu + OFF_GS);

        const int role = (bx >= 50);
        isL2 = role;
        const int bid  = bx - role * 50;
        const int grp  = bid / 25;
        ublk = bid - grp * 25;
        const int gb0  = grp * 128;
        const int u0   = ublk * 8;
        barid = role * 2 + grp;

        const float* whh = role ? whh2 : whh1;
        unsigned* hsout = role ? hs2 : hs1;
        unsigned* flag = &g_l1prog[grp][ublk];

        // stage recurrent weight slices: col c = gate*8+ul, packed bf16
        for (int i = 0; i < 13; ++i) {
            int lin = tid + 256 * i;
            if (lin < 3328) {
                int c = lin / 104, rem = lin - c * 104;
                int kb2 = rem >> 3, w = rem & 7;
                int kl = (w & 1) ? (w + 7) : w;
                int k0 = kb2 * 16 + kl;
                int grow = (c >> 3) * H_ + u0 + (c & 7);
                const float* wr_ = whh + (size_t)grow * H_;
                float v0 = (k0     < H_) ? wr_[k0]     : 0.f;
                float v1 = (k0 + 1 < H_) ? wr_[k0 + 1] : 0.f;
                w_su[c * 104 + kb2 * 8 + w] = bf2(v0, v1);
                if (!role) {
                    const float* w2r = wih2 + (size_t)grow * H_;
                    float u0v = (k0     < H_) ? w2r[k0]     : 0.f;
                    float u1v = (k0 + 1 < H_) ? w2r[k0 + 1] : 0.f;
                    w2_su[c * 104 + kb2 * 8 + w] = bf2(u0v, u1v);
                }
            }
        }
        if (!role) {
            for (int i = 0; i < 10; ++i) {
                int lin = tid + 256 * i;
                if (lin < 2560) {
                    int c = lin / 80, rem = lin - c * 80;
                    int kb2 = rem >> 3, w = rem & 7;
                    int kl = (w & 1) ? (w + 7) : w;
                    int k0 = kb2 * 16 + kl;
                    int grow = (c >> 3) * H_ + u0 + (c & 7);
                    const float* w1r = wih1 + (size_t)grow * I_;
                    float v0 = (k0     < I_) ? w1r[k0]     : 0.f;
                    float v1 = (k0 + 1 < I_) ? w1r[k0 + 1] : 0.f;
                    w1_su[c * 88 + kb2 * 8 + w] = bf2(v0, v1);
                }
            }
        }

        const int nc0 = (wn * 2 + 0) * H_ + u0 + tg * 2;
        const int nc1 = (wn * 2 + 1) * H_ + u0 + tg * 2;
        float bf00 = 0.f, bf01 = 0.f, bf10 = 0.f, bf11 = 0.f;
        if (!role) {
            bf00 = bi2[nc0] + bh2[nc0];     bf01 = bi2[nc0 + 1] + bh2[nc0 + 1];
            bf10 = bi2[nc1] + bh2[nc1];     bf11 = bi2[nc1 + 1] + bh2[nc1 + 1];
        }

        const int eb  = tid >> 1;
        const int eul = (tid & 1) * 4;
        float cc0 = 0.f, cc1 = 0.f, cc2 = 0.f, cc3 = 0.f;
        const int ug = u0 + eul;
        const int jg = ug >> 4;
        const int rr = ug & 15;
        const int p0 = rr >> 1;
        const int wo0 = (p0     < 4) ? 2 * p0       : 2 * (p0 - 4) + 1;
        const int wo1 = (p0 + 1 < 4) ? 2 * (p0 + 1) : 2 * (p0 - 3) + 1;

        float4 bq0, bq1, bq2, bq3;
        if (!role) {
            const float* bA = bi1; const float* bB = bh1;
            bq0 = make_float4(bA[0*H_+ug]+bB[0*H_+ug], bA[0*H_+ug+1]+bB[0*H_+ug+1],
                              bA[0*H_+ug+2]+bB[0*H_+ug+2], bA[0*H_+ug+3]+bB[0*H_+ug+3]);
            bq1 = make_float4(bA[1*H_+ug]+bB[1*H_+ug], bA[1*H_+ug+1]+bB[1*H_+ug+1],
                              bA[1*H_+ug+2]+bB[1*H_+ug+2], bA[1*H_+ug+3]+bB[1*H_+ug+3]);
            bq2 = make_float4(bA[2*H_+ug]+bB[2*H_+ug], bA[2*H_+ug+1]+bB[2*H_+ug+1],
                              bA[2*H_+ug+2]+bB[2*H_+ug+2], bA[2*H_+ug+3]+bB[2*H_+ug+3]);
            bq3 = make_float4(bA[3*H_+ug]+bB[3*H_+ug], bA[3*H_+ug+1]+bB[3*H_+ug+1],
                              bA[3*H_+ug+2]+bB[3*H_+ug+2], bA[3*H_+ug+3]+bB[3*H_+ug+3]);
        }

        const uint32_t* hA  = h_su + (wm * 32 + g4) * 104 + tg * 2;
        const uint32_t* xA  = xt_su + (wm * 32 + g4) * 88 + tg * 2;
        const uint32_t* wB0 = w_su + (wn * 16 + g4) * 104 + tg * 2;
        const uint32_t* wB1 = wB0 + 8 * 104;
        const uint32_t* vB0 = w2_su + (wn * 16 + g4) * 104 + tg * 2;
        const uint32_t* vB1 = vB0 + 8 * 104;
        const uint32_t* uB0 = w1_su + (wn * 16 + g4) * 88 + tg * 2;
        const uint32_t* uB1 = uB0 + 8 * 88;
        const int rowM = gb0 + wm * 32 + g4;
        const uint32_t h_su32  = (uint32_t)__cvta_generic_to_shared(h_su);
        const uint32_t xt_su32 = (uint32_t)__cvta_generic_to_shared(xt_su);

        const int TEND = role ? T_ : T_ + 1;

        for (int t = 0; t < TEND; ++t) {
            const bool tail = (!role && t == T_);

            if (!role && !tail) {
                const uint4* src = (const uint4*)(xtb + ((size_t)t * B_ + gb0) * XPW_);
#pragma unroll
                for (int i = 0; i < 10; ++i) {
                    int lin = tid + 256 * i;
                    int row = lin / 20, rem = lin - row * 20;
                    cpasync16(xt_su32 + (row * 88 + rem * 4) * 4, src + row * 20 + rem);
                }
                asm volatile("cp.async.commit_group;" ::: "memory");
            }

            if (t > 0) {
                if (warp == 0) {
                    if (lane < 25) {
                        const unsigned* f = &g_arr[barid][lane];
                        while (ld_acquire_gpu(f) < (unsigned)t) { __nanosleep(32); }
                    }
                    if (role && lane == 25) {
                        while (ld_acquire_gpu(flag) < (unsigned)(t + 1)) { __nanosleep(32); }
                    }
                }
                __syncthreads();
            } else if (role) {
                if (tid == 0) {
                    while (ld_acquire_gpu(flag) < 1u) { __nanosleep(32); }
                }
                __syncthreads();
            }

            float4 q0, q1, q2, q3;
            if (role) {
                const float* xr = xg2 + ((size_t)t * B_ + gb0 + eb) * G_ + u0 + eul;
                q0 = *(const float4*)(xr);
                q1 = *(const float4*)(xr + H_);
                q2 = *(const float4*)(xr + 2 * H_);
                q3 = *(const float4*)(xr + 3 * H_);
            } else {
                q0 = bq0; q1 = bq1; q2 = bq2; q3 = bq3;
            }

            if (t == 0) {
                uint4 z = make_uint4(0u, 0u, 0u, 0u);
                for (int lin = tid; lin < 3328; lin += 256)
                    ((uint4*)h_su)[lin] = z;
            } else {
                const uint4* src = (const uint4*)(hsout + ((size_t)(t - 1) * B_ + gb0) * HPW_);
#pragma unroll
                for (int i = 0; i < 13; ++i) {
                    int lin = tid + 256 * i;
                    int row = lin / 26, rem = lin - row * 26;
                    cpasync16(h_su32 + (row * 104 + rem * 4) * 4, src + row * 26 + rem);
                }
                asm volatile("cp.async.commit_group;" ::: "memory");
            }

            float acc[2][2][4] = {};

            if (!role && !tail) {
                if (t == 0) { asm volatile("cp.async.wait_group 0;" ::: "memory"); }
                else        { asm volatile("cp.async.wait_group 1;" ::: "memory"); }
                __syncthreads();
#pragma unroll
                for (int kb2 = 0; kb2 < 10; ++kb2) {
                    uint2 r0 = *(const uint2*)(xA + kb2 * 8);
                    uint2 r1 = *(const uint2*)(xA + kb2 * 8 + 8 * 88);
                    uint2 r2 = *(const uint2*)(xA + kb2 * 8 + 16 * 88);
                    uint2 r3 = *(const uint2*)(xA + kb2 * 8 + 24 * 88);
                    uint32_t a0[4] = {r0.x, r1.x, r0.y, r1.y};
                    uint32_t a1[4] = {r2.x, r3.x, r2.y, r3.y};
                    uint2 bb0 = *(const uint2*)(uB0 + kb2 * 8);
                    uint2 bb1 = *(const uint2*)(uB1 + kb2 * 8);
                    uint32_t b0[2] = {bb0.x, bb0.y};
                    uint32_t b1[2] = {bb1.x, bb1.y};
                    mma_bf16(acc[0][0], a0, b0);
                    mma_bf16(acc[1][0], a1, b0);
                    mma_bf16(acc[0][1], a0, b1);
                    mma_bf16(acc[1][1], a1, b1);
                }
                asm volatile("cp.async.wait_group 0;" ::: "memory");
                __syncthreads();
            } else {
                asm volatile("cp.async.wait_group 0;" ::: "memory");
                __syncthreads();
            }

            if (tail) {
                float xac[2][2][4] = {};
#pragma unroll
                for (int kb2 = 0; kb2 < 13; ++kb2) {
                    uint2 r0 = *(const uint2*)(hA + kb2 * 8);
                    uint2 r1 = *(const uint2*)(hA + kb2 * 8 + 8 * 104);
                    uint2 r2 = *(const uint2*)(hA + kb2 * 8 + 16 * 104);
                    uint2 r3 = *(const uint2*)(hA + kb2 * 8 + 24 * 104);
                    uint32_t a0[4] = {r0.x, r1.x, r0.y, r1.y};
                    uint32_t a1[4] = {r2.x, r3.x, r2.y, r3.y};
                    uint2 vv0 = *(const uint2*)(vB0 + kb2 * 8);
                    uint2 vv1 = *(const uint2*)(vB1 + kb2 * 8);
                    uint32_t v0[2] = {vv0.x, vv0.y};
                    uint32_t v1[2] = {vv1.x, vv1.y};
                    mma_bf16(xac[0][0], a0, v0);
                    mma_bf16(xac[1][0], a1, v0);
                    mma_bf16(xac[0][1], a0, v1);
                    mma_bf16(xac[1][1], a1, v1);
                }
#pragma unroll
                for (int mf = 0; mf < 2; ++mf) {
                    float* xo = xg2 + ((size_t)(t - 1) * B_ + rowM + mf * 16) * G_;
                    __stcg((float2*)(xo + nc0),          make_float2(xac[mf][0][0] + bf00, xac[mf][0][1] + bf01));
                    __stcg((float2*)(xo + nc1),          make_float2(xac[mf][1][0] + bf10, xac[mf][1][1] + bf11));
                    __stcg((float2*)(xo + 8 * G_ + nc0), make_float2(xac[mf][0][2] + bf00, xac[mf][0][3] + bf01));
                    __stcg((float2*)(xo + 8 * G_ + nc1), make_float2(xac[mf][1][2] + bf10, xac[mf][1][3] + bf11));
                }
                __syncthreads();
                if (tid == 0) st_release_gpu(flag, (unsigned)t);
                break;
            }

#pragma unroll
            for (int kb2 = 0; kb2 < 13; ++kb2) {
                uint2 r0 = *(const uint2*)(hA + kb2 * 8);
                uint2 r1 = *(const uint2*)(hA + kb2 * 8 + 8 * 104);
                uint2 r2 = *(const uint2*)(hA + kb2 * 8 + 16 * 104);
                uint2 r3 = *(const uint2*)(hA + kb2 * 8 + 24 * 104);
                uint32_t a0[4] = {r0.x, r1.x, r0.y, r1.y};
                uint32_t a1[4] = {r2.x, r3.x, r2.y, r3.y};
                uint2 bb0 = *(const uint2*)(wB0 + kb2 * 8);
                uint2 bb1 = *(const uint2*)(wB1 + kb2 * 8);
                uint32_t b0[2] = {bb0.x, bb0.y};
                uint32_t b1[2] = {bb1.x, bb1.y};
                mma_bf16(acc[0][0], a0, b0);
                mma_bf16(acc[1][0], a1, b0);
                mma_bf16(acc[0][1], a0, b1);
                mma_bf16(acc[1][1], a1, b1);
            }

#pragma unroll
            for (int mf = 0; mf < 2; ++mf) {
                float* d0 = g_s + (wm * 32 + mf * 16 + g4) * 40 + wn * 16 + tg * 2;
                *(float2*)(d0)              = make_float2(acc[mf][0][0], acc[mf][0][1]);
                *(float2*)(d0 + 8)          = make_float2(acc[mf][1][0], acc[mf][1][1]);
                *(float2*)(d0 + 8 * 40)     = make_float2(acc[mf][0][2], acc[mf][0][3]);
                *(float2*)(d0 + 8 * 40 + 8) = make_float2(acc[mf][1][2], acc[mf][1][3]);
            }
            __syncthreads();

            {
                const float* gr = g_s + eb * 40 + eul;
                float iv, fv, gv, ov, h0, h1, h2, h3;
                iv = sigmf(gr[0] + q0.x);  fv = sigmf(gr[8] + q1.x);
                gv = tanh_fast(gr[16] + q2.x); ov = sigmf(gr[24] + q3.x);
                cc0 = fv * cc0 + iv * gv;  h0 = ov * tanh_fast(cc0);

                iv = sigmf(gr[1] + q0.y);  fv = sigmf(gr[9] + q1.y);
                gv = tanh_fast(gr[17] + q2.y); ov = sigmf(gr[25] + q3.y);
                cc1 = fv * cc1 + iv * gv;  h1 = ov * tanh_fast(cc1);

                iv = sigmf(gr[2] + q0.z);  fv = sigmf(gr[10] + q1.z);
                gv = tanh_fast(gr[18] + q2.z); ov = sigmf(gr[26] + q3.z);
                cc2 = fv * cc2 + iv * gv;  h2 = ov * tanh_fast(cc2);

                iv = sigmf(gr[3] + q0.w);  fv = sigmf(gr[11] + q1.w);
                gv = tanh_fast(gr[19] + q2.w); ov = sigmf(gr[27] + q3.w);
                cc3 = fv * cc3 + iv * gv;  h3 = ov * tanh_fast(cc3);

                unsigned* hb = hsout + ((size_t)t * B_ + gb0 + eb) * HPW_ + jg * 8;
                __stcg(hb + wo0, bf2(h0, h1));
                __stcg(hb + wo1, bf2(h2, h3));
                if (role) {
                    float* hl = h2l + ((size_t)t * B_ + gb0 + eb) * H_ + u0 + eul;
                    *(float4*)hl = make_float4(h0, h1, h2, h3);
                }
            }

            __syncthreads();
            if (tid == 0) st_release_gpu(&g_arr[barid][ublk], (unsigned)(t + 1));

            // deferred xg2 production (off the recurrence critical path)
            if (!role && t > 0) {
                float xac[2][2][4] = {};
#pragma unroll
                for (int kb2 = 0; kb2 < 13; ++kb2) {
                    uint2 r0 = *(const uint2*)(hA + kb2 * 8);
                    uint2 r1 = *(const uint2*)(hA + kb2 * 8 + 8 * 104);
                    uint2 r2 = *(const uint2*)(hA + kb2 * 8 + 16 * 104);
                    uint2 r3 = *(const uint2*)(hA + kb2 * 8 + 24 * 104);
                    uint32_t a0[4] = {r0.x, r1.x, r0.y, r1.y};
                    uint32_t a1[4] = {r2.x, r3.x, r2.y, r3.y};
                    uint2 vv0 = *(const uint2*)(vB0 + kb2 * 8);
                    uint2 vv1 = *(const uint2*)(vB1 + kb2 * 8);
                    uint32_t v0[2] = {vv0.x, vv0.y};
                    uint32_t v1[2] = {vv1.x, vv1.y};
                    mma_bf16(xac[0][0], a0, v0);
                    mma_bf16(xac[1][0], a1, v0);
                    mma_bf16(xac[0][1], a0, v1);
                    mma_bf16(xac[1][1], a1, v1);
                }
#pragma unroll
                for (int mf = 0; mf < 2; ++mf) {
                    float* xo = xg2 + ((size_t)(t - 1) * B_ + rowM + mf * 16) * G_;
                    __stcg((float2*)(xo + nc0),          make_float2(xac[mf][0][0] + bf00, xac[mf][0][1] + bf01));
                    __stcg((float2*)(xo + nc1),          make_float2(xac[mf][1][0] + bf10, xac[mf][1][1] + bf11));
                    __stcg((float2*)(xo + 8 * G_ + nc0), make_float2(xac[mf][0][2] + bf00, xac[mf][0][3] + bf01));
                    __stcg((float2*)(xo + 8 * G_ + nc1), make_float2(xac[mf][1][2] + bf10, xac[mf][1][3] + bf11));
                }
                __syncthreads();
                if (tid == 0) st_release_gpu(flag, (unsigned)t);
            }
        }
    }

    // ---- global drain barrier over all blocks, then replay-safe resets ----
    __syncthreads();
    if (tid == 0) {
        unsigned gen = *(volatile unsigned*)&g_gen;
        __threadfence();
        if (atomicAdd(&g_cnt, 1u) == gridDim.x - 1) {
            atomicExch(&g_cnt, 0u);
            __threadfence();
            atomicAdd(&g_gen, 1u);
        } else {
            while (*(volatile unsigned*)&g_gen == gen) { __nanosleep(64); }
        }
        if (!fcrole) {
            g_arr[barid][ublk] = 0u;
            if (isL2) *(volatile unsigned*)&g_l1prog[barid - 2][ublk] = 0u;
        }
    }
}

// ---------------- launch --------------------------------------------------------
extern "C" void kernel_launch(void* const* d_in, const int* in_sizes, int n_in,
                              void* d_out, int out_size)
{
    const float* x     = (const float*)d_in[0];
    const float* w_ih1 = (const float*)d_in[1];
    const float* w_hh1 = (const float*)d_in[2];
    const float* b_ih1 = (const float*)d_in[3];
    const float* b_hh1 = (const float*)d_in[4];
    const float* w_ih2 = (const float*)d_in[5];
    const float* w_hh2 = (const float*)d_in[6];
    const float* b_ih2 = (const float*)d_in[7];
    const float* b_hh2 = (const float*)d_in[8];
    const float* fc1_w = (const float*)d_in[9];
    const float* fc1_b = (const float*)d_in[10];
    const float* fc2_w = (const float*)d_in[11];
    const float* fc2_b = (const float*)d_in[12];
    float* out = (float*)d_out;

    float *xg2, *h2l, *wp2;
    unsigned *hs1, *hs2, *xtb;
    cudaGetSymbolAddress((void**)&xg2, g_xg2);
    cudaGetSymbolAddress((void**)&xtb, g_xtb);
    cudaGetSymbolAddress((void**)&hs1, g_hs1);
    cudaGetSymbolAddress((void**)&hs2, g_hs2);
    cudaGetSymbolAddress((void**)&h2l, g_h2l);
    cudaGetSymbolAddress((void**)&wp2, g_wp2);

    const int SMEM = SMEM_WORDS * 4;                 // 157696 B
    cudaFuncSetAttribute(lstm_fused, cudaFuncAttributeMaxDynamicSharedMemorySize, SMEM);

    // 0. pad fc2_w to [129,160]
    pad_w<<<(I_ * KP_ + 255) / 256, 256>>>(fc2_w, wp2, I_, I_);
    // 1. x -> packed bf16 xtb (fused transpose + pack)
    transpose_pack<<<dim3((T_ + 31) / 32, KP_ / 32, B_), dim3(32, 8)>>>(x, xtb);
    // 2. everything else: L1 + L2 waves + streaming FC, one persistent kernel
    lstm_fused<<<148, 256, SMEM>>>(xtb, w_ih1, b_ih1, b_hh1, w_hh1,
                                   w_ih2, w_hh2, b_ih2, b_hh2,
                                   hs1, hs2, h2l, xg2,
                                   fc1_w, fc1_b, wp2, fc2_b, out);
}

// round 16
// speedup vs baseline: 3.4621x; 1.0040x over previous
#include <cuda_runtime.h>
#include <cstdint>
#include <cstdio>

#define B_   256
#define T_   600
#define I_   129
#define H_   200
#define G_   800   // 4*H
#define KP_  160   // padded K for the I=129 operands
#define HPW_ 104   // packed bf16 h row: 13 kb2-groups * 8 uint32 words
#define XPW_ 80    // packed bf16 xt row: 10 kb2-groups * 8 words

// wave-role smem word offsets
#define OFF_WHH  0        // 32*104
#define OFF_WIH2 3328     // 32*104
#define OFF_WIH1 6656     // 32*88 (stride 88, 80 used)
#define OFF_H    9472     // 128*104
#define OFF_XT   22784    // 128*88
#define OFF_GS   34048    // 128*40 floats
// FC-role layout: [0, 2*TB2) staging, y1 at 2*TB2 (128*164 floats)
#define TB2      9216
#define OFF_Y1   18432
#define SMEM_WORDS 39424  // max(wave 39168, fc 39424) -> 157696 B

// ---------------- scratch (device globals; no cudaMalloc allowed) ----------------
__device__ float    g_xg2[(size_t)T_ * B_ * G_];     // xg2 (with biases, from L1)
__device__ unsigned g_xtb[(size_t)T_ * B_ * XPW_];   // packed bf16 xt
__device__ unsigned g_hs1[(size_t)T_ * B_ * HPW_];   // packed bf16 h, layer 1
__device__ unsigned g_hs2[(size_t)T_ * B_ * HPW_];   // packed bf16 h, layer 2
__device__ float    g_h2l[(size_t)T_ * B_ * H_];     // linear fp32 h2 (for fc)
__device__ float    g_wp2[I_ * KP_];                 // fc2_w padded to [129,160]

// single end-of-kernel drain barrier (all blocks)
__device__ unsigned g_cnt = 0;
__device__ unsigned g_gen = 0;
// per-step arrival epochs: [barid][block]; value = completed step + 1
__device__ unsigned g_arr[4][25];
// L1 -> L2 progress flags (completed L1 xg2 step)
__device__ unsigned g_l1prog[2][25];

// ---------------- fast activations ----------------
__device__ __forceinline__ float sigmf(float x) {
    return __fdividef(1.f, 1.f + __expf(-x));
}
__device__ __forceinline__ float tanh_fast(float x) {
    float e = __expf(2.f * x);
    return 1.f - __fdividef(2.f, e + 1.f);
}

// ---------------- tf32 / bf16 helpers ----------------
__device__ __forceinline__ uint32_t f2tf32(float x) {
    uint32_t r;
    asm("cvt.rna.tf32.f32 %0, %1;" : "=r"(r) : "f"(x));
    return r;
}
__device__ __forceinline__ float tfhi(float v) { return __uint_as_float(f2tf32(v)); }
__device__ __forceinline__ uint32_t fu(float v) { return __float_as_uint(v); }

__device__ __forceinline__ uint32_t bf2(float a, float b) {
    uint32_t r;
    asm("cvt.rn.bf16x2.f32 %0, %1, %2;" : "=r"(r) : "f"(b), "f"(a));
    return r;
}

__device__ __forceinline__ void st_release_gpu(unsigned* p, unsigned v) {
    asm volatile("st.release.gpu.u32 [%0], %1;" :: "l"(p), "r"(v) : "memory");
}
__device__ __forceinline__ unsigned ld_acquire_gpu(const unsigned* p) {
    unsigned v;
    asm volatile("ld.acquire.gpu.u32 %0, [%1];" : "=r"(v) : "l"(p) : "memory");
    return v;
}

__device__ __forceinline__ void mma_tf32(float* d, const uint32_t* a, const uint32_t* b) {
    asm volatile(
        "mma.sync.aligned.m16n8k8.row.col.f32.tf32.tf32.f32 "
        "{%0,%1,%2,%3}, {%4,%5,%6,%7}, {%8,%9}, {%0,%1,%2,%3};"
        : "+f"(d[0]), "+f"(d[1]), "+f"(d[2]), "+f"(d[3])
        : "r"(a[0]), "r"(a[1]), "r"(a[2]), "r"(a[3]), "r"(b[0]), "r"(b[1]));
}
__device__ __forceinline__ void mma_bf16(float* d, const uint32_t* a, const uint32_t* b) {
    asm volatile(
        "mma.sync.aligned.m16n8k16.row.col.f32.bf16.bf16.f32 "
        "{%0,%1,%2,%3}, {%4,%5,%6,%7}, {%8,%9}, {%0,%1,%2,%3};"
        : "+f"(d[0]), "+f"(d[1]), "+f"(d[2]), "+f"(d[3])
        : "r"(a[0]), "r"(a[1]), "r"(a[2]), "r"(a[3]), "r"(b[0]), "r"(b[1]));
}

__device__ __forceinline__ void cpasync16(uint32_t dst, const void* src) {
    asm volatile("cp.async.cg.shared.global [%0], [%1], 16;" :: "r"(dst), "l"(src));
}

// interleaved 8-k split for the 3xTF32 FC GEMMs
__device__ __forceinline__ void split8(float4 p0, float4 p1, float4 q[4])
{
    float h0 = tfhi(p0.x), h1 = tfhi(p0.y), h2 = tfhi(p0.z), h3 = tfhi(p0.w);
    float g0 = tfhi(p1.x), g1 = tfhi(p1.y), g2 = tfhi(p1.z), g3 = tfhi(p1.w);
    q[0] = make_float4(h0, g0, tfhi(p0.x - h0), tfhi(p1.x - g0));
    q[1] = make_float4(h1, g1, tfhi(p0.y - h1), tfhi(p1.y - g1));
    q[2] = make_float4(h2, g2, tfhi(p0.z - h2), tfhi(p1.z - g2));
    q[3] = make_float4(h3, g3, tfhi(p0.w - h3), tfhi(p1.w - g3));
}

// ---------------- weight padding ----------------
__global__ void pad_w(const float* __restrict__ w, float* __restrict__ wp, int N, int K)
{
    int i = blockIdx.x * 256 + threadIdx.x;
    if (i < N * KP_) {
        int n = i / KP_, k = i - n * KP_;
        wp[i] = (k < K) ? w[(size_t)n * K + k] : 0.f;
    }
}

// ---------------- fused transpose + bf16 pack: x[B,129,T] -> xtb words ----------
__global__ void transpose_pack(const float* __restrict__ x, unsigned* __restrict__ xtb)
{
    __shared__ float sm[32][33];
    const int b  = blockIdx.z;
    const int i0 = blockIdx.y * 32;
    const int t0 = blockIdx.x * 32;
    const int tx = threadIdx.x, ty = threadIdx.y;   // (32,8)
#pragma unroll
    for (int s = 0; s < 32; s += 8) {
        int i = i0 + ty + s, t = t0 + tx;
        sm[ty + s][tx] = (i < I_ && t < T_) ? x[((size_t)b * I_ + i) * T_ + t] : 0.f;
    }
    __syncthreads();
#pragma unroll
    for (int j = 0; j < 2; ++j) {
        int widx = (ty * 32 + tx) + 256 * j;        // 0..511
        int tl = widx >> 4, rem16 = widx & 15;
        int kb2l = rem16 >> 3, w = rem16 & 7;
        int kl = (w & 1) ? (w + 7) : w;             // pair-interleaved layout
        int il = kb2l * 16 + kl;
        int t = t0 + tl;
        if (t < T_) {
            unsigned v = bf2(sm[il][tl], sm[il + 1][tl]);
            xtb[((size_t)t * B_ + b) * XPW_ + (i0 >> 4) * 8 + kb2l * 8 + w] = v;
        }
    }
}

// ---------------- 3xTF32 GEMM building blocks (FC role) --------------------------
__device__ __forceinline__ void ld_regs(
    const float* __restrict__ A, int ldA,
    const float* __restrict__ W, int ldW,
    int m0, int n0, int N, int K, int kt, int tid,
    float4 ra[2], float4 rw[2])
{
    const float4 z = make_float4(0.f, 0.f, 0.f, 0.f);
    const int row = tid >> 1, kbl = tid & 1;
    int k = kt * 16 + kbl * 8;
    if (k + 8 <= K) {
        const float* p = A + (size_t)(m0 + row) * ldA + k;
        ra[0] = *(const float4*)p;
        ra[1] = *(const float4*)(p + 4);
    } else { ra[0] = z; ra[1] = z; }
    if (tid < 128) {
        int wr = tid >> 1;
        if (k + 8 <= K && n0 + wr < N) {
            const float* p = W + (size_t)(n0 + wr) * ldW + k;
            rw[0] = *(const float4*)p;
            rw[1] = *(const float4*)(p + 4);
        } else { rw[0] = z; rw[1] = z; }
    }
}

__device__ __forceinline__ void ld_regs_y1(
    const float* __restrict__ y1s, const float* __restrict__ W,
    int n0, int kt, int tid, float4 ra[2], float4 rw[2])
{
    const float4 z = make_float4(0.f, 0.f, 0.f, 0.f);
    const int row = tid >> 1, kbl = tid & 1;
    int k = kt * 16 + kbl * 8;
    const float* p = y1s + row * 164 + k;
    ra[0] = *(const float4*)p;
    ra[1] = *(const float4*)(p + 4);
    if (tid < 128) {
        int wr = tid >> 1;
        if (n0 + wr < I_) {
            const float* q = W + (size_t)(n0 + wr) * KP_ + k;
            rw[0] = *(const float4*)q;
            rw[1] = *(const float4*)(q + 4);
        } else { rw[0] = z; rw[1] = z; }
    }
}

__device__ __forceinline__ void st_smem(float* buf, int tid, float4 ra[2], float4 rw[2])
{
    const int row = tid >> 1, kbl = tid & 1;
    {
        float4 q[4];
        split8(ra[0], ra[1], q);
        float4* da = (float4*)(buf + row * 48 + kbl * 16);
        int rot = row & 3;
#pragma unroll
        for (int j = 0; j < 4; ++j) { int jj = (rot + j) & 3; da[jj] = q[jj]; }
    }
    if (tid < 128) {
        int wr = tid >> 1;
        float4 q[4];
        split8(rw[0], rw[1], q);
        float4* dw = (float4*)(buf + 6144 + wr * 48 + kbl * 16);
        int rot = wr & 3;
#pragma unroll
        for (int j = 0; j < 4; ++j) { int jj = (rot + j) & 3; dw[jj] = q[jj]; }
    }
}

__device__ __forceinline__ void mma_tile16(const float* buf, int wm, int wn,
                                           int g4, int tg, float acc[2][4][4])
{
    const float* Sw = buf + 6144;
#pragma unroll
    for (int kk = 0; kk < 2; ++kk) {
        int koff = kk * 16 + tg * 4;
        uint32_t ah[2][4], al[2][4];
#pragma unroll
        for (int mf = 0; mf < 2; ++mf) {
            const float* pa = buf + (wm * 32 + mf * 16 + g4) * 48 + koff;
            float4 A0 = *(const float4*)pa;
            float4 A1 = *(const float4*)(pa + 8 * 48);
            ah[mf][0] = fu(A0.x); ah[mf][1] = fu(A1.x);
            ah[mf][2] = fu(A0.y); ah[mf][3] = fu(A1.y);
            al[mf][0] = fu(A0.z); al[mf][1] = fu(A1.z);
            al[mf][2] = fu(A0.w); al[mf][3] = fu(A1.w);
        }
#pragma unroll
        for (int nf = 0; nf < 4; ++nf) {
            const float* pb = Sw + (wn * 32 + nf * 8 + g4) * 48 + koff;
            float4 Bv = *(const float4*)pb;
            uint32_t bh[2] = {fu(Bv.x), fu(Bv.y)};
            uint32_t bl[2] = {fu(Bv.z), fu(Bv.w)};
            mma_tf32(acc[0][nf], ah[0], bh);
            mma_tf32(acc[0][nf], ah[0], bl);
            mma_tf32(acc[0][nf], al[0], bh);
            mma_tf32(acc[1][nf], ah[1], bh);
            mma_tf32(acc[1][nf], ah[1], bl);
            mma_tf32(acc[1][nf], al[1], bh);
        }
    }
}

// ---------------- unified persistent kernel --------------------------------------
// grid 148: [0,50) L1 wave, [50,100) L2 wave, [100,148) FC consumers.
// FC epoch polls are single-thread + heavy backoff to avoid contending the wave's
// hot barrier cache lines. L1 prefetches xt(t+1) right after the h(t) publish.
__global__ void __launch_bounds__(256, 1) lstm_fused(
    const unsigned* __restrict__ xtb,
    const float* __restrict__ wih1, const float* __restrict__ bi1,
    const float* __restrict__ bh1,  const float* __restrict__ whh1,
    const float* __restrict__ wih2, const float* __restrict__ whh2,
    const float* __restrict__ bi2,  const float* __restrict__ bh2,
    unsigned* __restrict__ hs1, unsigned* __restrict__ hs2,
    float* __restrict__ h2l, float* __restrict__ xg2,
    const float* __restrict__ fc1_w, const float* __restrict__ fc1_b,
    const float* __restrict__ wp2,   const float* __restrict__ fc2_b,
    float* __restrict__ out)
{
    extern __shared__ uint32_t smu[];
    const int tid  = threadIdx.x;
    const int warp = tid >> 5, lane = tid & 31;
    const int g4 = lane >> 2, tg = lane & 3;
    const int wm = warp >> 1;
    const int wn = warp & 1;

    const int bx = blockIdx.x;
    const bool fcrole = (bx >= 100);
    int barid = 0, ublk = 0, isL2 = 0;

    if (fcrole) {
        // ================= FC role =================
        float* smf = (float*)smu;
        float* y1s = smf + OFF_Y1;          // 128 x 164
        const int fcid = bx - 100;          // 0..47

        for (int it = fcid; it < 2 * T_; it += 48) {
            const int t   = it >> 1;
            const int grp = it & 1;
            const int r0  = t * B_ + grp * 128;

            // low-contention wait: ONE thread, sequential flags, heavy backoff
            if (tid == 0) {
                for (int j = 0; j < 25; ++j) {
                    const unsigned* f = &g_arr[2 + grp][j];
                    while (ld_acquire_gpu(f) < (unsigned)(t + 1)) { __nanosleep(1024); }
                }
            }
            __syncthreads();

            float4 ra[2], rw[2];
            // ---- fc1: y1 = relu(h2 @ fc1_w^T + b1), cols 129..159 zero ----
#pragma unroll 1
            for (int nt = 0; nt < 3; ++nt) {
                int n0 = nt * 64;
                float acc[2][4][4] = {};
                ld_regs(h2l, H_, fc1_w, H_, r0, n0, I_, H_, 0, tid, ra, rw);
                st_smem(smf, tid, ra, rw);
                __syncthreads();
#pragma unroll 1
                for (int kt = 0; kt < 13; ++kt) {
                    if (kt + 1 < 13)
                        ld_regs(h2l, H_, fc1_w, H_, r0, n0, I_, H_, kt + 1, tid, ra, rw);
                    mma_tile16(smf + (kt & 1) * TB2, wm, wn, g4, tg, acc);
                    if (kt + 1 < 13)
                        st_smem(smf + ((kt + 1) & 1) * TB2, tid, ra, rw);
                    __syncthreads();
                }
#pragma unroll
                for (int mf = 0; mf < 2; ++mf) {
                    int m_a = wm * 32 + mf * 16 + g4;
#pragma unroll
                    for (int nf = 0; nf < 4; ++nf) {
                        int n = n0 + wn * 32 + nf * 8 + tg * 2;
#pragma unroll
                        for (int half = 0; half < 2; ++half) {
                            int m = m_a + half * 8;
                            if (n < KP_) {
                                float v0 = acc[mf][nf][half * 2 + 0];
                                float v1 = acc[mf][nf][half * 2 + 1];
                                y1s[m * 164 + n]     = (n     < I_) ? fmaxf(v0 + fc1_b[n], 0.f)     : 0.f;
                                y1s[m * 164 + n + 1] = (n + 1 < I_) ? fmaxf(v1 + fc1_b[n + 1], 0.f) : 0.f;
                            }
                        }
                    }
                }
                __syncthreads();
            }

            // ---- fc2: out = sigmoid(y1 @ wp2^T + b2), transposed [B,129,T] ----
#pragma unroll 1
            for (int nt = 0; nt < 3; ++nt) {
                int n0 = nt * 64;
                float acc[2][4][4] = {};
                ld_regs_y1(y1s, wp2, n0, 0, tid, ra, rw);
                st_smem(smf, tid, ra, rw);
                __syncthreads();
#pragma unroll 1
                for (int kt = 0; kt < 10; ++kt) {
                    if (kt + 1 < 10)
                        ld_regs_y1(y1s, wp2, n0, kt + 1, tid, ra, rw);
                    mma_tile16(smf + (kt & 1) * TB2, wm, wn, g4, tg, acc);
                    if (kt + 1 < 10)
                        st_smem(smf + ((kt + 1) & 1) * TB2, tid, ra, rw);
                    __syncthreads();
                }
#pragma unroll
                for (int mf = 0; mf < 2; ++mf) {
                    int m_a = wm * 32 + mf * 16 + g4;
#pragma unroll
                    for (int nf = 0; nf < 4; ++nf) {
                        int n = n0 + wn * 32 + nf * 8 + tg * 2;
#pragma unroll
                        for (int half = 0; half < 2; ++half) {
                            int m = m_a + half * 8;
                            int b = grp * 128 + m;
                            float v0 = acc[mf][nf][half * 2 + 0];
                            float v1 = acc[mf][nf][half * 2 + 1];
                            if (n < I_)
                                out[((size_t)b * I_ + n) * T_ + t] = sigmf(v0 + fc2_b[n]);
                            if (n + 1 < I_)
                                out[((size_t)b * I_ + n + 1) * T_ + t] = sigmf(v1 + fc2_b[n + 1]);
                        }
                    }
                }
                __syncthreads();
            }
        }
    } else {
        // ================= wave roles (L1/L2) =================
        uint32_t* w_su  = smu + OFF_WHH;
        uint32_t* w2_su = smu + OFF_WIH2;
        uint32_t* w1_su = smu + OFF_WIH1;
        uint32_t* h_su  = smu + OFF_H;
        uint32_t* xt_su = smu + OFF_XT;
        float*    g_s   = (float*)(smu + OFF_GS);

        const int role = (bx >= 50);
        isL2 = role;
        const int bid  = bx - role * 50;
        const int grp  = bid / 25;
        ublk = bid - grp * 25;
        const int gb0  = grp * 128;
        const int u0   = ublk * 8;
        barid = role * 2 + grp;

        const float* whh = role ? whh2 : whh1;
        unsigned* hsout = role ? hs2 : hs1;
        unsigned* flag = &g_l1prog[grp][ublk];

        for (int i = 0; i < 13; ++i) {
            int lin = tid + 256 * i;
            if (lin < 3328) {
                int c = lin / 104, rem = lin - c * 104;
                int kb2 = rem >> 3, w = rem & 7;
                int kl = (w & 1) ? (w + 7) : w;
                int k0 = kb2 * 16 + kl;
                int grow = (c >> 3) * H_ + u0 + (c & 7);
                const float* wr_ = whh + (size_t)grow * H_;
                float v0 = (k0     < H_) ? wr_[k0]     : 0.f;
                float v1 = (k0 + 1 < H_) ? wr_[k0 + 1] : 0.f;
                w_su[c * 104 + kb2 * 8 + w] = bf2(v0, v1);
                if (!role) {
                    const float* w2r = wih2 + (size_t)grow * H_;
                    float u0v = (k0     < H_) ? w2r[k0]     : 0.f;
                    float u1v = (k0 + 1 < H_) ? w2r[k0 + 1] : 0.f;
                    w2_su[c * 104 + kb2 * 8 + w] = bf2(u0v, u1v);
                }
            }
        }
        if (!role) {
            for (int i = 0; i < 10; ++i) {
                int lin = tid + 256 * i;
                if (lin < 2560) {
                    int c = lin / 80, rem = lin - c * 80;
                    int kb2 = rem >> 3, w = rem & 7;
                    int kl = (w & 1) ? (w + 7) : w;
                    int k0 = kb2 * 16 + kl;
                    int grow = (c >> 3) * H_ + u0 + (c & 7);
                    const float* w1r = wih1 + (size_t)grow * I_;
                    float v0 = (k0     < I_) ? w1r[k0]     : 0.f;
                    float v1 = (k0 + 1 < I_) ? w1r[k0 + 1] : 0.f;
                    w1_su[c * 88 + kb2 * 8 + w] = bf2(v0, v1);
                }
            }
        }

        const int nc0 = (wn * 2 + 0) * H_ + u0 + tg * 2;
        const int nc1 = (wn * 2 + 1) * H_ + u0 + tg * 2;
        float bf00 = 0.f, bf01 = 0.f, bf10 = 0.f, bf11 = 0.f;
        if (!role) {
            bf00 = bi2[nc0] + bh2[nc0];     bf01 = bi2[nc0 + 1] + bh2[nc0 + 1];
            bf10 = bi2[nc1] + bh2[nc1];     bf11 = bi2[nc1 + 1] + bh2[nc1 + 1];
        }

        const int eb  = tid >> 1;
        const int eul = (tid & 1) * 4;
        float cc0 = 0.f, cc1 = 0.f, cc2 = 0.f, cc3 = 0.f;
        const int ug = u0 + eul;
        const int jg = ug >> 4;
        const int rr = ug & 15;
        const int p0 = rr >> 1;
        const int wo0 = (p0     < 4) ? 2 * p0       : 2 * (p0 - 4) + 1;
        const int wo1 = (p0 + 1 < 4) ? 2 * (p0 + 1) : 2 * (p0 - 3) + 1;

        float4 bq0, bq1, bq2, bq3;
        if (!role) {
            const float* bA = bi1; const float* bB = bh1;
            bq0 = make_float4(bA[0*H_+ug]+bB[0*H_+ug], bA[0*H_+ug+1]+bB[0*H_+ug+1],
                              bA[0*H_+ug+2]+bB[0*H_+ug+2], bA[0*H_+ug+3]+bB[0*H_+ug+3]);
            bq1 = make_float4(bA[1*H_+ug]+bB[1*H_+ug], bA[1*H_+ug+1]+bB[1*H_+ug+1],
                              bA[1*H_+ug+2]+bB[1*H_+ug+2], bA[1*H_+ug+3]+bB[1*H_+ug+3]);
            bq2 = make_float4(bA[2*H_+ug]+bB[2*H_+ug], bA[2*H_+ug+1]+bB[2*H_+ug+1],
                              bA[2*H_+ug+2]+bB[2*H_+ug+2], bA[2*H_+ug+3]+bB[2*H_+ug+3]);
            bq3 = make_float4(bA[3*H_+ug]+bB[3*H_+ug], bA[3*H_+ug+1]+bB[3*H_+ug+1],
                              bA[3*H_+ug+2]+bB[3*H_+ug+2], bA[3*H_+ug+3]+bB[3*H_+ug+3]);
        }

        const uint32_t* hA  = h_su + (wm * 32 + g4) * 104 + tg * 2;
        const uint32_t* xA  = xt_su + (wm * 32 + g4) * 88 + tg * 2;
        const uint32_t* wB0 = w_su + (wn * 16 + g4) * 104 + tg * 2;
        const uint32_t* wB1 = wB0 + 8 * 104;
        const uint32_t* vB0 = w2_su + (wn * 16 + g4) * 104 + tg * 2;
        const uint32_t* vB1 = vB0 + 8 * 104;
        const uint32_t* uB0 = w1_su + (wn * 16 + g4) * 88 + tg * 2;
        const uint32_t* uB1 = uB0 + 8 * 88;
        const int rowM = gb0 + wm * 32 + g4;
        const uint32_t h_su32  = (uint32_t)__cvta_generic_to_shared(h_su);
        const uint32_t xt_su32 = (uint32_t)__cvta_generic_to_shared(xt_su);

        // L1: prefetch xt(0) before the loop (subsequent prefetches at loop end)
        if (!role) {
            const uint4* src = (const uint4*)(xtb + ((size_t)0 * B_ + gb0) * XPW_);
#pragma unroll
            for (int i = 0; i < 10; ++i) {
                int lin = tid + 256 * i;
                int row = lin / 20, rem = lin - row * 20;
                cpasync16(xt_su32 + (row * 88 + rem * 4) * 4, src + row * 20 + rem);
            }
            asm volatile("cp.async.commit_group;" ::: "memory");
        }

        const int TEND = role ? T_ : T_ + 1;

        for (int t = 0; t < TEND; ++t) {
            const bool tail = (!role && t == T_);

            if (t > 0) {
                if (warp == 0) {
                    if (lane < 25) {
                        const unsigned* f = &g_arr[barid][lane];
                        while (ld_acquire_gpu(f) < (unsigned)t) { __nanosleep(32); }
                    }
                    if (role && lane == 25) {
                        while (ld_acquire_gpu(flag) < (unsigned)(t + 1)) { __nanosleep(32); }
                    }
                }
                __syncthreads();
            } else if (role) {
                if (tid == 0) {
                    while (ld_acquire_gpu(flag) < 1u) { __nanosleep(32); }
                }
                __syncthreads();
            }

            float4 q0, q1, q2, q3;
            if (role) {
                const float* xr = xg2 + ((size_t)t * B_ + gb0 + eb) * G_ + u0 + eul;
                q0 = *(const float4*)(xr);
                q1 = *(const float4*)(xr + H_);
                q2 = *(const float4*)(xr + 2 * H_);
                q3 = *(const float4*)(xr + 3 * H_);
            } else {
                q0 = bq0; q1 = bq1; q2 = bq2; q3 = bq3;
            }

            if (t == 0) {
                uint4 z = make_uint4(0u, 0u, 0u, 0u);
                for (int lin = tid; lin < 3328; lin += 256)
                    ((uint4*)h_su)[lin] = z;
            } else {
                const uint4* src = (const uint4*)(hsout + ((size_t)(t - 1) * B_ + gb0) * HPW_);
#pragma unroll
                for (int i = 0; i < 13; ++i) {
                    int lin = tid + 256 * i;
                    int row = lin / 26, rem = lin - row * 26;
                    cpasync16(h_su32 + (row * 104 + rem * 4) * 4, src + row * 26 + rem);
                }
                asm volatile("cp.async.commit_group;" ::: "memory");
            }

            float acc[2][2][4] = {};

            if (!role && !tail) {
                // wait for the xt group only (h may still be in flight)
                if (t == 0) { asm volatile("cp.async.wait_group 0;" ::: "memory"); }
                else        { asm volatile("cp.async.wait_group 1;" ::: "memory"); }
                __syncthreads();
#pragma unroll
                for (int kb2 = 0; kb2 < 10; ++kb2) {
                    uint2 r0 = *(const uint2*)(xA + kb2 * 8);
                    uint2 r1 = *(const uint2*)(xA + kb2 * 8 + 8 * 88);
                    uint2 r2 = *(const uint2*)(xA + kb2 * 8 + 16 * 88);
                    uint2 r3 = *(const uint2*)(xA + kb2 * 8 + 24 * 88);
                    uint32_t a0[4] = {r0.x, r1.x, r0.y, r1.y};
                    uint32_t a1[4] = {r2.x, r3.x, r2.y, r3.y};
                    uint2 bb0 = *(const uint2*)(uB0 + kb2 * 8);
                    uint2 bb1 = *(const uint2*)(uB1 + kb2 * 8);
                    uint32_t b0[2] = {bb0.x, bb0.y};
                    uint32_t b1[2] = {bb1.x, bb1.y};
                    mma_bf16(acc[0][0], a0, b0);
                    mma_bf16(acc[1][0], a1, b0);
                    mma_bf16(acc[0][1], a0, b1);
                    mma_bf16(acc[1][1], a1, b1);
                }
                asm volatile("cp.async.wait_group 0;" ::: "memory");
                __syncthreads();
            } else {
                asm volatile("cp.async.wait_group 0;" ::: "memory");
                __syncthreads();
            }

            if (tail) {
                float xac[2][2][4] = {};
#pragma unroll
                for (int kb2 = 0; kb2 < 13; ++kb2) {
                    uint2 r0 = *(const uint2*)(hA + kb2 * 8);
                    uint2 r1 = *(const uint2*)(hA + kb2 * 8 + 8 * 104);
                    uint2 r2 = *(const uint2*)(hA + kb2 * 8 + 16 * 104);
                    uint2 r3 = *(const uint2*)(hA + kb2 * 8 + 24 * 104);
                    uint32_t a0[4] = {r0.x, r1.x, r0.y, r1.y};
                    uint32_t a1[4] = {r2.x, r3.x, r2.y, r3.y};
                    uint2 vv0 = *(const uint2*)(vB0 + kb2 * 8);
                    uint2 vv1 = *(const uint2*)(vB1 + kb2 * 8);
                    uint32_t v0[2] = {vv0.x, vv0.y};
                    uint32_t v1[2] = {vv1.x, vv1.y};
                    mma_bf16(xac[0][0], a0, v0);
                    mma_bf16(xac[1][0], a1, v0);
                    mma_bf16(xac[0][1], a0, v1);
                    mma_bf16(xac[1][1], a1, v1);
                }
#pragma unroll
                for (int mf = 0; mf < 2; ++mf) {
                    float* xo = xg2 + ((size_t)(t - 1) * B_ + rowM + mf * 16) * G_;
                    __stcg((float2*)(xo + nc0),          make_float2(xac[mf][0][0] + bf00, xac[mf][0][1] + bf01));
                    __stcg((float2*)(xo + nc1),          make_float2(xac[mf][1][0] + bf10, xac[mf][1][1] + bf11));
                    __stcg((float2*)(xo + 8 * G_ + nc0), make_float2(xac[mf][0][2] + bf00, xac[mf][0][3] + bf01));
                    __stcg((float2*)(xo + 8 * G_ + nc1), make_float2(xac[mf][1][2] + bf10, xac[mf][1][3] + bf11));
                }
                __syncthreads();
                if (tid == 0) st_release_gpu(flag, (unsigned)t);
                break;
            }

#pragma unroll
            for (int kb2 = 0; kb2 < 13; ++kb2) {
                uint2 r0 = *(const uint2*)(hA + kb2 * 8);
                uint2 r1 = *(const uint2*)(hA + kb2 * 8 + 8 * 104);
                uint2 r2 = *(const uint2*)(hA + kb2 * 8 + 16 * 104);
                uint2 r3 = *(const uint2*)(hA + kb2 * 8 + 24 * 104);
                uint32_t a0[4] = {r0.x, r1.x, r0.y, r1.y};
                uint32_t a1[4] = {r2.x, r3.x, r2.y, r3.y};
                uint2 bb0 = *(const uint2*)(wB0 + kb2 * 8);
                uint2 bb1 = *(const uint2*)(wB1 + kb2 * 8);
                uint32_t b0[2] = {bb0.x, bb0.y};
                uint32_t b1[2] = {bb1.x, bb1.y};
                mma_bf16(acc[0][0], a0, b0);
                mma_bf16(acc[1][0], a1, b0);
                mma_bf16(acc[0][1], a0, b1);
                mma_bf16(acc[1][1], a1, b1);
            }

#pragma unroll
            for (int mf = 0; mf < 2; ++mf) {
                float* d0 = g_s + (wm * 32 + mf * 16 + g4) * 40 + wn * 16 + tg * 2;
                *(float2*)(d0)              = make_float2(acc[mf][0][0], acc[mf][0][1]);
                *(float2*)(d0 + 8)          = make_float2(acc[mf][1][0], acc[mf][1][1]);
                *(float2*)(d0 + 8 * 40)     = make_float2(acc[mf][0][2], acc[mf][0][3]);
                *(float2*)(d0 + 8 * 40 + 8) = make_float2(acc[mf][1][2], acc[mf][1][3]);
            }
            __syncthreads();

            {
                const float* gr = g_s + eb * 40 + eul;
                float iv, fv, gv, ov, h0, h1, h2, h3;
                iv = sigmf(gr[0] + q0.x);  fv = sigmf(gr[8] + q1.x);
                gv = tanh_fast(gr[16] + q2.x); ov = sigmf(gr[24] + q3.x);
                cc0 = fv * cc0 + iv * gv;  h0 = ov * tanh_fast(cc0);

                iv = sigmf(gr[1] + q0.y);  fv = sigmf(gr[9] + q1.y);
                gv = tanh_fast(gr[17] + q2.y); ov = sigmf(gr[25] + q3.y);
                cc1 = fv * cc1 + iv * gv;  h1 = ov * tanh_fast(cc1);

                iv = sigmf(gr[2] + q0.z);  fv = sigmf(gr[10] + q1.z);
                gv = tanh_fast(gr[18] + q2.z); ov = sigmf(gr[26] + q3.z);
                cc2 = fv * cc2 + iv * gv;  h2 = ov * tanh_fast(cc2);

                iv = sigmf(gr[3] + q0.w);  fv = sigmf(gr[11] + q1.w);
                gv = tanh_fast(gr[19] + q2.w); ov = sigmf(gr[27] + q3.w);
                cc3 = fv * cc3 + iv * gv;  h3 = ov * tanh_fast(cc3);

                unsigned* hb = hsout + ((size_t)t * B_ + gb0 + eb) * HPW_ + jg * 8;
                __stcg(hb + wo0, bf2(h0, h1));
                __stcg(hb + wo1, bf2(h2, h3));
                if (role) {
                    float* hl = h2l + ((size_t)t * B_ + gb0 + eb) * H_ + u0 + eul;
                    *(float4*)hl = make_float4(h0, h1, h2, h3);
                }
            }

            // publish arrival ASAP
            __syncthreads();
            if (tid == 0) st_release_gpu(&g_arr[barid][ublk], (unsigned)(t + 1));

            // L1: prefetch xt(t+1) NOW so it overlaps the deferred xg2 work
            if (!role && t + 1 < T_) {
                const uint4* src = (const uint4*)(xtb + ((size_t)(t + 1) * B_ + gb0) * XPW_);
#pragma unroll
                for (int i = 0; i < 10; ++i) {
                    int lin = tid + 256 * i;
                    int row = lin / 20, rem = lin - row * 20;
                    cpasync16(xt_su32 + (row * 88 + rem * 4) * 4, src + row * 20 + rem);
                }
                asm volatile("cp.async.commit_group;" ::: "memory");
            }

            // deferred xg2 production (off the recurrence critical path)
            if (!role && t > 0) {
                float xac[2][2][4] = {};
#pragma unroll
                for (int kb2 = 0; kb2 < 13; ++kb2) {
                    uint2 r0 = *(const uint2*)(hA + kb2 * 8);
                    uint2 r1 = *(const uint2*)(hA + kb2 * 8 + 8 * 104);
                    uint2 r2 = *(const uint2*)(hA + kb2 * 8 + 16 * 104);
                    uint2 r3 = *(const uint2*)(hA + kb2 * 8 + 24 * 104);
                    uint32_t a0[4] = {r0.x, r1.x, r0.y, r1.y};
                    uint32_t a1[4] = {r2.x, r3.x, r2.y, r3.y};
                    uint2 vv0 = *(const uint2*)(vB0 + kb2 * 8);
                    uint2 vv1 = *(const uint2*)(vB1 + kb2 * 8);
                    uint32_t v0[2] = {vv0.x, vv0.y};
                    uint32_t v1[2] = {vv1.x, vv1.y};
                    mma_bf16(xac[0][0], a0, v0);
                    mma_bf16(xac[1][0], a1, v0);
                    mma_bf16(xac[0][1], a0, v1);
                    mma_bf16(xac[1][1], a1, v1);
                }
#pragma unroll
                for (int mf = 0; mf < 2; ++mf) {
                    float* xo = xg2 + ((size_t)(t - 1) * B_ + rowM + mf * 16) * G_;
                    __stcg((float2*)(xo + nc0),          make_float2(xac[mf][0][0] + bf00, xac[mf][0][1] + bf01));
                    __stcg((float2*)(xo + nc1),          make_float2(xac[mf][1][0] + bf10, xac[mf][1][1] + bf11));
                    __stcg((float2*)(xo + 8 * G_ + nc0), make_float2(xac[mf][0][2] + bf00, xac[mf][0][3] + bf01));
                    __stcg((float2*)(xo + 8 * G_ + nc1), make_float2(xac[mf][1][2] + bf10, xac[mf][1][3] + bf11));
                }
                __syncthreads();
                if (tid == 0) st_release_gpu(flag, (unsigned)t);
            }
        }
    }

    // ---- global drain barrier over all blocks, then replay-safe resets ----
    __syncthreads();
    if (tid == 0) {
        unsigned gen = *(volatile unsigned*)&g_gen;
        __threadfence();
        if (atomicAdd(&g_cnt, 1u) == gridDim.x - 1) {
            atomicExch(&g_cnt, 0u);
            __threadfence();
            atomicAdd(&g_gen, 1u);
        } else {
            while (*(volatile unsigned*)&g_gen == gen) { __nanosleep(64); }
        }
        if (!fcrole) {
            g_arr[barid][ublk] = 0u;
            if (isL2) *(volatile unsigned*)&g_l1prog[barid - 2][ublk] = 0u;
        }
    }
}

// ---------------- launch --------------------------------------------------------
extern "C" void kernel_launch(void* const* d_in, const int* in_sizes, int n_in,
                              void* d_out, int out_size)
{
    const float* x     = (const float*)d_in[0];
    const float* w_ih1 = (const float*)d_in[1];
    const float* w_hh1 = (const float*)d_in[2];
    const float* b_ih1 = (const float*)d_in[3];
    const float* b_hh1 = (const float*)d_in[4];
    const float* w_ih2 = (const float*)d_in[5];
    const float* w_hh2 = (const float*)d_in[6];
    const float* b_ih2 = (const float*)d_in[7];
    const float* b_hh2 = (const float*)d_in[8];
    const float* fc1_w = (const float*)d_in[9];
    const float* fc1_b = (const float*)d_in[10];
    const float* fc2_w = (const float*)d_in[11];
    const float* fc2_b = (const float*)d_in[12];
    float* out = (float*)d_out;

    float *xg2, *h2l, *wp2;
    unsigned *hs1, *hs2, *xtb;
    cudaGetSymbolAddress((void**)&xg2, g_xg2);
    cudaGetSymbolAddress((void**)&xtb, g_xtb);
    cudaGetSymbolAddress((void**)&hs1, g_hs1);
    cudaGetSymbolAddress((void**)&hs2, g_hs2);
    cudaGetSymbolAddress((void**)&h2l, g_h2l);
    cudaGetSymbolAddress((void**)&wp2, g_wp2);

    const int SMEM = SMEM_WORDS * 4;                 // 157696 B
    cudaFuncSetAttribute(lstm_fused, cudaFuncAttributeMaxDynamicSharedMemorySize, SMEM);

    // 0. pad fc2_w to [129,160]
    pad_w<<<(I_ * KP_ + 255) / 256, 256>>>(fc2_w, wp2, I_, I_);
    // 1. x -> packed bf16 xtb (fused transpose + pack)
    transpose_pack<<<dim3((T_ + 31) / 32, KP_ / 32, B_), dim3(32, 8)>>>(x, xtb);
    // 2. everything else: L1 + L2 waves + streaming FC, one persistent kernel
    lstm_fused<<<148, 256, SMEM>>>(xtb, w_ih1, b_ih1, b_hh1, w_hh1,
                                   w_ih2, w_hh2, b_ih2, b_hh2,
                                   hs1, hs2, h2l, xg2,
                                   fc1_w, fc1_b, wp2, fc2_b, out);
}